// round 1
// baseline (speedup 1.0000x reference)
#include <cuda_runtime.h>
#include <cstdint>

#define E_EDGES 1600000
#define N_NODES 50000
#define EPS_BN 1e-5f

// ---------------- scratch (device globals; no allocations allowed) ----------
__device__ float g_Y[(size_t)E_EDGES * 128];      // pre-BN edge activations (819 MB)
__device__ float g_s[(size_t)N_NODES * 128];      // scatter-sum accumulator
__device__ int   g_cnt[N_NODES];                  // per-node edge counts
__device__ float g_h2in[(size_t)N_NODES * 256];   // concat(x, agg)
__device__ float g_Z2[(size_t)N_NODES * 256];     // pre-BN node activations
__device__ float g_sum1[128], g_ssq1[128], g_scale1[128], g_shift1[128];
__device__ float g_sum2[256], g_ssq2[256], g_scale2[256], g_shift2[256];

__device__ __forceinline__ float4 ld4(const float* p) {
    return *reinterpret_cast<const float4*>(p);
}

// ---------------- zero scratch ----------------------------------------------
__global__ void zero_kernel() {
    int idx = blockIdx.x * blockDim.x + threadIdx.x;
    int stride = gridDim.x * blockDim.x;
    float4 z4 = make_float4(0.f, 0.f, 0.f, 0.f);
    int total4 = N_NODES * 32;  // g_s as float4
    float4* s4 = reinterpret_cast<float4*>(g_s);
    for (int i = idx; i < total4; i += stride) s4[i] = z4;
    for (int i = idx; i < N_NODES; i += stride) g_cnt[i] = 0;
    if (idx < 128) { g_sum1[idx] = 0.f; g_ssq1[idx] = 0.f; }
    if (idx < 256) { g_sum2[idx] = 0.f; g_ssq2[idx] = 0.f; }
}

// ---------------- generic SGEMM with fused epilogues -------------------------
// MODE 0: A = concat(x[row[e]], edge_attr[e]) [E,192]; out=g_Y; stats->g_sum1/g_ssq1
// MODE 1: A = g_h2in [N,256];                          out=g_Z2; stats->g_sum2/g_ssq2
// MODE 2: A = relu(bn2(g_Z2)) [N,256];                 out=OutParam, final relu
template<int MODE>
__global__ __launch_bounds__(256)
void sgemm(const float* __restrict__ Aptr,    // MODE0: x
           const float* __restrict__ eattr,   // MODE0: edge_attr
           const int*   __restrict__ erow,    // MODE0: edge_index row
           const float* __restrict__ W,       // [K, Ntot]
           const float* __restrict__ bias,    // [Ntot]
           float* __restrict__ OutParam,      // MODE2: d_out
           int M, int K, int Ntot)
{
    __shared__ float As[16][132];  // padded stride (528B, 16B-aligned rows)
    __shared__ float Ws[16][128];
    __shared__ float s_sum[128];
    __shared__ float s_ssq[128];

    const int t  = threadIdx.x;
    const int tx = t & 15;
    const int ty = t >> 4;
    const int mBase = blockIdx.x * 128;
    const int nBase = blockIdx.y * 128;

    // A-tile float4 load assignments (fixed across k-chunks)
    const int r0 = t >> 2,          kq0 = t & 3;
    const int r1 = (t + 256) >> 2,  kq1 = t & 3;  // (t+256)&3 == t&3

    int grow0 = 0, grow1 = 0;
    if (MODE == 0) {
        grow0 = erow[mBase + r0];
        grow1 = erow[mBase + r1];
    }

    const float* A = (MODE == 1) ? (const float*)g_h2in
                   : (MODE == 2) ? (const float*)g_Z2
                                 : Aptr;

    float acc[8][8];
    #pragma unroll
    for (int i = 0; i < 8; ++i)
        #pragma unroll
        for (int j = 0; j < 8; ++j) acc[i][j] = 0.f;

    const int nK = K >> 4;
    for (int kb = 0; kb < nK; ++kb) {
        // ---- load A tile ----
        float4 v0 = make_float4(0.f,0.f,0.f,0.f);
        float4 v1 = make_float4(0.f,0.f,0.f,0.f);
        const int k0 = (kb << 4) + (kq0 << 2);
        const int k1 = (kb << 4) + (kq1 << 2);
        if (MODE == 0) {
            v0 = (k0 < 128) ? ld4(A + (size_t)grow0 * 128 + k0)
                            : ld4(eattr + (size_t)(mBase + r0) * 64 + (k0 - 128));
            v1 = (k1 < 128) ? ld4(A + (size_t)grow1 * 128 + k1)
                            : ld4(eattr + (size_t)(mBase + r1) * 64 + (k1 - 128));
        } else if (MODE == 1) {
            int rg0 = mBase + r0, rg1 = mBase + r1;
            if (rg0 < M) v0 = ld4(A + (size_t)rg0 * 256 + k0);
            if (rg1 < M) v1 = ld4(A + (size_t)rg1 * 256 + k1);
        } else {
            int rg0 = mBase + r0, rg1 = mBase + r1;
            if (rg0 < M) {
                float4 z = ld4(A + (size_t)rg0 * 256 + k0);
                float4 sc = ld4(g_scale2 + k0), sh = ld4(g_shift2 + k0);
                v0.x = fmaxf(fmaf(z.x, sc.x, sh.x), 0.f);
                v0.y = fmaxf(fmaf(z.y, sc.y, sh.y), 0.f);
                v0.z = fmaxf(fmaf(z.z, sc.z, sh.z), 0.f);
                v0.w = fmaxf(fmaf(z.w, sc.w, sh.w), 0.f);
            }
            if (rg1 < M) {
                float4 z = ld4(A + (size_t)rg1 * 256 + k1);
                float4 sc = ld4(g_scale2 + k1), sh = ld4(g_shift2 + k1);
                v1.x = fmaxf(fmaf(z.x, sc.x, sh.x), 0.f);
                v1.y = fmaxf(fmaf(z.y, sc.y, sh.y), 0.f);
                v1.z = fmaxf(fmaf(z.z, sc.z, sh.z), 0.f);
                v1.w = fmaxf(fmaf(z.w, sc.w, sh.w), 0.f);
            }
        }
        As[(kq0<<2)+0][r0] = v0.x;
        As[(kq0<<2)+1][r0] = v0.y;
        As[(kq0<<2)+2][r0] = v0.z;
        As[(kq0<<2)+3][r0] = v0.w;
        As[(kq1<<2)+0][r1] = v1.x;
        As[(kq1<<2)+1][r1] = v1.y;
        As[(kq1<<2)+2][r1] = v1.z;
        As[(kq1<<2)+3][r1] = v1.w;

        // ---- load W tile ----
        {
            int k  = t >> 5, cq = t & 31;
            float4 w = ld4(W + (size_t)((kb << 4) + k) * Ntot + nBase + (cq << 2));
            *reinterpret_cast<float4*>(&Ws[k][cq << 2]) = w;
            k = (t + 256) >> 5;
            w = ld4(W + (size_t)((kb << 4) + k) * Ntot + nBase + (cq << 2));
            *reinterpret_cast<float4*>(&Ws[k][cq << 2]) = w;
        }
        __syncthreads();

        #pragma unroll
        for (int kk = 0; kk < 16; ++kk) {
            float a[8], b[8];
            *reinterpret_cast<float4*>(&a[0]) = *reinterpret_cast<const float4*>(&As[kk][ty << 3]);
            *reinterpret_cast<float4*>(&a[4]) = *reinterpret_cast<const float4*>(&As[kk][(ty << 3) + 4]);
            *reinterpret_cast<float4*>(&b[0]) = *reinterpret_cast<const float4*>(&Ws[kk][tx << 3]);
            *reinterpret_cast<float4*>(&b[4]) = *reinterpret_cast<const float4*>(&Ws[kk][(tx << 3) + 4]);
            #pragma unroll
            for (int i = 0; i < 8; ++i)
                #pragma unroll
                for (int j = 0; j < 8; ++j)
                    acc[i][j] = fmaf(a[i], b[j], acc[i][j]);
        }
        __syncthreads();
    }

    // ---- epilogue ----
    float bcol[8];
    #pragma unroll
    for (int j = 0; j < 8; ++j) bcol[j] = bias[nBase + (tx << 3) + j];

    if (MODE <= 1) {
        float* Yout = (MODE == 0) ? g_Y : g_Z2;
        float* sumg = (MODE == 0) ? g_sum1 : g_sum2;
        float* ssqg = (MODE == 0) ? g_ssq1 : g_ssq2;

        float csum[8], cssq[8];
        #pragma unroll
        for (int j = 0; j < 8; ++j) { csum[j] = 0.f; cssq[j] = 0.f; }

        #pragma unroll
        for (int i = 0; i < 8; ++i) {
            int rg = mBase + (ty << 3) + i;
            if (rg < M) {
                float yv[8];
                #pragma unroll
                for (int j = 0; j < 8; ++j) {
                    float y = acc[i][j] + bcol[j];
                    yv[j] = y;
                    csum[j] += y;
                    cssq[j] = fmaf(y, y, cssq[j]);
                }
                float* dst = Yout + (size_t)rg * Ntot + nBase + (tx << 3);
                *reinterpret_cast<float4*>(dst)     = make_float4(yv[0], yv[1], yv[2], yv[3]);
                *reinterpret_cast<float4*>(dst + 4) = make_float4(yv[4], yv[5], yv[6], yv[7]);
            }
        }
        __syncthreads();
        if (t < 128) { s_sum[t] = 0.f; s_ssq[t] = 0.f; }
        __syncthreads();
        #pragma unroll
        for (int j = 0; j < 8; ++j) {
            atomicAdd(&s_sum[(tx << 3) + j], csum[j]);
            atomicAdd(&s_ssq[(tx << 3) + j], cssq[j]);
        }
        __syncthreads();
        if (t < 128) {
            atomicAdd(&sumg[nBase + t], s_sum[t]);
            atomicAdd(&ssqg[nBase + t], s_ssq[t]);
        }
    } else {
        #pragma unroll
        for (int i = 0; i < 8; ++i) {
            int rg = mBase + (ty << 3) + i;
            if (rg < M) {
                float yv[8];
                #pragma unroll
                for (int j = 0; j < 8; ++j)
                    yv[j] = fmaxf(acc[i][j] + bcol[j], 0.f);
                float* dst = OutParam + (size_t)rg * Ntot + nBase + (tx << 3);
                *reinterpret_cast<float4*>(dst)     = make_float4(yv[0], yv[1], yv[2], yv[3]);
                *reinterpret_cast<float4*>(dst + 4) = make_float4(yv[4], yv[5], yv[6], yv[7]);
            }
        }
    }
}

// ---------------- BN finalize: scale/shift from sums ------------------------
__global__ void finalize_bn(const float* __restrict__ gamma,
                            const float* __restrict__ beta,
                            int C, float invM, int which)
{
    int i = blockIdx.x * blockDim.x + threadIdx.x;
    if (i < C) {
        const float* sum = (which == 0) ? g_sum1 : g_sum2;
        const float* ssq = (which == 0) ? g_ssq1 : g_ssq2;
        float*     scale = (which == 0) ? g_scale1 : g_scale2;
        float*     shift = (which == 0) ? g_shift1 : g_shift2;
        float mu  = sum[i] * invM;
        float var = ssq[i] * invM - mu * mu;
        float inv = rsqrtf(var + EPS_BN);
        float sc  = gamma[i] * inv;
        scale[i] = sc;
        shift[i] = beta[i] - mu * sc;
    }
}

// ---------------- BN+ReLU then scatter-add (vector atomics) -----------------
__global__ void scatter_kernel(const int* __restrict__ ecol) {
    const int lane   = threadIdx.x & 31;
    const int warp   = (blockIdx.x * blockDim.x + threadIdx.x) >> 5;
    const int nWarps = (gridDim.x * blockDim.x) >> 5;

    float4 sc = *reinterpret_cast<const float4*>(&g_scale1[lane << 2]);
    float4 sh = *reinterpret_cast<const float4*>(&g_shift1[lane << 2]);

    for (int e = warp; e < E_EDGES; e += nWarps) {
        int c = ecol[e];
        float4 y = *reinterpret_cast<const float4*>(&g_Y[(size_t)e * 128 + (lane << 2)]);
        y.x = fmaxf(fmaf(y.x, sc.x, sh.x), 0.f);
        y.y = fmaxf(fmaf(y.y, sc.y, sh.y), 0.f);
        y.z = fmaxf(fmaf(y.z, sc.z, sh.z), 0.f);
        y.w = fmaxf(fmaf(y.w, sc.w, sh.w), 0.f);
        float* dst = &g_s[(size_t)c * 128 + (lane << 2)];
        asm volatile("red.global.add.v4.f32 [%0], {%1,%2,%3,%4};"
                     :: "l"(dst), "f"(y.x), "f"(y.y), "f"(y.z), "f"(y.w)
                     : "memory");
        if (lane == 0) atomicAdd(&g_cnt[c], 1);
    }
}

// ---------------- build h2in = concat(x, s/cnt) ------------------------------
__global__ void build_h2in(const float* __restrict__ x) {
    int idx = blockIdx.x * blockDim.x + threadIdx.x;
    int stride = gridDim.x * blockDim.x;
    const int total = N_NODES * 64;  // float4 slots per row: 64 (256 floats)
    for (int i = idx; i < total; i += stride) {
        int n = i >> 6, q = i & 63;
        float4 v;
        if (q < 32) {
            v = ld4(x + (size_t)n * 128 + (q << 2));
        } else {
            int c = q - 32;
            v = ld4(g_s + (size_t)n * 128 + (c << 2));
            int cnt = g_cnt[n];
            float inv = (cnt > 0) ? (1.f / (float)cnt) : 0.f;
            v.x *= inv; v.y *= inv; v.z *= inv; v.w *= inv;
        }
        *reinterpret_cast<float4*>(g_h2in + (size_t)n * 256 + (q << 2)) = v;
    }
}

// ---------------- launch ------------------------------------------------------
extern "C" void kernel_launch(void* const* d_in, const int* in_sizes, int n_in,
                              void* d_out, int out_size)
{
    const float* x     = (const float*)d_in[0];
    const int*   eidx  = (const int*)  d_in[1];   // [2, E]
    const float* eattr = (const float*)d_in[2];
    // d_in[3] = u (unused), d_in[4] = batch (unused)
    const float* W1  = (const float*)d_in[5];
    const float* b1  = (const float*)d_in[6];
    const float* g1  = (const float*)d_in[7];
    const float* be1 = (const float*)d_in[8];
    const float* W2  = (const float*)d_in[9];
    const float* b2  = (const float*)d_in[10];
    const float* g2  = (const float*)d_in[11];
    const float* be2 = (const float*)d_in[12];
    const float* Wl  = (const float*)d_in[13];
    const float* bl  = (const float*)d_in[14];
    float* out = (float*)d_out;

    const int* erow = eidx;
    const int* ecol = eidx + E_EDGES;

    // 0) zero accumulators
    zero_kernel<<<2048, 256>>>();

    // 1) edge GEMM: Y = concat(x[row], eattr) @ W1 + b1, fused BN1 stats
    sgemm<0><<<dim3(E_EDGES / 128, 1), 256>>>(x, eattr, erow, W1, b1, nullptr,
                                              E_EDGES, 192, 128);

    // 2) BN1 scale/shift
    finalize_bn<<<1, 256>>>(g1, be1, 128, 1.f / (float)E_EDGES, 0);

    // 3) BN1 + ReLU + scatter-add into g_s, counts into g_cnt
    scatter_kernel<<<2368, 256>>>(ecol);

    // 4) h2in = concat(x, s/cnt)
    build_h2in<<<2048, 256>>>(x);

    // 5) node GEMM: Z2 = h2in @ W2 + b2, fused BN2 stats
    sgemm<1><<<dim3((N_NODES + 127) / 128, 2), 256>>>(nullptr, nullptr, nullptr,
                                                      W2, b2, nullptr,
                                                      N_NODES, 256, 256);

    // 6) BN2 scale/shift
    finalize_bn<<<1, 256>>>(g2, be2, 256, 1.f / (float)N_NODES, 1);

    // 7) out = relu(relu(bn2(Z2)) @ Wl + bl)
    sgemm<2><<<dim3((N_NODES + 127) / 128, 1), 256>>>(nullptr, nullptr, nullptr,
                                                      Wl, bl, out,
                                                      N_NODES, 256, 128);
}

// round 3
// speedup vs baseline: 1.2892x; 1.2892x over previous
#include <cuda_runtime.h>
#include <cuda_bf16.h>
#include <cstdint>

#define E_EDGES 1600000
#define N_NODES 50000
#define EPS_BN 1e-5f

// ---------------- scratch (device globals; no allocations allowed) ----------
__device__ float g_Y[(size_t)E_EDGES * 128];      // pre-BN edge activations
__device__ float g_s[(size_t)N_NODES * 128];      // scatter-sum accumulator
__device__ int   g_cnt[N_NODES];
__device__ float g_h2in[(size_t)N_NODES * 256];
__device__ float g_Z2[(size_t)N_NODES * 256];
__device__ float g_sum1[128], g_ssq1[128], g_scale1[128], g_shift1[128];
__device__ float g_sum2[256], g_ssq2[256], g_scale2[256], g_shift2[256];
// W1 hi/lo bf16 images in padded [192][136] layout (52224 B each, uint4-clean)
__device__ uint4 g_WimgHi[3264];
__device__ uint4 g_WimgLo[3264];

__device__ __forceinline__ float4 ld4(const float* p) {
    return *reinterpret_cast<const float4*>(p);
}
__device__ __forceinline__ uint32_t smem_u32(const void* p) {
    uint32_t a;
    asm("{ .reg .u64 t; cvta.to.shared.u64 t, %1; cvt.u32.u64 %0, t; }" : "=r"(a) : "l"(p));
    return a;
}

// ---------------- warp MMA primitives (sm_80 baseline, no 'a' features) -----
__device__ __forceinline__ void mma_bf16(float* c, const uint32_t* a, const uint32_t* b) {
    asm volatile(
        "mma.sync.aligned.m16n8k16.row.col.f32.bf16.bf16.f32 "
        "{%0,%1,%2,%3}, {%4,%5,%6,%7}, {%8,%9}, {%0,%1,%2,%3};"
        : "+f"(c[0]), "+f"(c[1]), "+f"(c[2]), "+f"(c[3])
        : "r"(a[0]), "r"(a[1]), "r"(a[2]), "r"(a[3]), "r"(b[0]), "r"(b[1]));
}
__device__ __forceinline__ void ldsm4(uint32_t* r, uint32_t addr) {
    asm volatile("ldmatrix.sync.aligned.m8n8.x4.shared.b16 {%0,%1,%2,%3}, [%4];"
        : "=r"(r[0]), "=r"(r[1]), "=r"(r[2]), "=r"(r[3]) : "r"(addr));
}
__device__ __forceinline__ void ldsm4t(uint32_t* r, uint32_t addr) {
    asm volatile("ldmatrix.sync.aligned.m8n8.x4.trans.shared.b16 {%0,%1,%2,%3}, [%4];"
        : "=r"(r[0]), "=r"(r[1]), "=r"(r[2]), "=r"(r[3]) : "r"(addr));
}

// ---------------- zero scratch ----------------------------------------------
__global__ void zero_kernel() {
    int idx = blockIdx.x * blockDim.x + threadIdx.x;
    int stride = gridDim.x * blockDim.x;
    float4 z4 = make_float4(0.f, 0.f, 0.f, 0.f);
    int total4 = N_NODES * 32;
    float4* s4 = reinterpret_cast<float4*>(g_s);
    for (int i = idx; i < total4; i += stride) s4[i] = z4;
    for (int i = idx; i < N_NODES; i += stride) g_cnt[i] = 0;
    if (idx < 128) { g_sum1[idx] = 0.f; g_ssq1[idx] = 0.f; }
    if (idx < 256) { g_sum2[idx] = 0.f; g_ssq2[idx] = 0.f; }
}

// ---------------- prep: W1 [192][128] -> padded bf16 hi/lo images ------------
__global__ void prep_W(const float* __restrict__ W1) {
    int idx = blockIdx.x * blockDim.x + threadIdx.x;
    if (idx < 192 * 128) {
        int k = idx >> 7, n = idx & 127;
        float f = W1[idx];
        __nv_bfloat16 h = __float2bfloat16_rn(f);
        __nv_bfloat16 l = __float2bfloat16_rn(f - __bfloat162float(h));
        reinterpret_cast<uint16_t*>(g_WimgHi)[k * 136 + n] = *reinterpret_cast<uint16_t*>(&h);
        reinterpret_cast<uint16_t*>(g_WimgLo)[k * 136 + n] = *reinterpret_cast<uint16_t*>(&l);
    }
}

// ---------------- GEMM1 via mma.sync bf16 (3-pass hi/lo split) --------------
// SMEM layout (bytes):
//   A_hi [128][200 bf16] : 0      .. 51200
//   A_lo [128][200 bf16] : 51200  .. 102400
//   W_hi [192][136 bf16] : 102400 .. 154624
//   W_lo [192][136 bf16] : 154624 .. 206848
//   bias [128 f32]       : 206848 .. 207360
//   s_sum[128 f32]       : 207360 .. 207872
//   s_ssq[128 f32]       : 207872 .. 208384
#define SG_AHI 0
#define SG_ALO 51200
#define SG_WHI 102400
#define SG_WLO 154624
#define SG_BIAS 206848
#define SG_SUM 207360
#define SG_SSQ 207872
#define SG_TOT 208384

__global__ void __launch_bounds__(256, 1)
gemm1_mma(const float* __restrict__ x, const float* __restrict__ eattr,
          const int* __restrict__ erow, const float* __restrict__ bias) {
    extern __shared__ char smem[];
    const uint32_t sb = smem_u32(smem);
    const int tid = threadIdx.x, wid = tid >> 5, lane = tid & 31;
    const int mBase = blockIdx.x * 128;

    // ---- copy prebuilt W hi/lo images (uint4, coalesced) ----
    {
        uint4* dh = reinterpret_cast<uint4*>(smem + SG_WHI);
        uint4* dl = reinterpret_cast<uint4*>(smem + SG_WLO);
        #pragma unroll 4
        for (int i = tid; i < 3264; i += 256) { dh[i] = g_WimgHi[i]; dl[i] = g_WimgLo[i]; }
    }
    if (tid < 128) ((float*)(smem + SG_BIAS))[tid] = bias[tid];

    // ---- gather A rows, split to bf16 hi/lo ----
    {
        const int r = tid >> 1, h = tid & 1;
        const int grow = erow[mBase + r];
        const float4* xr = reinterpret_cast<const float4*>(x + (size_t)grow * 128);
        const float4* er = reinterpret_cast<const float4*>(eattr + (size_t)(mBase + r) * 64);
        char* ahi = smem + SG_AHI + r * 400;
        char* alo = smem + SG_ALO + r * 400;
        #pragma unroll 6
        for (int jj = 0; jj < 24; ++jj) {
            int j = h * 24 + jj;
            float4 v = (j < 32) ? xr[j] : er[j - 32];
            __nv_bfloat16 h0 = __float2bfloat16_rn(v.x), h1 = __float2bfloat16_rn(v.y);
            __nv_bfloat16 h2 = __float2bfloat16_rn(v.z), h3 = __float2bfloat16_rn(v.w);
            __nv_bfloat162 hp0(h0, h1), hp1(h2, h3);
            __nv_bfloat162 lp0(__float2bfloat16_rn(v.x - __bfloat162float(h0)),
                               __float2bfloat16_rn(v.y - __bfloat162float(h1)));
            __nv_bfloat162 lp1(__float2bfloat16_rn(v.z - __bfloat162float(h2)),
                               __float2bfloat16_rn(v.w - __bfloat162float(h3)));
            uint2 hv = make_uint2(*reinterpret_cast<uint32_t*>(&hp0),
                                  *reinterpret_cast<uint32_t*>(&hp1));
            uint2 lv = make_uint2(*reinterpret_cast<uint32_t*>(&lp0),
                                  *reinterpret_cast<uint32_t*>(&lp1));
            *reinterpret_cast<uint2*>(ahi + j * 8) = hv;
            *reinterpret_cast<uint2*>(alo + j * 8) = lv;
        }
    }
    __syncthreads();

    // ---- warp tiles: 8 warps -> (4 m) x (2 n); warp tile 32x64 ----
    const int m0 = (wid & 3) * 32;
    const int n0 = (wid >> 2) * 64;

    float acc[2][8][4];
    #pragma unroll
    for (int mi = 0; mi < 2; ++mi)
        #pragma unroll
        for (int ni = 0; ni < 8; ++ni)
            #pragma unroll
            for (int c = 0; c < 4; ++c) acc[mi][ni][c] = 0.f;

    // ldmatrix lane addressing
    const uint32_t aRowOff = (uint32_t)(m0 + (lane & 15)) * 400u + (uint32_t)(lane >> 4) * 16u;
    const uint32_t bOff = (uint32_t)((lane & 7) + ((lane >> 3) & 1) * 8) * 272u
                        + ((uint32_t)(lane >> 4) * 8u + (uint32_t)n0) * 2u;

    #pragma unroll 1
    for (int kt = 0; kt < 12; ++kt) {
        const uint32_t k0b = (uint32_t)kt * 32u;     // k0*2 bytes (A)
        const uint32_t kwb = (uint32_t)kt * 4352u;   // kt*16*272 bytes (W)
        uint32_t ah[2][4], al[2][4];
        ldsm4(ah[0], sb + SG_AHI + aRowOff + k0b);
        ldsm4(ah[1], sb + SG_AHI + aRowOff + 6400u + k0b);
        ldsm4(al[0], sb + SG_ALO + aRowOff + k0b);
        ldsm4(al[1], sb + SG_ALO + aRowOff + 6400u + k0b);

        uint32_t bh[8][2], bl[8][2];
        #pragma unroll
        for (int ni2 = 0; ni2 < 4; ++ni2) {
            uint32_t t4[4];
            ldsm4t(t4, sb + SG_WHI + bOff + kwb + (uint32_t)ni2 * 32u);
            bh[2 * ni2][0] = t4[0]; bh[2 * ni2][1] = t4[1];
            bh[2 * ni2 + 1][0] = t4[2]; bh[2 * ni2 + 1][1] = t4[3];
            ldsm4t(t4, sb + SG_WLO + bOff + kwb + (uint32_t)ni2 * 32u);
            bl[2 * ni2][0] = t4[0]; bl[2 * ni2][1] = t4[1];
            bl[2 * ni2 + 1][0] = t4[2]; bl[2 * ni2 + 1][1] = t4[3];
        }

        #pragma unroll
        for (int mi = 0; mi < 2; ++mi)
            #pragma unroll
            for (int ni = 0; ni < 8; ++ni) {
                mma_bf16(acc[mi][ni], ah[mi], bh[ni]);   // hi*hi
                mma_bf16(acc[mi][ni], al[mi], bh[ni]);   // lo*hi
                mma_bf16(acc[mi][ni], ah[mi], bl[ni]);   // hi*lo
            }
    }

    // ---- epilogue: bias, Y store, BN1 stats ----
    __syncthreads();
    if (tid < 128) {
        ((float*)(smem + SG_SUM))[tid] = 0.f;
        ((float*)(smem + SG_SSQ))[tid] = 0.f;
    }
    __syncthreads();

    const float* bs = (const float*)(smem + SG_BIAS);
    float* s_sum = (float*)(smem + SG_SUM);
    float* s_ssq = (float*)(smem + SG_SSQ);
    const int g = lane >> 2, t2 = (lane & 3) * 2;

    float csum[8][2], cssq[8][2];
    #pragma unroll
    for (int ni = 0; ni < 8; ++ni) {
        csum[ni][0] = 0.f; csum[ni][1] = 0.f;
        cssq[ni][0] = 0.f; cssq[ni][1] = 0.f;
    }

    #pragma unroll
    for (int mi = 0; mi < 2; ++mi) {
        const int row = mBase + m0 + mi * 16 + g;
        #pragma unroll
        for (int ni = 0; ni < 8; ++ni) {
            const int col = n0 + ni * 8 + t2;
            float b0 = bs[col], b1 = bs[col + 1];
            float y0 = acc[mi][ni][0] + b0;
            float y1 = acc[mi][ni][1] + b1;
            float y2 = acc[mi][ni][2] + b0;
            float y3 = acc[mi][ni][3] + b1;
            *reinterpret_cast<float2*>(g_Y + (size_t)row * 128 + col)       = make_float2(y0, y1);
            *reinterpret_cast<float2*>(g_Y + (size_t)(row + 8) * 128 + col) = make_float2(y2, y3);
            csum[ni][0] += y0 + y2;
            csum[ni][1] += y1 + y3;
            cssq[ni][0] += y0 * y0 + y2 * y2;
            cssq[ni][1] += y1 * y1 + y3 * y3;
        }
    }
    // reduce over the 8 lane-groups (same t2 -> same columns)
    #pragma unroll
    for (int ni = 0; ni < 8; ++ni)
        #pragma unroll
        for (int par = 0; par < 2; ++par) {
            float s = csum[ni][par], q = cssq[ni][par];
            #pragma unroll
            for (int o = 4; o < 32; o <<= 1) {
                s += __shfl_xor_sync(0xFFFFFFFFu, s, o);
                q += __shfl_xor_sync(0xFFFFFFFFu, q, o);
            }
            if (g == 0) {
                atomicAdd(&s_sum[n0 + ni * 8 + t2 + par], s);
                atomicAdd(&s_ssq[n0 + ni * 8 + t2 + par], q);
            }
        }
    __syncthreads();
    if (tid < 128) {
        atomicAdd(&g_sum1[tid], s_sum[tid]);
        atomicAdd(&g_ssq1[tid], s_ssq[tid]);
    }
}

// ---------------- fp32 register-tiled SGEMM for node GEMMs -------------------
template<int MODE>
__global__ __launch_bounds__(256)
void sgemm(const float* __restrict__ W, const float* __restrict__ bias,
           float* __restrict__ OutParam, int M, int K, int Ntot)
{
    __shared__ float As[16][132];
    __shared__ float Ws[16][128];
    __shared__ float s_sum[128];
    __shared__ float s_ssq[128];

    const int t  = threadIdx.x;
    const int tx = t & 15;
    const int ty = t >> 4;
    const int mBase = blockIdx.x * 128;
    const int nBase = blockIdx.y * 128;

    const int r0 = t >> 2,         kq0 = t & 3;
    const int r1 = (t + 256) >> 2, kq1 = t & 3;

    const float* A = (MODE == 1) ? (const float*)g_h2in : (const float*)g_Z2;

    float acc[8][8];
    #pragma unroll
    for (int i = 0; i < 8; ++i)
        #pragma unroll
        for (int j = 0; j < 8; ++j) acc[i][j] = 0.f;

    const int nK = K >> 4;
    for (int kb = 0; kb < nK; ++kb) {
        float4 v0 = make_float4(0.f, 0.f, 0.f, 0.f);
        float4 v1 = make_float4(0.f, 0.f, 0.f, 0.f);
        const int k0 = (kb << 4) + (kq0 << 2);
        const int k1 = (kb << 4) + (kq1 << 2);
        int rg0 = mBase + r0, rg1 = mBase + r1;
        if (MODE == 1) {
            if (rg0 < M) v0 = ld4(A + (size_t)rg0 * 256 + k0);
            if (rg1 < M) v1 = ld4(A + (size_t)rg1 * 256 + k1);
        } else {
            if (rg0 < M) {
                float4 z = ld4(A + (size_t)rg0 * 256 + k0);
                float4 sc = ld4(g_scale2 + k0), sh = ld4(g_shift2 + k0);
                v0.x = fmaxf(fmaf(z.x, sc.x, sh.x), 0.f);
                v0.y = fmaxf(fmaf(z.y, sc.y, sh.y), 0.f);
                v0.z = fmaxf(fmaf(z.z, sc.z, sh.z), 0.f);
                v0.w = fmaxf(fmaf(z.w, sc.w, sh.w), 0.f);
            }
            if (rg1 < M) {
                float4 z = ld4(A + (size_t)rg1 * 256 + k1);
                float4 sc = ld4(g_scale2 + k1), sh = ld4(g_shift2 + k1);
                v1.x = fmaxf(fmaf(z.x, sc.x, sh.x), 0.f);
                v1.y = fmaxf(fmaf(z.y, sc.y, sh.y), 0.f);
                v1.z = fmaxf(fmaf(z.z, sc.z, sh.z), 0.f);
                v1.w = fmaxf(fmaf(z.w, sc.w, sh.w), 0.f);
            }
        }
        As[(kq0 << 2) + 0][r0] = v0.x;
        As[(kq0 << 2) + 1][r0] = v0.y;
        As[(kq0 << 2) + 2][r0] = v0.z;
        As[(kq0 << 2) + 3][r0] = v0.w;
        As[(kq1 << 2) + 0][r1] = v1.x;
        As[(kq1 << 2) + 1][r1] = v1.y;
        As[(kq1 << 2) + 2][r1] = v1.z;
        As[(kq1 << 2) + 3][r1] = v1.w;

        {
            int k = t >> 5, cq = t & 31;
            float4 w = ld4(W + (size_t)((kb << 4) + k) * Ntot + nBase + (cq << 2));
            *reinterpret_cast<float4*>(&Ws[k][cq << 2]) = w;
            k = (t + 256) >> 5;
            w = ld4(W + (size_t)((kb << 4) + k) * Ntot + nBase + (cq << 2));
            *reinterpret_cast<float4*>(&Ws[k][cq << 2]) = w;
        }
        __syncthreads();

        #pragma unroll
        for (int kk = 0; kk < 16; ++kk) {
            float a[8], b[8];
            *reinterpret_cast<float4*>(&a[0]) = *reinterpret_cast<const float4*>(&As[kk][ty << 3]);
            *reinterpret_cast<float4*>(&a[4]) = *reinterpret_cast<const float4*>(&As[kk][(ty << 3) + 4]);
            *reinterpret_cast<float4*>(&b[0]) = *reinterpret_cast<const float4*>(&Ws[kk][tx << 3]);
            *reinterpret_cast<float4*>(&b[4]) = *reinterpret_cast<const float4*>(&Ws[kk][(tx << 3) + 4]);
            #pragma unroll
            for (int i = 0; i < 8; ++i)
                #pragma unroll
                for (int j = 0; j < 8; ++j)
                    acc[i][j] = fmaf(a[i], b[j], acc[i][j]);
        }
        __syncthreads();
    }

    float bcol[8];
    #pragma unroll
    for (int j = 0; j < 8; ++j) bcol[j] = bias[nBase + (tx << 3) + j];

    if (MODE == 1) {
        float csum[8], cssq[8];
        #pragma unroll
        for (int j = 0; j < 8; ++j) { csum[j] = 0.f; cssq[j] = 0.f; }

        #pragma unroll
        for (int i = 0; i < 8; ++i) {
            int rg = mBase + (ty << 3) + i;
            if (rg < M) {
                float yv[8];
                #pragma unroll
                for (int j = 0; j < 8; ++j) {
                    float y = acc[i][j] + bcol[j];
                    yv[j] = y;
                    csum[j] += y;
                    cssq[j] = fmaf(y, y, cssq[j]);
                }
                float* dst = g_Z2 + (size_t)rg * Ntot + nBase + (tx << 3);
                *reinterpret_cast<float4*>(dst)     = make_float4(yv[0], yv[1], yv[2], yv[3]);
                *reinterpret_cast<float4*>(dst + 4) = make_float4(yv[4], yv[5], yv[6], yv[7]);
            }
        }
        __syncthreads();
        if (t < 128) { s_sum[t] = 0.f; s_ssq[t] = 0.f; }
        __syncthreads();
        #pragma unroll
        for (int j = 0; j < 8; ++j) {
            atomicAdd(&s_sum[(tx << 3) + j], csum[j]);
            atomicAdd(&s_ssq[(tx << 3) + j], cssq[j]);
        }
        __syncthreads();
        if (t < 128) {
            atomicAdd(&g_sum2[nBase + t], s_sum[t]);
            atomicAdd(&g_ssq2[nBase + t], s_ssq[t]);
        }
    } else {
        #pragma unroll
        for (int i = 0; i < 8; ++i) {
            int rg = mBase + (ty << 3) + i;
            if (rg < M) {
                float yv[8];
                #pragma unroll
                for (int j = 0; j < 8; ++j)
                    yv[j] = fmaxf(acc[i][j] + bcol[j], 0.f);
                float* dst = OutParam + (size_t)rg * Ntot + nBase + (tx << 3);
                *reinterpret_cast<float4*>(dst)     = make_float4(yv[0], yv[1], yv[2], yv[3]);
                *reinterpret_cast<float4*>(dst + 4) = make_float4(yv[4], yv[5], yv[6], yv[7]);
            }
        }
    }
}

// ---------------- BN finalize -------------------------------------------------
__global__ void finalize_bn(const float* __restrict__ gamma,
                            const float* __restrict__ beta,
                            int C, float invM, int which)
{
    int i = blockIdx.x * blockDim.x + threadIdx.x;
    if (i < C) {
        const float* sum = (which == 0) ? g_sum1 : g_sum2;
        const float* ssq = (which == 0) ? g_ssq1 : g_ssq2;
        float*     scale = (which == 0) ? g_scale1 : g_scale2;
        float*     shift = (which == 0) ? g_shift1 : g_shift2;
        float mu  = sum[i] * invM;
        float var = ssq[i] * invM - mu * mu;
        float inv = rsqrtf(var + EPS_BN);
        float sc  = gamma[i] * inv;
        scale[i] = sc;
        shift[i] = beta[i] - mu * sc;
    }
}

// ---------------- BN+ReLU then scatter-add (vector atomics) -----------------
__global__ void scatter_kernel(const int* __restrict__ ecol) {
    const int lane   = threadIdx.x & 31;
    const int warp   = (blockIdx.x * blockDim.x + threadIdx.x) >> 5;
    const int nWarps = (gridDim.x * blockDim.x) >> 5;

    float4 sc = *reinterpret_cast<const float4*>(&g_scale1[lane << 2]);
    float4 sh = *reinterpret_cast<const float4*>(&g_shift1[lane << 2]);

    for (int e = warp; e < E_EDGES; e += nWarps) {
        int c = ecol[e];
        float4 y = *reinterpret_cast<const float4*>(&g_Y[(size_t)e * 128 + (lane << 2)]);
        y.x = fmaxf(fmaf(y.x, sc.x, sh.x), 0.f);
        y.y = fmaxf(fmaf(y.y, sc.y, sh.y), 0.f);
        y.z = fmaxf(fmaf(y.z, sc.z, sh.z), 0.f);
        y.w = fmaxf(fmaf(y.w, sc.w, sh.w), 0.f);
        float* dst = &g_s[(size_t)c * 128 + (lane << 2)];
        asm volatile("red.global.add.v4.f32 [%0], {%1,%2,%3,%4};"
                     :: "l"(dst), "f"(y.x), "f"(y.y), "f"(y.z), "f"(y.w)
                     : "memory");
        if (lane == 0) atomicAdd(&g_cnt[c], 1);
    }
}

// ---------------- build h2in = concat(x, s/cnt) ------------------------------
__global__ void build_h2in(const float* __restrict__ x) {
    int idx = blockIdx.x * blockDim.x + threadIdx.x;
    int stride = gridDim.x * blockDim.x;
    const int total = N_NODES * 64;
    for (int i = idx; i < total; i += stride) {
        int n = i >> 6, q = i & 63;
        float4 v;
        if (q < 32) {
            v = ld4(x + (size_t)n * 128 + (q << 2));
        } else {
            int c = q - 32;
            v = ld4(g_s + (size_t)n * 128 + (c << 2));
            int cnt = g_cnt[n];
            float inv = (cnt > 0) ? (1.f / (float)cnt) : 0.f;
            v.x *= inv; v.y *= inv; v.z *= inv; v.w *= inv;
        }
        *reinterpret_cast<float4*>(g_h2in + (size_t)n * 256 + (q << 2)) = v;
    }
}

// ---------------- launch ------------------------------------------------------
extern "C" void kernel_launch(void* const* d_in, const int* in_sizes, int n_in,
                              void* d_out, int out_size)
{
    const float* x     = (const float*)d_in[0];
    const int*   eidx  = (const int*)  d_in[1];
    const float* eattr = (const float*)d_in[2];
    const float* W1  = (const float*)d_in[5];
    const float* b1  = (const float*)d_in[6];
    const float* g1  = (const float*)d_in[7];
    const float* be1 = (const float*)d_in[8];
    const float* W2  = (const float*)d_in[9];
    const float* b2  = (const float*)d_in[10];
    const float* g2  = (const float*)d_in[11];
    const float* be2 = (const float*)d_in[12];
    const float* Wl  = (const float*)d_in[13];
    const float* bl  = (const float*)d_in[14];
    float* out = (float*)d_out;

    const int* erow = eidx;
    const int* ecol = eidx + E_EDGES;

    cudaFuncSetAttribute(gemm1_mma, cudaFuncAttributeMaxDynamicSharedMemorySize, SG_TOT);

    // 0) zero accumulators + build W1 bf16 hi/lo images
    zero_kernel<<<2048, 256>>>();
    prep_W<<<(192 * 128 + 255) / 256, 256>>>(W1);

    // 1) edge GEMM on tensor cores (bf16 3-pass split), fused BN1 stats
    gemm1_mma<<<E_EDGES / 128, 256, SG_TOT>>>(x, eattr, erow, b1);

    // 2) BN1 scale/shift
    finalize_bn<<<1, 256>>>(g1, be1, 128, 1.f / (float)E_EDGES, 0);

    // 3) BN1 + ReLU + scatter
    scatter_kernel<<<2368, 256>>>(ecol);

    // 4) h2in = concat(x, s/cnt)
    build_h2in<<<2048, 256>>>(x);

    // 5) node GEMM: Z2 = h2in @ W2 + b2, fused BN2 stats
    sgemm<1><<<dim3((N_NODES + 127) / 128, 2), 256>>>(W2, b2, nullptr, N_NODES, 256, 256);

    // 6) BN2 scale/shift
    finalize_bn<<<1, 256>>>(g2, be2, 256, 1.f / (float)N_NODES, 1);

    // 7) out = relu(relu(bn2(Z2)) @ Wl + bl)
    sgemm<2><<<dim3((N_NODES + 127) / 128, 1), 256>>>(Wl, bl, out, N_NODES, 256, 128);
}

// round 5
// speedup vs baseline: 1.9716x; 1.5293x over previous
#include <cuda_runtime.h>
#include <cuda_bf16.h>
#include <cstdint>

#define E_EDGES 1600000
#define N_NODES 50000
#define EPS_BN 1e-5f

// ---------------- scratch (device globals; no allocations allowed) ----------
__device__ float g_Y[(size_t)E_EDGES * 128];      // pre-BN edge activations
__device__ float g_P[(size_t)N_NODES * 128];      // x @ W1_top + b1
__device__ float g_s[(size_t)N_NODES * 128];      // scatter-sum accumulator
__device__ int   g_cnt[N_NODES];
__device__ float g_h2in[(size_t)N_NODES * 256];
__device__ float g_Z2[(size_t)N_NODES * 256];
__device__ float g_sum1[128], g_ssq1[128], g_scale1[128], g_shift1[128];
__device__ float g_sum2[256], g_ssq2[256], g_scale2[256], g_shift2[256];
// W1_bot hi/lo bf16 images: [64 k][136 n] padded, 17408 B each
__device__ uint4 g_WimgHi[1088];
__device__ uint4 g_WimgLo[1088];

__device__ __forceinline__ float4 ld4(const float* p) {
    return *reinterpret_cast<const float4*>(p);
}
__device__ __forceinline__ uint32_t smem_u32(const void* p) {
    uint32_t a;
    asm("{ .reg .u64 t; cvta.to.shared.u64 t, %1; cvt.u32.u64 %0, t; }" : "=r"(a) : "l"(p));
    return a;
}

// ---------------- warp MMA primitives (sm_80 baseline) ----------------------
__device__ __forceinline__ void mma_bf16(float* c, const uint32_t* a, const uint32_t* b) {
    asm volatile(
        "mma.sync.aligned.m16n8k16.row.col.f32.bf16.bf16.f32 "
        "{%0,%1,%2,%3}, {%4,%5,%6,%7}, {%8,%9}, {%0,%1,%2,%3};"
        : "+f"(c[0]), "+f"(c[1]), "+f"(c[2]), "+f"(c[3])
        : "r"(a[0]), "r"(a[1]), "r"(a[2]), "r"(a[3]), "r"(b[0]), "r"(b[1]));
}
__device__ __forceinline__ void ldsm4(uint32_t* r, uint32_t addr) {
    asm volatile("ldmatrix.sync.aligned.m8n8.x4.shared.b16 {%0,%1,%2,%3}, [%4];"
        : "=r"(r[0]), "=r"(r[1]), "=r"(r[2]), "=r"(r[3]) : "r"(addr));
}
__device__ __forceinline__ void ldsm4t(uint32_t* r, uint32_t addr) {
    asm volatile("ldmatrix.sync.aligned.m8n8.x4.trans.shared.b16 {%0,%1,%2,%3}, [%4];"
        : "=r"(r[0]), "=r"(r[1]), "=r"(r[2]), "=r"(r[3]) : "r"(addr));
}

// ---------------- zero scratch ----------------------------------------------
__global__ void zero_kernel() {
    int idx = blockIdx.x * blockDim.x + threadIdx.x;
    int stride = gridDim.x * blockDim.x;
    float4 z4 = make_float4(0.f, 0.f, 0.f, 0.f);
    int total4 = N_NODES * 32;
    float4* s4 = reinterpret_cast<float4*>(g_s);
    for (int i = idx; i < total4; i += stride) s4[i] = z4;
    for (int i = idx; i < N_NODES; i += stride) g_cnt[i] = 0;
    if (idx < 128) { g_sum1[idx] = 0.f; g_ssq1[idx] = 0.f; }
    if (idx < 256) { g_sum2[idx] = 0.f; g_ssq2[idx] = 0.f; }
}

// ---------------- prep: W1_bot [64][128] -> padded bf16 hi/lo images ---------
__global__ void prep_W(const float* __restrict__ W1) {
    int idx = blockIdx.x * blockDim.x + threadIdx.x;
    if (idx < 64 * 128) {
        int k = idx >> 7, n = idx & 127;
        float f = W1[(size_t)(128 + k) * 128 + n];
        __nv_bfloat16 h = __float2bfloat16_rn(f);
        __nv_bfloat16 l = __float2bfloat16_rn(f - __bfloat162float(h));
        reinterpret_cast<uint16_t*>(g_WimgHi)[k * 136 + n] = *reinterpret_cast<uint16_t*>(&h);
        reinterpret_cast<uint16_t*>(g_WimgLo)[k * 136 + n] = *reinterpret_cast<uint16_t*>(&l);
    }
}

// ---------------- Q GEMM: Q = eattr @ W1_bot; Y = Q + P[row]; BN1 stats -----
// A rows padded to 144 B (16B-aligned for ldmatrix). 128 rows -> 18432 B/image.
// SMEM (bytes): A_hi 0..18432, A_lo ..36864, W_hi ..54272, W_lo ..71680,
//               s_row ..72192, s_sum ..72704, s_ssq ..73216
#define Q_AHI 0
#define Q_ALO 18432
#define Q_WHI 36864
#define Q_WLO 54272
#define Q_ROW 71680
#define Q_SUM 72192
#define Q_SSQ 72704
#define Q_TOT 73216
#define A_STRIDE 144

__global__ void __launch_bounds__(256, 2)
gemm1_mma(const float* __restrict__ eattr, const int* __restrict__ erow) {
    extern __shared__ char smem[];
    const uint32_t sb = smem_u32(smem);
    const int tid = threadIdx.x, wid = tid >> 5, lane = tid & 31;
    const int mBase = blockIdx.x * 128;

    // W images copy (2 x 1088 uint4)
    {
        uint4* dh = reinterpret_cast<uint4*>(smem + Q_WHI);
        uint4* dl = reinterpret_cast<uint4*>(smem + Q_WLO);
        for (int i = tid; i < 1088; i += 256) { dh[i] = g_WimgHi[i]; dl[i] = g_WimgLo[i]; }
    }
    if (tid < 128) {
        ((int*)(smem + Q_ROW))[tid] = erow[mBase + tid];
        ((float*)(smem + Q_SUM))[tid] = 0.f;
        ((float*)(smem + Q_SSQ))[tid] = 0.f;
    }

    // A = eattr rows (sequential), split to bf16 hi/lo. 2 threads per row.
    {
        const int r = tid >> 1, h = tid & 1;
        const float4* er = reinterpret_cast<const float4*>(eattr + (size_t)(mBase + r) * 64);
        char* ahi = smem + Q_AHI + r * A_STRIDE;
        char* alo = smem + Q_ALO + r * A_STRIDE;
        #pragma unroll
        for (int jj = 0; jj < 8; ++jj) {
            int j = h * 8 + jj;
            float4 v = er[j];
            __nv_bfloat16 h0 = __float2bfloat16_rn(v.x), h1 = __float2bfloat16_rn(v.y);
            __nv_bfloat16 h2 = __float2bfloat16_rn(v.z), h3 = __float2bfloat16_rn(v.w);
            __nv_bfloat162 hp0(h0, h1), hp1(h2, h3);
            __nv_bfloat162 lp0(__float2bfloat16_rn(v.x - __bfloat162float(h0)),
                               __float2bfloat16_rn(v.y - __bfloat162float(h1)));
            __nv_bfloat162 lp1(__float2bfloat16_rn(v.z - __bfloat162float(h2)),
                               __float2bfloat16_rn(v.w - __bfloat162float(h3)));
            *reinterpret_cast<uint2*>(ahi + j * 8) =
                make_uint2(*reinterpret_cast<uint32_t*>(&hp0), *reinterpret_cast<uint32_t*>(&hp1));
            *reinterpret_cast<uint2*>(alo + j * 8) =
                make_uint2(*reinterpret_cast<uint32_t*>(&lp0), *reinterpret_cast<uint32_t*>(&lp1));
        }
    }
    __syncthreads();

    // warp tiles: 8 warps -> (4 m) x (2 n); warp tile 32x64
    const int m0 = (wid & 3) * 32;
    const int n0 = (wid >> 2) * 64;

    float acc[2][8][4];
    #pragma unroll
    for (int mi = 0; mi < 2; ++mi)
        #pragma unroll
        for (int ni = 0; ni < 8; ++ni)
            #pragma unroll
            for (int c = 0; c < 4; ++c) acc[mi][ni][c] = 0.f;

    const uint32_t aRowOff = (uint32_t)(m0 + (lane & 15)) * (uint32_t)A_STRIDE
                           + (uint32_t)(lane >> 4) * 16u;
    const uint32_t bOff = (uint32_t)((lane & 7) + ((lane >> 3) & 1) * 8) * 272u
                        + ((uint32_t)(lane >> 4) * 8u + (uint32_t)n0) * 2u;

    #pragma unroll
    for (int kt = 0; kt < 4; ++kt) {
        const uint32_t k0b = (uint32_t)kt * 32u;     // A: 16 bf16 = 32 B per k-step
        const uint32_t kwb = (uint32_t)kt * 4352u;   // W: 16 rows * 272 B
        uint32_t ah[2][4], al[2][4];
        ldsm4(ah[0], sb + Q_AHI + aRowOff + k0b);
        ldsm4(ah[1], sb + Q_AHI + aRowOff + 16u * A_STRIDE + k0b);
        ldsm4(al[0], sb + Q_ALO + aRowOff + k0b);
        ldsm4(al[1], sb + Q_ALO + aRowOff + 16u * A_STRIDE + k0b);

        #pragma unroll
        for (int ni2 = 0; ni2 < 4; ++ni2) {
            uint32_t th[4], tl[4];
            ldsm4t(th, sb + Q_WHI + bOff + kwb + (uint32_t)ni2 * 32u);
            ldsm4t(tl, sb + Q_WLO + bOff + kwb + (uint32_t)ni2 * 32u);
            #pragma unroll
            for (int mi = 0; mi < 2; ++mi) {
                mma_bf16(acc[mi][2 * ni2],     ah[mi], th);
                mma_bf16(acc[mi][2 * ni2],     al[mi], th);
                mma_bf16(acc[mi][2 * ni2],     ah[mi], tl);
                mma_bf16(acc[mi][2 * ni2 + 1], ah[mi], th + 2);
                mma_bf16(acc[mi][2 * ni2 + 1], al[mi], th + 2);
                mma_bf16(acc[mi][2 * ni2 + 1], ah[mi], tl + 2);
            }
        }
    }

    // ---- epilogue: Y = Q + P[row], store, BN1 stats ----
    const int* s_row = (const int*)(smem + Q_ROW);
    float* s_sum = (float*)(smem + Q_SUM);
    float* s_ssq = (float*)(smem + Q_SSQ);
    const int g = lane >> 2, t2 = (lane & 3) * 2;

    float csum[8][2], cssq[8][2];
    #pragma unroll
    for (int ni = 0; ni < 8; ++ni) {
        csum[ni][0] = 0.f; csum[ni][1] = 0.f;
        cssq[ni][0] = 0.f; cssq[ni][1] = 0.f;
    }

    #pragma unroll
    for (int mi = 0; mi < 2; ++mi) {
        const int r0 = m0 + mi * 16 + g;
        const int G0 = s_row[r0], G1 = s_row[r0 + 8];
        const int row = mBase + r0;
        #pragma unroll
        for (int ni = 0; ni < 8; ++ni) {
            const int col = n0 + ni * 8 + t2;
            float2 p0 = *reinterpret_cast<const float2*>(g_P + (size_t)G0 * 128 + col);
            float2 p1 = *reinterpret_cast<const float2*>(g_P + (size_t)G1 * 128 + col);
            float y0 = acc[mi][ni][0] + p0.x;
            float y1 = acc[mi][ni][1] + p0.y;
            float y2 = acc[mi][ni][2] + p1.x;
            float y3 = acc[mi][ni][3] + p1.y;
            *reinterpret_cast<float2*>(g_Y + (size_t)row * 128 + col)       = make_float2(y0, y1);
            *reinterpret_cast<float2*>(g_Y + (size_t)(row + 8) * 128 + col) = make_float2(y2, y3);
            csum[ni][0] += y0 + y2;
            csum[ni][1] += y1 + y3;
            cssq[ni][0] += y0 * y0 + y2 * y2;
            cssq[ni][1] += y1 * y1 + y3 * y3;
        }
    }
    #pragma unroll
    for (int ni = 0; ni < 8; ++ni)
        #pragma unroll
        for (int par = 0; par < 2; ++par) {
            float s = csum[ni][par], q = cssq[ni][par];
            #pragma unroll
            for (int o = 4; o < 32; o <<= 1) {
                s += __shfl_xor_sync(0xFFFFFFFFu, s, o);
                q += __shfl_xor_sync(0xFFFFFFFFu, q, o);
            }
            if (g == 0) {
                atomicAdd(&s_sum[n0 + ni * 8 + t2 + par], s);
                atomicAdd(&s_ssq[n0 + ni * 8 + t2 + par], q);
            }
        }
    __syncthreads();
    if (tid < 128) {
        atomicAdd(&g_sum1[tid], s_sum[tid]);
        atomicAdd(&g_ssq1[tid], s_ssq[tid]);
    }
}

// ---------------- fp32 register-tiled SGEMM ----------------------------------
// MODE 0: A=Aext [M,128]; out=g_P (+bias)      -- P = x @ W1_top + b1
// MODE 1: A=g_h2in [M,256]; out=g_Z2 (+bias, stats)
// MODE 2: A=relu(bn2(g_Z2)); out=OutParam (+bias, relu)
template<int MODE>
__global__ __launch_bounds__(256)
void sgemm(const float* __restrict__ Aext,
           const float* __restrict__ W, const float* __restrict__ bias,
           float* __restrict__ OutParam, int M, int K, int Ntot)
{
    __shared__ float As[16][132];
    __shared__ float Ws[16][128];
    __shared__ float s_sum[128];
    __shared__ float s_ssq[128];

    const int t  = threadIdx.x;
    const int tx = t & 15;
    const int ty = t >> 4;
    const int mBase = blockIdx.x * 128;
    const int nBase = blockIdx.y * 128;
    const int lda = (MODE == 0) ? 128 : 256;

    const int r0 = t >> 2,         kq0 = t & 3;
    const int r1 = (t + 256) >> 2, kq1 = t & 3;

    const float* A = (MODE == 0) ? Aext : (MODE == 1) ? (const float*)g_h2in
                                                      : (const float*)g_Z2;

    float acc[8][8];
    #pragma unroll
    for (int i = 0; i < 8; ++i)
        #pragma unroll
        for (int j = 0; j < 8; ++j) acc[i][j] = 0.f;

    const int nK = K >> 4;
    for (int kb = 0; kb < nK; ++kb) {
        float4 v0 = make_float4(0.f, 0.f, 0.f, 0.f);
        float4 v1 = make_float4(0.f, 0.f, 0.f, 0.f);
        const int k0 = (kb << 4) + (kq0 << 2);
        const int k1 = (kb << 4) + (kq1 << 2);
        int rg0 = mBase + r0, rg1 = mBase + r1;
        if (MODE <= 1) {
            if (rg0 < M) v0 = ld4(A + (size_t)rg0 * lda + k0);
            if (rg1 < M) v1 = ld4(A + (size_t)rg1 * lda + k1);
        } else {
            if (rg0 < M) {
                float4 z = ld4(A + (size_t)rg0 * 256 + k0);
                float4 sc = ld4(g_scale2 + k0), sh = ld4(g_shift2 + k0);
                v0.x = fmaxf(fmaf(z.x, sc.x, sh.x), 0.f);
                v0.y = fmaxf(fmaf(z.y, sc.y, sh.y), 0.f);
                v0.z = fmaxf(fmaf(z.z, sc.z, sh.z), 0.f);
                v0.w = fmaxf(fmaf(z.w, sc.w, sh.w), 0.f);
            }
            if (rg1 < M) {
                float4 z = ld4(A + (size_t)rg1 * 256 + k1);
                float4 sc = ld4(g_scale2 + k1), sh = ld4(g_shift2 + k1);
                v1.x = fmaxf(fmaf(z.x, sc.x, sh.x), 0.f);
                v1.y = fmaxf(fmaf(z.y, sc.y, sh.y), 0.f);
                v1.z = fmaxf(fmaf(z.z, sc.z, sh.z), 0.f);
                v1.w = fmaxf(fmaf(z.w, sc.w, sh.w), 0.f);
            }
        }
        As[(kq0 << 2) + 0][r0] = v0.x;
        As[(kq0 << 2) + 1][r0] = v0.y;
        As[(kq0 << 2) + 2][r0] = v0.z;
        As[(kq0 << 2) + 3][r0] = v0.w;
        As[(kq1 << 2) + 0][r1] = v1.x;
        As[(kq1 << 2) + 1][r1] = v1.y;
        As[(kq1 << 2) + 2][r1] = v1.z;
        As[(kq1 << 2) + 3][r1] = v1.w;

        {
            int k = t >> 5, cq = t & 31;
            float4 w = ld4(W + (size_t)((kb << 4) + k) * Ntot + nBase + (cq << 2));
            *reinterpret_cast<float4*>(&Ws[k][cq << 2]) = w;
            k = (t + 256) >> 5;
            w = ld4(W + (size_t)((kb << 4) + k) * Ntot + nBase + (cq << 2));
            *reinterpret_cast<float4*>(&Ws[k][cq << 2]) = w;
        }
        __syncthreads();

        #pragma unroll
        for (int kk = 0; kk < 16; ++kk) {
            float a[8], b[8];
            *reinterpret_cast<float4*>(&a[0]) = *reinterpret_cast<const float4*>(&As[kk][ty << 3]);
            *reinterpret_cast<float4*>(&a[4]) = *reinterpret_cast<const float4*>(&As[kk][(ty << 3) + 4]);
            *reinterpret_cast<float4*>(&b[0]) = *reinterpret_cast<const float4*>(&Ws[kk][tx << 3]);
            *reinterpret_cast<float4*>(&b[4]) = *reinterpret_cast<const float4*>(&Ws[kk][(tx << 3) + 4]);
            #pragma unroll
            for (int i = 0; i < 8; ++i)
                #pragma unroll
                for (int j = 0; j < 8; ++j)
                    acc[i][j] = fmaf(a[i], b[j], acc[i][j]);
        }
        __syncthreads();
    }

    float bcol[8];
    #pragma unroll
    for (int j = 0; j < 8; ++j) bcol[j] = bias[nBase + (tx << 3) + j];

    if (MODE == 0) {
        #pragma unroll
        for (int i = 0; i < 8; ++i) {
            int rg = mBase + (ty << 3) + i;
            if (rg < M) {
                float yv[8];
                #pragma unroll
                for (int j = 0; j < 8; ++j) yv[j] = acc[i][j] + bcol[j];
                float* dst = g_P + (size_t)rg * Ntot + nBase + (tx << 3);
                *reinterpret_cast<float4*>(dst)     = make_float4(yv[0], yv[1], yv[2], yv[3]);
                *reinterpret_cast<float4*>(dst + 4) = make_float4(yv[4], yv[5], yv[6], yv[7]);
            }
        }
    } else if (MODE == 1) {
        float csum[8], cssq[8];
        #pragma unroll
        for (int j = 0; j < 8; ++j) { csum[j] = 0.f; cssq[j] = 0.f; }

        #pragma unroll
        for (int i = 0; i < 8; ++i) {
            int rg = mBase + (ty << 3) + i;
            if (rg < M) {
                float yv[8];
                #pragma unroll
                for (int j = 0; j < 8; ++j) {
                    float y = acc[i][j] + bcol[j];
                    yv[j] = y;
                    csum[j] += y;
                    cssq[j] = fmaf(y, y, cssq[j]);
                }
                float* dst = g_Z2 + (size_t)rg * Ntot + nBase + (tx << 3);
                *reinterpret_cast<float4*>(dst)     = make_float4(yv[0], yv[1], yv[2], yv[3]);
                *reinterpret_cast<float4*>(dst + 4) = make_float4(yv[4], yv[5], yv[6], yv[7]);
            }
        }
        __syncthreads();
        if (t < 128) { s_sum[t] = 0.f; s_ssq[t] = 0.f; }
        __syncthreads();
        #pragma unroll
        for (int j = 0; j < 8; ++j) {
            atomicAdd(&s_sum[(tx << 3) + j], csum[j]);
            atomicAdd(&s_ssq[(tx << 3) + j], cssq[j]);
        }
        __syncthreads();
        if (t < 128) {
            atomicAdd(&g_sum2[nBase + t], s_sum[t]);
            atomicAdd(&g_ssq2[nBase + t], s_ssq[t]);
        }
    } else {
        #pragma unroll
        for (int i = 0; i < 8; ++i) {
            int rg = mBase + (ty << 3) + i;
            if (rg < M) {
                float yv[8];
                #pragma unroll
                for (int j = 0; j < 8; ++j)
                    yv[j] = fmaxf(acc[i][j] + bcol[j], 0.f);
                float* dst = OutParam + (size_t)rg * Ntot + nBase + (tx << 3);
                *reinterpret_cast<float4*>(dst)     = make_float4(yv[0], yv[1], yv[2], yv[3]);
                *reinterpret_cast<float4*>(dst + 4) = make_float4(yv[4], yv[5], yv[6], yv[7]);
            }
        }
    }
}

// ---------------- BN finalize -------------------------------------------------
__global__ void finalize_bn(const float* __restrict__ gamma,
                            const float* __restrict__ beta,
                            int C, float invM, int which)
{
    int i = blockIdx.x * blockDim.x + threadIdx.x;
    if (i < C) {
        const float* sum = (which == 0) ? g_sum1 : g_sum2;
        const float* ssq = (which == 0) ? g_ssq1 : g_ssq2;
        float*     scale = (which == 0) ? g_scale1 : g_scale2;
        float*     shift = (which == 0) ? g_shift1 : g_shift2;
        float mu  = sum[i] * invM;
        float var = ssq[i] * invM - mu * mu;
        float inv = rsqrtf(var + EPS_BN);
        float sc  = gamma[i] * inv;
        scale[i] = sc;
        shift[i] = beta[i] - mu * sc;
    }
}

// ---------------- BN+ReLU then scatter-add (vector atomics) -----------------
__global__ void scatter_kernel(const int* __restrict__ ecol) {
    const int lane   = threadIdx.x & 31;
    const int warp   = (blockIdx.x * blockDim.x + threadIdx.x) >> 5;
    const int nWarps = (gridDim.x * blockDim.x) >> 5;

    float4 sc = *reinterpret_cast<const float4*>(&g_scale1[lane << 2]);
    float4 sh = *reinterpret_cast<const float4*>(&g_shift1[lane << 2]);

    for (int e = warp; e < E_EDGES; e += nWarps) {
        int c = ecol[e];
        float4 y = *reinterpret_cast<const float4*>(&g_Y[(size_t)e * 128 + (lane << 2)]);
        y.x = fmaxf(fmaf(y.x, sc.x, sh.x), 0.f);
        y.y = fmaxf(fmaf(y.y, sc.y, sh.y), 0.f);
        y.z = fmaxf(fmaf(y.z, sc.z, sh.z), 0.f);
        y.w = fmaxf(fmaf(y.w, sc.w, sh.w), 0.f);
        float* dst = &g_s[(size_t)c * 128 + (lane << 2)];
        asm volatile("red.global.add.v4.f32 [%0], {%1,%2,%3,%4};"
                     :: "l"(dst), "f"(y.x), "f"(y.y), "f"(y.z), "f"(y.w)
                     : "memory");
        if (lane == 0) atomicAdd(&g_cnt[c], 1);
    }
}

// ---------------- build h2in = concat(x, s/cnt) ------------------------------
__global__ void build_h2in(const float* __restrict__ x) {
    int idx = blockIdx.x * blockDim.x + threadIdx.x;
    int stride = gridDim.x * blockDim.x;
    const int total = N_NODES * 64;
    for (int i = idx; i < total; i += stride) {
        int n = i >> 6, q = i & 63;
        float4 v;
        if (q < 32) {
            v = ld4(x + (size_t)n * 128 + (q << 2));
        } else {
            int c = q - 32;
            v = ld4(g_s + (size_t)n * 128 + (c << 2));
            int cnt = g_cnt[n];
            float inv = (cnt > 0) ? (1.f / (float)cnt) : 0.f;
            v.x *= inv; v.y *= inv; v.z *= inv; v.w *= inv;
        }
        *reinterpret_cast<float4*>(g_h2in + (size_t)n * 256 + (q << 2)) = v;
    }
}

// ---------------- launch ------------------------------------------------------
extern "C" void kernel_launch(void* const* d_in, const int* in_sizes, int n_in,
                              void* d_out, int out_size)
{
    const float* x     = (const float*)d_in[0];
    const int*   eidx  = (const int*)  d_in[1];
    const float* eattr = (const float*)d_in[2];
    const float* W1  = (const float*)d_in[5];
    const float* b1  = (const float*)d_in[6];
    const float* g1  = (const float*)d_in[7];
    const float* be1 = (const float*)d_in[8];
    const float* W2  = (const float*)d_in[9];
    const float* b2  = (const float*)d_in[10];
    const float* g2  = (const float*)d_in[11];
    const float* be2 = (const float*)d_in[12];
    const float* Wl  = (const float*)d_in[13];
    const float* bl  = (const float*)d_in[14];
    float* out = (float*)d_out;

    const int* erow = eidx;
    const int* ecol = eidx + E_EDGES;

    cudaFuncSetAttribute(gemm1_mma, cudaFuncAttributeMaxDynamicSharedMemorySize, Q_TOT);

    // 0) zero accumulators + prep W1_bot bf16 hi/lo images
    zero_kernel<<<2048, 256>>>();
    prep_W<<<(64 * 128 + 255) / 256, 256>>>(W1);

    // 1) P = x @ W1_top + b1  (fp32, exact)
    sgemm<0><<<dim3((N_NODES + 127) / 128, 1), 256>>>(x, W1, b1, nullptr,
                                                      N_NODES, 128, 128);

    // 2) Q = eattr @ W1_bot; Y = Q + P[row]; fused BN1 stats
    gemm1_mma<<<E_EDGES / 128, 256, Q_TOT>>>(eattr, erow);

    // 3) BN1 scale/shift
    finalize_bn<<<1, 256>>>(g1, be1, 128, 1.f / (float)E_EDGES, 0);

    // 4) BN1 + ReLU + scatter
    scatter_kernel<<<2368, 256>>>(ecol);

    // 5) h2in = concat(x, s/cnt)
    build_h2in<<<2048, 256>>>(x);

    // 6) node GEMM: Z2 = h2in @ W2 + b2, fused BN2 stats
    sgemm<1><<<dim3((N_NODES + 127) / 128, 2), 256>>>(nullptr, W2, b2, nullptr,
                                                      N_NODES, 256, 256);

    // 7) BN2 scale/shift
    finalize_bn<<<1, 256>>>(g2, be2, 256, 1.f / (float)N_NODES, 1);

    // 8) out = relu(relu(bn2(Z2)) @ Wl + bl)
    sgemm<2><<<dim3((N_NODES + 127) / 128, 1), 256>>>(nullptr, Wl, bl, out,
                                                      N_NODES, 256, 128);
}

// round 7
// speedup vs baseline: 2.3510x; 1.1924x over previous
#include <cuda_runtime.h>
#include <cuda_bf16.h>
#include <cstdint>

#define E_EDGES 1600000
#define N_NODES 50000
#define EPS_BN 1e-5f

// ---------------- scratch (device globals; no allocations allowed) ----------
__device__ float g_Y[(size_t)E_EDGES * 128];      // pre-BN edge activations
__device__ float g_P[(size_t)N_NODES * 128];      // x @ W1_top + b1
__device__ float g_s[(size_t)N_NODES * 128];      // scatter-sum accumulator
__device__ int   g_cnt[N_NODES];
__device__ float g_h2in[(size_t)N_NODES * 256];
__device__ float g_Z2[(size_t)N_NODES * 256];
__device__ float g_sum1[128], g_ssq1[128], g_scale1[128], g_shift1[128];
__device__ float g_sum2[256], g_ssq2[256], g_scale2[256], g_shift2[256];
// Weight bf16 hi/lo images (padded rows, uint4-clean)
__device__ uint4 g_WimgHi[1088],  g_WimgLo[1088];   // W1_bot [64 k][136 n]
__device__ uint4 g_W1tH[2176],    g_W1tL[2176];     // W1_top [128 k][136 n]
__device__ uint4 g_W2H[8448],     g_W2L[8448];      // W2    [256 k][264 n]
__device__ uint4 g_WlH[4352],     g_WlL[4352];      // Wl    [256 k][136 n]

__device__ __forceinline__ float4 ld4(const float* p) {
    return *reinterpret_cast<const float4*>(p);
}
__device__ __forceinline__ uint32_t smem_u32(const void* p) {
    uint32_t a;
    asm("{ .reg .u64 t; cvta.to.shared.u64 t, %1; cvt.u32.u64 %0, t; }" : "=r"(a) : "l"(p));
    return a;
}

// ---------------- warp MMA primitives (sm_80 baseline) ----------------------
__device__ __forceinline__ void mma_bf16(float* c, const uint32_t* a, const uint32_t* b) {
    asm volatile(
        "mma.sync.aligned.m16n8k16.row.col.f32.bf16.bf16.f32 "
        "{%0,%1,%2,%3}, {%4,%5,%6,%7}, {%8,%9}, {%0,%1,%2,%3};"
        : "+f"(c[0]), "+f"(c[1]), "+f"(c[2]), "+f"(c[3])
        : "r"(a[0]), "r"(a[1]), "r"(a[2]), "r"(a[3]), "r"(b[0]), "r"(b[1]));
}
__device__ __forceinline__ void ldsm4(uint32_t* r, uint32_t addr) {
    asm volatile("ldmatrix.sync.aligned.m8n8.x4.shared.b16 {%0,%1,%2,%3}, [%4];"
        : "=r"(r[0]), "=r"(r[1]), "=r"(r[2]), "=r"(r[3]) : "r"(addr));
}
__device__ __forceinline__ void ldsm4t(uint32_t* r, uint32_t addr) {
    asm volatile("ldmatrix.sync.aligned.m8n8.x4.trans.shared.b16 {%0,%1,%2,%3}, [%4];"
        : "=r"(r[0]), "=r"(r[1]), "=r"(r[2]), "=r"(r[3]) : "r"(addr));
}
__device__ __forceinline__ void split_store(char* hi, char* lo, int j, float4 v) {
    __nv_bfloat16 h0 = __float2bfloat16_rn(v.x), h1 = __float2bfloat16_rn(v.y);
    __nv_bfloat16 h2 = __float2bfloat16_rn(v.z), h3 = __float2bfloat16_rn(v.w);
    __nv_bfloat162 hp0(h0, h1), hp1(h2, h3);
    __nv_bfloat162 lp0(__float2bfloat16_rn(v.x - __bfloat162float(h0)),
                       __float2bfloat16_rn(v.y - __bfloat162float(h1)));
    __nv_bfloat162 lp1(__float2bfloat16_rn(v.z - __bfloat162float(h2)),
                       __float2bfloat16_rn(v.w - __bfloat162float(h3)));
    *reinterpret_cast<uint2*>(hi + j * 8) =
        make_uint2(*reinterpret_cast<uint32_t*>(&hp0), *reinterpret_cast<uint32_t*>(&hp1));
    *reinterpret_cast<uint2*>(lo + j * 8) =
        make_uint2(*reinterpret_cast<uint32_t*>(&lp0), *reinterpret_cast<uint32_t*>(&lp1));
}

// ---------------- zero scratch ----------------------------------------------
__global__ void zero_kernel() {
    int idx = blockIdx.x * blockDim.x + threadIdx.x;
    int stride = gridDim.x * blockDim.x;
    float4 z4 = make_float4(0.f, 0.f, 0.f, 0.f);
    int total4 = N_NODES * 32;
    float4* s4 = reinterpret_cast<float4*>(g_s);
    for (int i = idx; i < total4; i += stride) s4[i] = z4;
    for (int i = idx; i < N_NODES; i += stride) g_cnt[i] = 0;
    if (idx < 128) { g_sum1[idx] = 0.f; g_ssq1[idx] = 0.f; }
    if (idx < 256) { g_sum2[idx] = 0.f; g_ssq2[idx] = 0.f; }
}

// ---------------- prep: all weight hi/lo bf16 images --------------------------
__global__ void prep_W(const float* __restrict__ W1, const float* __restrict__ W2,
                       const float* __restrict__ Wl) {
    int idx = blockIdx.x * blockDim.x + threadIdx.x;
    float f;
    uint16_t *dh, *dl;
    int off;
    if (idx < 8192) {                       // W1_bot: [64 k][128 n] -> 136 stride
        int k = idx >> 7, n = idx & 127;
        f = W1[(size_t)(128 + k) * 128 + n];
        dh = reinterpret_cast<uint16_t*>(g_WimgHi);
        dl = reinterpret_cast<uint16_t*>(g_WimgLo);
        off = k * 136 + n;
    } else if (idx < 24576) {               // W1_top: [128 k][128 n] -> 136
        int l = idx - 8192, k = l >> 7, n = l & 127;
        f = W1[(size_t)k * 128 + n];
        dh = reinterpret_cast<uint16_t*>(g_W1tH);
        dl = reinterpret_cast<uint16_t*>(g_W1tL);
        off = k * 136 + n;
    } else if (idx < 90112) {               // W2: [256 k][256 n] -> 264
        int l = idx - 24576, k = l >> 8, n = l & 255;
        f = W2[(size_t)k * 256 + n];
        dh = reinterpret_cast<uint16_t*>(g_W2H);
        dl = reinterpret_cast<uint16_t*>(g_W2L);
        off = k * 264 + n;
    } else if (idx < 122880) {              // Wl: [256 k][128 n] -> 136
        int l = idx - 90112, k = l >> 7, n = l & 127;
        f = Wl[(size_t)k * 128 + n];
        dh = reinterpret_cast<uint16_t*>(g_WlH);
        dl = reinterpret_cast<uint16_t*>(g_WlL);
        off = k * 136 + n;
    } else return;
    __nv_bfloat16 h = __float2bfloat16_rn(f);
    __nv_bfloat16 l = __float2bfloat16_rn(f - __bfloat162float(h));
    dh[off] = *reinterpret_cast<uint16_t*>(&h);
    dl[off] = *reinterpret_cast<uint16_t*>(&l);
}

// ---------------- shared SMEM layout (73216 B, 2 CTAs/SM) ---------------------
#define Q_AHI 0
#define Q_ALO 18432
#define Q_WHI 36864
#define Q_WLO 54272
#define Q_ROW 71680
#define Q_SUM 72192
#define Q_SSQ 72704
#define Q_TOT 73216
#define A_STRIDE 144

// ---------------- Q GEMM: Q = eattr @ W1_bot; Y = Q + P[row]; BN1 stats -----
__global__ void __launch_bounds__(256, 2)
gemm1_mma(const float* __restrict__ eattr, const int* __restrict__ erow) {
    extern __shared__ char smem[];
    const uint32_t sb = smem_u32(smem);
    const int tid = threadIdx.x, wid = tid >> 5, lane = tid & 31;
    const int mBase = blockIdx.x * 128;

    {
        uint4* dh = reinterpret_cast<uint4*>(smem + Q_WHI);
        uint4* dl = reinterpret_cast<uint4*>(smem + Q_WLO);
        for (int i = tid; i < 1088; i += 256) { dh[i] = g_WimgHi[i]; dl[i] = g_WimgLo[i]; }
    }
    if (tid < 128) {
        ((int*)(smem + Q_ROW))[tid] = erow[mBase + tid];
        ((float*)(smem + Q_SUM))[tid] = 0.f;
        ((float*)(smem + Q_SSQ))[tid] = 0.f;
    }
    {
        const int r = tid >> 1, h = tid & 1;
        const float4* er = reinterpret_cast<const float4*>(eattr + (size_t)(mBase + r) * 64);
        char* ahi = smem + Q_AHI + r * A_STRIDE;
        char* alo = smem + Q_ALO + r * A_STRIDE;
        #pragma unroll
        for (int jj = 0; jj < 8; ++jj) {
            int j = h * 8 + jj;
            split_store(ahi, alo, j, er[j]);
        }
    }
    __syncthreads();

    const int m0 = (wid & 3) * 32;
    const int n0 = (wid >> 2) * 64;

    float acc[2][8][4];
    #pragma unroll
    for (int mi = 0; mi < 2; ++mi)
        #pragma unroll
        for (int ni = 0; ni < 8; ++ni)
            #pragma unroll
            for (int c = 0; c < 4; ++c) acc[mi][ni][c] = 0.f;

    const uint32_t aRowOff = (uint32_t)(m0 + (lane & 15)) * (uint32_t)A_STRIDE
                           + (uint32_t)(lane >> 4) * 16u;
    const uint32_t bOff = (uint32_t)((lane & 7) + ((lane >> 3) & 1) * 8) * 272u
                        + ((uint32_t)(lane >> 4) * 8u + (uint32_t)n0) * 2u;

    #pragma unroll
    for (int kt = 0; kt < 4; ++kt) {
        const uint32_t k0b = (uint32_t)kt * 32u;
        const uint32_t kwb = (uint32_t)kt * 4352u;
        uint32_t ah[2][4], al[2][4];
        ldsm4(ah[0], sb + Q_AHI + aRowOff + k0b);
        ldsm4(ah[1], sb + Q_AHI + aRowOff + 16u * A_STRIDE + k0b);
        ldsm4(al[0], sb + Q_ALO + aRowOff + k0b);
        ldsm4(al[1], sb + Q_ALO + aRowOff + 16u * A_STRIDE + k0b);

        #pragma unroll
        for (int ni2 = 0; ni2 < 4; ++ni2) {
            uint32_t th[4], tl[4];
            ldsm4t(th, sb + Q_WHI + bOff + kwb + (uint32_t)ni2 * 32u);
            ldsm4t(tl, sb + Q_WLO + bOff + kwb + (uint32_t)ni2 * 32u);
            #pragma unroll
            for (int mi = 0; mi < 2; ++mi) {
                mma_bf16(acc[mi][2 * ni2],     ah[mi], th);
                mma_bf16(acc[mi][2 * ni2],     al[mi], th);
                mma_bf16(acc[mi][2 * ni2],     ah[mi], tl);
                mma_bf16(acc[mi][2 * ni2 + 1], ah[mi], th + 2);
                mma_bf16(acc[mi][2 * ni2 + 1], al[mi], th + 2);
                mma_bf16(acc[mi][2 * ni2 + 1], ah[mi], tl + 2);
            }
        }
    }

    const int* s_row = (const int*)(smem + Q_ROW);
    float* s_sum = (float*)(smem + Q_SUM);
    float* s_ssq = (float*)(smem + Q_SSQ);
    const int g = lane >> 2, t2 = (lane & 3) * 2;

    float csum[8][2], cssq[8][2];
    #pragma unroll
    for (int ni = 0; ni < 8; ++ni) {
        csum[ni][0] = 0.f; csum[ni][1] = 0.f;
        cssq[ni][0] = 0.f; cssq[ni][1] = 0.f;
    }

    #pragma unroll
    for (int mi = 0; mi < 2; ++mi) {
        const int r0 = m0 + mi * 16 + g;
        const int G0 = s_row[r0], G1 = s_row[r0 + 8];
        const int row = mBase + r0;
        #pragma unroll
        for (int ni = 0; ni < 8; ++ni) {
            const int col = n0 + ni * 8 + t2;
            float2 p0 = *reinterpret_cast<const float2*>(g_P + (size_t)G0 * 128 + col);
            float2 p1 = *reinterpret_cast<const float2*>(g_P + (size_t)G1 * 128 + col);
            float y0 = acc[mi][ni][0] + p0.x;
            float y1 = acc[mi][ni][1] + p0.y;
            float y2 = acc[mi][ni][2] + p1.x;
            float y3 = acc[mi][ni][3] + p1.y;
            *reinterpret_cast<float2*>(g_Y + (size_t)row * 128 + col)       = make_float2(y0, y1);
            *reinterpret_cast<float2*>(g_Y + (size_t)(row + 8) * 128 + col) = make_float2(y2, y3);
            csum[ni][0] += y0 + y2;
            csum[ni][1] += y1 + y3;
            cssq[ni][0] += y0 * y0 + y2 * y2;
            cssq[ni][1] += y1 * y1 + y3 * y3;
        }
    }
    #pragma unroll
    for (int ni = 0; ni < 8; ++ni)
        #pragma unroll
        for (int par = 0; par < 2; ++par) {
            float s = csum[ni][par], q = cssq[ni][par];
            #pragma unroll
            for (int o = 4; o < 32; o <<= 1) {
                s += __shfl_xor_sync(0xFFFFFFFFu, s, o);
                q += __shfl_xor_sync(0xFFFFFFFFu, q, o);
            }
            if (g == 0) {
                atomicAdd(&s_sum[n0 + ni * 8 + t2 + par], s);
                atomicAdd(&s_ssq[n0 + ni * 8 + t2 + par], q);
            }
        }
    __syncthreads();
    if (tid < 128) {
        atomicAdd(&g_sum1[tid], s_sum[tid]);
        atomicAdd(&g_ssq1[tid], s_ssq[tid]);
    }
}

// ---------------- unified k-chunked bf16-split MMA GEMM ----------------------
// Pointers to device globals are resolved IN DEVICE CODE via selectors
// (passing __device__ symbols as host-side kernel args reads the host shadow).
// ASEL: 0=ext arg (x), 1=g_h2in, 2=g_Z2 (+bn2+relu transform)
// WSEL: 0=W1_top(17), 1=W2(33), 2=Wl(17)
// OSEL: 0=g_P, 1=g_Z2(+BN2 stats), 2=ext out arg(+relu)
template<int KCH, int ASEL, int WSEL, int OSEL>
__global__ void __launch_bounds__(256, 2)
mma_gemm(const float* __restrict__ Aext, int ldA, int M,
         const float* __restrict__ bias, float* __restrict__ outExt, int outLd)
{
    extern __shared__ char smem[];
    const uint32_t sb = smem_u32(smem);
    const int tid = threadIdx.x, wid = tid >> 5, lane = tid & 31;
    const int mBase = blockIdx.x * 128;
    const int nBase = blockIdx.y * 128;

    const float* A = (ASEL == 0) ? Aext : (ASEL == 1) ? (const float*)g_h2in
                                                      : (const float*)g_Z2;
    const uint4* WH = (WSEL == 0) ? g_W1tH : (WSEL == 1) ? g_W2H : g_WlH;
    const uint4* WL = (WSEL == 0) ? g_W1tL : (WSEL == 1) ? g_W2L : g_WlL;
    const int WR16 = (WSEL == 1) ? 33 : 17;
    float* outp = (OSEL == 0) ? (float*)g_P : (OSEL == 1) ? (float*)g_Z2 : outExt;

    if (tid < 128) {
        ((float*)(smem + Q_ROW))[tid] = bias[nBase + tid];   // bias in Q_ROW slot
        ((float*)(smem + Q_SUM))[tid] = 0.f;
        ((float*)(smem + Q_SSQ))[tid] = 0.f;
    }

    const int m0 = (wid & 3) * 32;
    const int n0 = (wid >> 2) * 64;
    float acc[2][8][4];
    #pragma unroll
    for (int mi = 0; mi < 2; ++mi)
        #pragma unroll
        for (int ni = 0; ni < 8; ++ni)
            #pragma unroll
            for (int c = 0; c < 4; ++c) acc[mi][ni][c] = 0.f;

    const uint32_t aRowOff = (uint32_t)(m0 + (lane & 15)) * (uint32_t)A_STRIDE
                           + (uint32_t)(lane >> 4) * 16u;
    const uint32_t bOff = (uint32_t)((lane & 7) + ((lane >> 3) & 1) * 8) * 272u
                        + ((uint32_t)(lane >> 4) * 8u + (uint32_t)n0) * 2u;

    #pragma unroll 1
    for (int c = 0; c < KCH; ++c) {
        if (c) __syncthreads();
        // W chunk copy (rows c*64 .. c*64+63, 17 uint4 per row starting at nBase)
        {
            uint4* dh = reinterpret_cast<uint4*>(smem + Q_WHI);
            uint4* dl = reinterpret_cast<uint4*>(smem + Q_WLO);
            const uint4* sh = WH + (size_t)(c * 64) * WR16 + (nBase >> 3);
            const uint4* sl = WL + (size_t)(c * 64) * WR16 + (nBase >> 3);
            for (int i = tid; i < 1088; i += 256) {
                int kk = i / 17, q = i - kk * 17;
                dh[i] = sh[(size_t)kk * WR16 + q];
                dl[i] = sl[(size_t)kk * WR16 + q];
            }
        }
        // A chunk convert (64 floats per row)
        {
            const int r = tid >> 1, h = tid & 1, rg = mBase + r;
            char* ahi = smem + Q_AHI + r * A_STRIDE;
            char* alo = smem + Q_ALO + r * A_STRIDE;
            const float4* ar = reinterpret_cast<const float4*>(A + (size_t)rg * ldA + c * 64);
            #pragma unroll
            for (int jj = 0; jj < 8; ++jj) {
                int j = h * 8 + jj;
                float4 v = make_float4(0.f, 0.f, 0.f, 0.f);
                if (rg < M) {
                    v = ar[j];
                    if (ASEL == 2) {
                        int kg = c * 64 + j * 4;
                        float4 sc = ld4(g_scale2 + kg), sh4 = ld4(g_shift2 + kg);
                        v.x = fmaxf(fmaf(v.x, sc.x, sh4.x), 0.f);
                        v.y = fmaxf(fmaf(v.y, sc.y, sh4.y), 0.f);
                        v.z = fmaxf(fmaf(v.z, sc.z, sh4.z), 0.f);
                        v.w = fmaxf(fmaf(v.w, sc.w, sh4.w), 0.f);
                    }
                }
                split_store(ahi, alo, j, v);
            }
        }
        __syncthreads();

        #pragma unroll
        for (int kt = 0; kt < 4; ++kt) {
            const uint32_t k0b = (uint32_t)kt * 32u;
            const uint32_t kwb = (uint32_t)kt * 4352u;
            uint32_t ah[2][4], al[2][4];
            ldsm4(ah[0], sb + Q_AHI + aRowOff + k0b);
            ldsm4(ah[1], sb + Q_AHI + aRowOff + 16u * A_STRIDE + k0b);
            ldsm4(al[0], sb + Q_ALO + aRowOff + k0b);
            ldsm4(al[1], sb + Q_ALO + aRowOff + 16u * A_STRIDE + k0b);

            #pragma unroll
            for (int ni2 = 0; ni2 < 4; ++ni2) {
                uint32_t th[4], tl[4];
                ldsm4t(th, sb + Q_WHI + bOff + kwb + (uint32_t)ni2 * 32u);
                ldsm4t(tl, sb + Q_WLO + bOff + kwb + (uint32_t)ni2 * 32u);
                #pragma unroll
                for (int mi = 0; mi < 2; ++mi) {
                    mma_bf16(acc[mi][2 * ni2],     ah[mi], th);
                    mma_bf16(acc[mi][2 * ni2],     al[mi], th);
                    mma_bf16(acc[mi][2 * ni2],     ah[mi], tl);
                    mma_bf16(acc[mi][2 * ni2 + 1], ah[mi], th + 2);
                    mma_bf16(acc[mi][2 * ni2 + 1], al[mi], th + 2);
                    mma_bf16(acc[mi][2 * ni2 + 1], ah[mi], tl + 2);
                }
            }
        }
    }
    __syncthreads();

    // ---- epilogue ----
    const float* bs = (const float*)(smem + Q_ROW);
    float* s_sum = (float*)(smem + Q_SUM);
    float* s_ssq = (float*)(smem + Q_SSQ);
    const int g = lane >> 2, t2 = (lane & 3) * 2;

    float csum[8][2], cssq[8][2];
    if (OSEL == 1) {
        #pragma unroll
        for (int ni = 0; ni < 8; ++ni) {
            csum[ni][0] = 0.f; csum[ni][1] = 0.f;
            cssq[ni][0] = 0.f; cssq[ni][1] = 0.f;
        }
    }

    #pragma unroll
    for (int mi = 0; mi < 2; ++mi) {
        const int row = mBase + m0 + mi * 16 + g;
        const bool v0 = row < M, v1 = (row + 8) < M;
        #pragma unroll
        for (int ni = 0; ni < 8; ++ni) {
            const int col = n0 + ni * 8 + t2;
            float b0 = bs[col], b1 = bs[col + 1];
            float y0 = acc[mi][ni][0] + b0;
            float y1 = acc[mi][ni][1] + b1;
            float y2 = acc[mi][ni][2] + b0;
            float y3 = acc[mi][ni][3] + b1;
            if (OSEL == 2) {
                y0 = fmaxf(y0, 0.f); y1 = fmaxf(y1, 0.f);
                y2 = fmaxf(y2, 0.f); y3 = fmaxf(y3, 0.f);
            }
            if (v0)
                *reinterpret_cast<float2*>(outp + (size_t)row * outLd + nBase + col)
                    = make_float2(y0, y1);
            if (v1)
                *reinterpret_cast<float2*>(outp + (size_t)(row + 8) * outLd + nBase + col)
                    = make_float2(y2, y3);
            if (OSEL == 1) {
                if (v0) {
                    csum[ni][0] += y0; csum[ni][1] += y1;
                    cssq[ni][0] += y0 * y0; cssq[ni][1] += y1 * y1;
                }
                if (v1) {
                    csum[ni][0] += y2; csum[ni][1] += y3;
                    cssq[ni][0] += y2 * y2; cssq[ni][1] += y3 * y3;
                }
            }
        }
    }
    if (OSEL == 1) {
        #pragma unroll
        for (int ni = 0; ni < 8; ++ni)
            #pragma unroll
            for (int par = 0; par < 2; ++par) {
                float s = csum[ni][par], q = cssq[ni][par];
                #pragma unroll
                for (int o = 4; o < 32; o <<= 1) {
                    s += __shfl_xor_sync(0xFFFFFFFFu, s, o);
                    q += __shfl_xor_sync(0xFFFFFFFFu, q, o);
                }
                if (g == 0) {
                    atomicAdd(&s_sum[n0 + ni * 8 + t2 + par], s);
                    atomicAdd(&s_ssq[n0 + ni * 8 + t2 + par], q);
                }
            }
        __syncthreads();
        if (tid < 128) {
            atomicAdd(&g_sum2[nBase + tid], s_sum[tid]);
            atomicAdd(&g_ssq2[nBase + tid], s_ssq[tid]);
        }
    }
}

// ---------------- BN finalize -------------------------------------------------
__global__ void finalize_bn(const float* __restrict__ gamma,
                            const float* __restrict__ beta,
                            int C, float invM, int which)
{
    int i = blockIdx.x * blockDim.x + threadIdx.x;
    if (i < C) {
        const float* sum = (which == 0) ? g_sum1 : g_sum2;
        const float* ssq = (which == 0) ? g_ssq1 : g_ssq2;
        float*     scale = (which == 0) ? g_scale1 : g_scale2;
        float*     shift = (which == 0) ? g_shift1 : g_shift2;
        float mu  = sum[i] * invM;
        float var = ssq[i] * invM - mu * mu;
        float inv = rsqrtf(var + EPS_BN);
        float sc  = gamma[i] * inv;
        scale[i] = sc;
        shift[i] = beta[i] - mu * sc;
    }
}

// ---------------- BN+ReLU then scatter-add (vector atomics) -----------------
__global__ void scatter_kernel(const int* __restrict__ ecol) {
    const int lane   = threadIdx.x & 31;
    const int warp   = (blockIdx.x * blockDim.x + threadIdx.x) >> 5;
    const int nWarps = (gridDim.x * blockDim.x) >> 5;

    float4 sc = *reinterpret_cast<const float4*>(&g_scale1[lane << 2]);
    float4 sh = *reinterpret_cast<const float4*>(&g_shift1[lane << 2]);

    for (int e = warp; e < E_EDGES; e += nWarps) {
        int c = ecol[e];
        float4 y = *reinterpret_cast<const float4*>(&g_Y[(size_t)e * 128 + (lane << 2)]);
        y.x = fmaxf(fmaf(y.x, sc.x, sh.x), 0.f);
        y.y = fmaxf(fmaf(y.y, sc.y, sh.y), 0.f);
        y.z = fmaxf(fmaf(y.z, sc.z, sh.z), 0.f);
        y.w = fmaxf(fmaf(y.w, sc.w, sh.w), 0.f);
        float* dst = &g_s[(size_t)c * 128 + (lane << 2)];
        asm volatile("red.global.add.v4.f32 [%0], {%1,%2,%3,%4};"
                     :: "l"(dst), "f"(y.x), "f"(y.y), "f"(y.z), "f"(y.w)
                     : "memory");
        if (lane == 0) atomicAdd(&g_cnt[c], 1);
    }
}

// ---------------- build h2in = concat(x, s/cnt) ------------------------------
__global__ void build_h2in(const float* __restrict__ x) {
    int idx = blockIdx.x * blockDim.x + threadIdx.x;
    int stride = gridDim.x * blockDim.x;
    const int total = N_NODES * 64;
    for (int i = idx; i < total; i += stride) {
        int n = i >> 6, q = i & 63;
        float4 v;
        if (q < 32) {
            v = ld4(x + (size_t)n * 128 + (q << 2));
        } else {
            int c = q - 32;
            v = ld4(g_s + (size_t)n * 128 + (c << 2));
            int cnt = g_cnt[n];
            float inv = (cnt > 0) ? (1.f / (float)cnt) : 0.f;
            v.x *= inv; v.y *= inv; v.z *= inv; v.w *= inv;
        }
        *reinterpret_cast<float4*>(g_h2in + (size_t)n * 256 + (q << 2)) = v;
    }
}

// ---------------- launch ------------------------------------------------------
extern "C" void kernel_launch(void* const* d_in, const int* in_sizes, int n_in,
                              void* d_out, int out_size)
{
    const float* x     = (const float*)d_in[0];
    const int*   eidx  = (const int*)  d_in[1];
    const float* eattr = (const float*)d_in[2];
    const float* W1  = (const float*)d_in[5];
    const float* b1  = (const float*)d_in[6];
    const float* g1  = (const float*)d_in[7];
    const float* be1 = (const float*)d_in[8];
    const float* W2  = (const float*)d_in[9];
    const float* b2  = (const float*)d_in[10];
    const float* g2  = (const float*)d_in[11];
    const float* be2 = (const float*)d_in[12];
    const float* Wl  = (const float*)d_in[13];
    const float* bl  = (const float*)d_in[14];
    float* out = (float*)d_out;

    const int* erow = eidx;
    const int* ecol = eidx + E_EDGES;

    cudaFuncSetAttribute(gemm1_mma, cudaFuncAttributeMaxDynamicSharedMemorySize, Q_TOT);
    cudaFuncSetAttribute(mma_gemm<2, 0, 0, 0>, cudaFuncAttributeMaxDynamicSharedMemorySize, Q_TOT);
    cudaFuncSetAttribute(mma_gemm<4, 1, 1, 1>, cudaFuncAttributeMaxDynamicSharedMemorySize, Q_TOT);
    cudaFuncSetAttribute(mma_gemm<4, 2, 2, 2>, cudaFuncAttributeMaxDynamicSharedMemorySize, Q_TOT);

    const int MB = (N_NODES + 127) / 128;   // 391

    // 0) zero accumulators + prep all weight images
    zero_kernel<<<2048, 256>>>();
    prep_W<<<480, 256>>>(W1, W2, Wl);

    // 1) P = x @ W1_top + b1
    mma_gemm<2, 0, 0, 0><<<dim3(MB, 1), 256, Q_TOT>>>(x, 128, N_NODES, b1, nullptr, 128);

    // 2) Q = eattr @ W1_bot; Y = Q + P[row]; fused BN1 stats
    gemm1_mma<<<E_EDGES / 128, 256, Q_TOT>>>(eattr, erow);

    // 3) BN1 scale/shift
    finalize_bn<<<1, 256>>>(g1, be1, 128, 1.f / (float)E_EDGES, 0);

    // 4) BN1 + ReLU + scatter
    scatter_kernel<<<2368, 256>>>(ecol);

    // 5) h2in = concat(x, s/cnt)
    build_h2in<<<2048, 256>>>(x);

    // 6) Z2 = h2in @ W2 + b2, fused BN2 stats
    mma_gemm<4, 1, 1, 1><<<dim3(MB, 2), 256, Q_TOT>>>(nullptr, 256, N_NODES, b2, nullptr, 256);

    // 7) BN2 scale/shift
    finalize_bn<<<1, 256>>>(g2, be2, 256, 1.f / (float)N_NODES, 1);

    // 8) out = relu(relu(bn2(Z2)) @ Wl + bl)
    mma_gemm<4, 2, 2, 2><<<dim3(MB, 1), 256, Q_TOT>>>(nullptr, 256, N_NODES, bl, out, 128);
}

// round 8
// speedup vs baseline: 2.3768x; 1.0110x over previous
#include <cuda_runtime.h>
#include <cuda_bf16.h>
#include <cstdint>

#define E_EDGES 1600000
#define N_NODES 50000
#define EPS_BN 1e-5f

// ---------------- scratch (device globals; no allocations allowed) ----------
__device__ float g_Y[(size_t)E_EDGES * 128];      // pre-BN edge activations
__device__ float g_P[(size_t)N_NODES * 128];      // x @ W1_top + b1
__device__ float g_s[(size_t)N_NODES * 128];      // scatter-sum accumulator
__device__ int   g_cnt[N_NODES];
__device__ float g_h2in[(size_t)N_NODES * 256];
__device__ float g_Z2[(size_t)N_NODES * 256];
__device__ float g_sum1[128], g_ssq1[128], g_scale1[128], g_shift1[128];
__device__ float g_sum2[256], g_ssq2[256], g_scale2[256], g_shift2[256];
// Weight bf16 hi/lo images (padded rows, uint4-clean)
__device__ uint4 g_WimgHi[1088],  g_WimgLo[1088];   // W1_bot [64 k][136 n]
__device__ uint4 g_W1tH[2176],    g_W1tL[2176];     // W1_top [128 k][136 n]
__device__ uint4 g_W2H[8448],     g_W2L[8448];      // W2    [256 k][264 n]
__device__ uint4 g_WlH[4352],     g_WlL[4352];      // Wl    [256 k][136 n]

__device__ __forceinline__ float4 ld4(const float* p) {
    return *reinterpret_cast<const float4*>(p);
}
__device__ __forceinline__ uint32_t smem_u32(const void* p) {
    uint32_t a;
    asm("{ .reg .u64 t; cvta.to.shared.u64 t, %1; cvt.u32.u64 %0, t; }" : "=r"(a) : "l"(p));
    return a;
}

// ---------------- warp MMA primitives (sm_80 baseline) ----------------------
__device__ __forceinline__ void mma_bf16(float* c, const uint32_t* a, const uint32_t* b) {
    asm volatile(
        "mma.sync.aligned.m16n8k16.row.col.f32.bf16.bf16.f32 "
        "{%0,%1,%2,%3}, {%4,%5,%6,%7}, {%8,%9}, {%0,%1,%2,%3};"
        : "+f"(c[0]), "+f"(c[1]), "+f"(c[2]), "+f"(c[3])
        : "r"(a[0]), "r"(a[1]), "r"(a[2]), "r"(a[3]), "r"(b[0]), "r"(b[1]));
}
__device__ __forceinline__ void ldsm4(uint32_t* r, uint32_t addr) {
    asm volatile("ldmatrix.sync.aligned.m8n8.x4.shared.b16 {%0,%1,%2,%3}, [%4];"
        : "=r"(r[0]), "=r"(r[1]), "=r"(r[2]), "=r"(r[3]) : "r"(addr));
}
__device__ __forceinline__ void ldsm4t(uint32_t* r, uint32_t addr) {
    asm volatile("ldmatrix.sync.aligned.m8n8.x4.trans.shared.b16 {%0,%1,%2,%3}, [%4];"
        : "=r"(r[0]), "=r"(r[1]), "=r"(r[2]), "=r"(r[3]) : "r"(addr));
}
__device__ __forceinline__ void split_store(char* hi, char* lo, int j, float4 v) {
    __nv_bfloat16 h0 = __float2bfloat16_rn(v.x), h1 = __float2bfloat16_rn(v.y);
    __nv_bfloat16 h2 = __float2bfloat16_rn(v.z), h3 = __float2bfloat16_rn(v.w);
    __nv_bfloat162 hp0(h0, h1), hp1(h2, h3);
    __nv_bfloat162 lp0(__float2bfloat16_rn(v.x - __bfloat162float(h0)),
                       __float2bfloat16_rn(v.y - __bfloat162float(h1)));
    __nv_bfloat162 lp1(__float2bfloat16_rn(v.z - __bfloat162float(h2)),
                       __float2bfloat16_rn(v.w - __bfloat162float(h3)));
    *reinterpret_cast<uint2*>(hi + j * 8) =
        make_uint2(*reinterpret_cast<uint32_t*>(&hp0), *reinterpret_cast<uint32_t*>(&hp1));
    *reinterpret_cast<uint2*>(lo + j * 8) =
        make_uint2(*reinterpret_cast<uint32_t*>(&lp0), *reinterpret_cast<uint32_t*>(&lp1));
}
__device__ __forceinline__ void cp_async16(uint32_t saddr, const void* gptr) {
    asm volatile("cp.async.cg.shared.global [%0], [%1], 16;"
                 :: "r"(saddr), "l"(gptr) : "memory");
}

// ---------------- zero scratch ----------------------------------------------
__global__ void zero_kernel() {
    int idx = blockIdx.x * blockDim.x + threadIdx.x;
    int stride = gridDim.x * blockDim.x;
    float4 z4 = make_float4(0.f, 0.f, 0.f, 0.f);
    int total4 = N_NODES * 32;
    float4* s4 = reinterpret_cast<float4*>(g_s);
    for (int i = idx; i < total4; i += stride) s4[i] = z4;
    for (int i = idx; i < N_NODES; i += stride) g_cnt[i] = 0;
    if (idx < 128) { g_sum1[idx] = 0.f; g_ssq1[idx] = 0.f; }
    if (idx < 256) { g_sum2[idx] = 0.f; g_ssq2[idx] = 0.f; }
}

// ---------------- prep: all weight hi/lo bf16 images --------------------------
__global__ void prep_W(const float* __restrict__ W1, const float* __restrict__ W2,
                       const float* __restrict__ Wl) {
    int idx = blockIdx.x * blockDim.x + threadIdx.x;
    float f;
    uint16_t *dh, *dl;
    int off;
    if (idx < 8192) {                       // W1_bot: [64 k][128 n] -> 136 stride
        int k = idx >> 7, n = idx & 127;
        f = W1[(size_t)(128 + k) * 128 + n];
        dh = reinterpret_cast<uint16_t*>(g_WimgHi);
        dl = reinterpret_cast<uint16_t*>(g_WimgLo);
        off = k * 136 + n;
    } else if (idx < 24576) {               // W1_top: [128 k][128 n] -> 136
        int l = idx - 8192, k = l >> 7, n = l & 127;
        f = W1[(size_t)k * 128 + n];
        dh = reinterpret_cast<uint16_t*>(g_W1tH);
        dl = reinterpret_cast<uint16_t*>(g_W1tL);
        off = k * 136 + n;
    } else if (idx < 90112) {               // W2: [256 k][256 n] -> 264
        int l = idx - 24576, k = l >> 8, n = l & 255;
        f = W2[(size_t)k * 256 + n];
        dh = reinterpret_cast<uint16_t*>(g_W2H);
        dl = reinterpret_cast<uint16_t*>(g_W2L);
        off = k * 264 + n;
    } else if (idx < 122880) {              // Wl: [256 k][128 n] -> 136
        int l = idx - 90112, k = l >> 7, n = l & 127;
        f = Wl[(size_t)k * 128 + n];
        dh = reinterpret_cast<uint16_t*>(g_WlH);
        dl = reinterpret_cast<uint16_t*>(g_WlL);
        off = k * 136 + n;
    } else return;
    __nv_bfloat16 h = __float2bfloat16_rn(f);
    __nv_bfloat16 l = __float2bfloat16_rn(f - __bfloat162float(h));
    dh[off] = *reinterpret_cast<uint16_t*>(&h);
    dl[off] = *reinterpret_cast<uint16_t*>(&l);
}

// ---------------- shared SMEM layout ------------------------------------------
#define Q_AHI 0
#define Q_ALO 18432
#define Q_WHI 36864
#define Q_WLO 54272
#define Q_ROW 71680          // (mma_gemm: bias slot)
#define Q_SUM 72192
#define Q_SSQ 72704
#define Q_TOT 73216          // mma_gemm footprint
#define A_STRIDE 144
// gemm1 persistent additions:
#define G_STAGE 71680        // raw eattr tile [128][272B] = 34816
#define G_SROWSTG 106496     // staged erow (512)
#define G_SROW 107008        // active erow (512)
#define G_SUM 107520
#define G_SSQ 108032
#define G_TOT 108544
#define G_GRID 296
#define G_NT (E_EDGES / 128)

// ---------------- gemm1 (persistent): Q = eattr @ W1_bot; Y = Q + P[row] -----
__global__ void __launch_bounds__(256, 2)
gemm1_mma(const float* __restrict__ eattr, const int* __restrict__ erow) {
    extern __shared__ char smem[];
    const uint32_t sb = smem_u32(smem);
    const int tid = threadIdx.x, wid = tid >> 5, lane = tid & 31;

    // one-time: W images, stat init
    {
        uint4* dh = reinterpret_cast<uint4*>(smem + Q_WHI);
        uint4* dl = reinterpret_cast<uint4*>(smem + Q_WLO);
        for (int i = tid; i < 1088; i += 256) { dh[i] = g_WimgHi[i]; dl[i] = g_WimgLo[i]; }
    }
    if (tid < 128) {
        ((float*)(smem + G_SUM))[tid] = 0.f;
        ((float*)(smem + G_SSQ))[tid] = 0.f;
    }

    // prologue: stage first tile
    {
        int t0 = blockIdx.x;
        const char* src = (const char*)(eattr + (size_t)t0 * 128 * 64);
        #pragma unroll
        for (int i = tid; i < 2048; i += 256) {
            int r = i >> 4, q = i & 15;
            cp_async16(sb + G_STAGE + r * 272 + q * 16, src + (size_t)r * 256 + q * 16);
        }
        if (tid < 32)
            cp_async16(sb + G_SROWSTG + tid * 16,
                       (const char*)(erow + (size_t)t0 * 128) + tid * 16);
        asm volatile("cp.async.commit_group;" ::: "memory");
    }

    const int m0 = (wid & 3) * 32;
    const int n0 = (wid >> 2) * 64;
    const uint32_t aRowOff = (uint32_t)(m0 + (lane & 15)) * (uint32_t)A_STRIDE
                           + (uint32_t)(lane >> 4) * 16u;
    const uint32_t bOff = (uint32_t)((lane & 7) + ((lane >> 3) & 1) * 8) * 272u
                        + ((uint32_t)(lane >> 4) * 8u + (uint32_t)n0) * 2u;
    const int g = lane >> 2, t2 = (lane & 3) * 2;
    const int* s_row = (const int*)(smem + G_SROW);
    float* s_sum = (float*)(smem + G_SUM);
    float* s_ssq = (float*)(smem + G_SSQ);

    for (int t = blockIdx.x; t < G_NT; t += G_GRID) {
        asm volatile("cp.async.wait_group 0;" ::: "memory");
        __syncthreads();   // stage ready; prior epilogue done (A images + s_row free)

        // convert stage -> A hi/lo images; publish erow
        {
            const int r = tid >> 1, h = tid & 1;
            const char* srow = smem + G_STAGE + r * 272;
            char* ahi = smem + Q_AHI + r * A_STRIDE;
            char* alo = smem + Q_ALO + r * A_STRIDE;
            #pragma unroll
            for (int jj = 0; jj < 8; ++jj) {
                int j = h * 8 + jj;
                float4 v = *reinterpret_cast<const float4*>(srow + j * 16);
                split_store(ahi, alo, j, v);
            }
            if (tid < 128)
                ((int*)(smem + G_SROW))[tid] = ((const int*)(smem + G_SROWSTG))[tid];
        }
        __syncthreads();   // images + s_row visible; stage consumed

        // stage next tile (overlaps MMA + epilogue)
        if (t + G_GRID < G_NT) {
            int tn = t + G_GRID;
            const char* src = (const char*)(eattr + (size_t)tn * 128 * 64);
            #pragma unroll
            for (int i = tid; i < 2048; i += 256) {
                int r = i >> 4, q = i & 15;
                cp_async16(sb + G_STAGE + r * 272 + q * 16, src + (size_t)r * 256 + q * 16);
            }
            if (tid < 32)
                cp_async16(sb + G_SROWSTG + tid * 16,
                           (const char*)(erow + (size_t)tn * 128) + tid * 16);
            asm volatile("cp.async.commit_group;" ::: "memory");
        }

        // ---- MMA ----
        float acc[2][8][4];
        #pragma unroll
        for (int mi = 0; mi < 2; ++mi)
            #pragma unroll
            for (int ni = 0; ni < 8; ++ni)
                #pragma unroll
                for (int c = 0; c < 4; ++c) acc[mi][ni][c] = 0.f;

        #pragma unroll
        for (int kt = 0; kt < 4; ++kt) {
            const uint32_t k0b = (uint32_t)kt * 32u;
            const uint32_t kwb = (uint32_t)kt * 4352u;
            uint32_t ah[2][4], al[2][4];
            ldsm4(ah[0], sb + Q_AHI + aRowOff + k0b);
            ldsm4(ah[1], sb + Q_AHI + aRowOff + 16u * A_STRIDE + k0b);
            ldsm4(al[0], sb + Q_ALO + aRowOff + k0b);
            ldsm4(al[1], sb + Q_ALO + aRowOff + 16u * A_STRIDE + k0b);

            #pragma unroll
            for (int ni2 = 0; ni2 < 4; ++ni2) {
                uint32_t th[4], tl[4];
                ldsm4t(th, sb + Q_WHI + bOff + kwb + (uint32_t)ni2 * 32u);
                ldsm4t(tl, sb + Q_WLO + bOff + kwb + (uint32_t)ni2 * 32u);
                #pragma unroll
                for (int mi = 0; mi < 2; ++mi) {
                    mma_bf16(acc[mi][2 * ni2],     ah[mi], th);
                    mma_bf16(acc[mi][2 * ni2],     al[mi], th);
                    mma_bf16(acc[mi][2 * ni2],     ah[mi], tl);
                    mma_bf16(acc[mi][2 * ni2 + 1], ah[mi], th + 2);
                    mma_bf16(acc[mi][2 * ni2 + 1], al[mi], th + 2);
                    mma_bf16(acc[mi][2 * ni2 + 1], ah[mi], tl + 2);
                }
            }
        }

        // ---- epilogue: Y = Q + P[row], store, BN1 stats (smem-resident) ----
        const int mBase = t * 128;
        float csum[8][2], cssq[8][2];
        #pragma unroll
        for (int ni = 0; ni < 8; ++ni) {
            csum[ni][0] = 0.f; csum[ni][1] = 0.f;
            cssq[ni][0] = 0.f; cssq[ni][1] = 0.f;
        }

        #pragma unroll
        for (int mi = 0; mi < 2; ++mi) {
            const int r0 = m0 + mi * 16 + g;
            const int G0 = s_row[r0], G1 = s_row[r0 + 8];
            const int row = mBase + r0;
            #pragma unroll
            for (int ni = 0; ni < 8; ++ni) {
                const int col = n0 + ni * 8 + t2;
                float2 p0 = *reinterpret_cast<const float2*>(g_P + (size_t)G0 * 128 + col);
                float2 p1 = *reinterpret_cast<const float2*>(g_P + (size_t)G1 * 128 + col);
                float y0 = acc[mi][ni][0] + p0.x;
                float y1 = acc[mi][ni][1] + p0.y;
                float y2 = acc[mi][ni][2] + p1.x;
                float y3 = acc[mi][ni][3] + p1.y;
                *reinterpret_cast<float2*>(g_Y + (size_t)row * 128 + col)       = make_float2(y0, y1);
                *reinterpret_cast<float2*>(g_Y + (size_t)(row + 8) * 128 + col) = make_float2(y2, y3);
                csum[ni][0] += y0 + y2;
                csum[ni][1] += y1 + y3;
                cssq[ni][0] += y0 * y0 + y2 * y2;
                cssq[ni][1] += y1 * y1 + y3 * y3;
            }
        }
        #pragma unroll
        for (int ni = 0; ni < 8; ++ni)
            #pragma unroll
            for (int par = 0; par < 2; ++par) {
                float s = csum[ni][par], q = cssq[ni][par];
                #pragma unroll
                for (int o = 4; o < 32; o <<= 1) {
                    s += __shfl_xor_sync(0xFFFFFFFFu, s, o);
                    q += __shfl_xor_sync(0xFFFFFFFFu, q, o);
                }
                if (g == 0) {
                    atomicAdd(&s_sum[n0 + ni * 8 + t2 + par], s);
                    atomicAdd(&s_ssq[n0 + ni * 8 + t2 + par], q);
                }
            }
    }

    // single global flush of BN1 partial stats
    __syncthreads();
    if (tid < 128) {
        atomicAdd(&g_sum1[tid], s_sum[tid]);
        atomicAdd(&g_ssq1[tid], s_ssq[tid]);
    }
}

// ---------------- unified k-chunked bf16-split MMA GEMM ----------------------
// ASEL: 0=ext arg (x), 1=g_h2in, 2=g_Z2 (+bn2+relu transform)
// WSEL: 0=W1_top(17), 1=W2(33), 2=Wl(17)
// OSEL: 0=g_P, 1=g_Z2(+BN2 stats), 2=ext out arg(+relu)
template<int KCH, int ASEL, int WSEL, int OSEL>
__global__ void __launch_bounds__(256, 2)
mma_gemm(const float* __restrict__ Aext, int ldA, int M,
         const float* __restrict__ bias, float* __restrict__ outExt, int outLd)
{
    extern __shared__ char smem[];
    const uint32_t sb = smem_u32(smem);
    const int tid = threadIdx.x, wid = tid >> 5, lane = tid & 31;
    const int mBase = blockIdx.x * 128;
    const int nBase = blockIdx.y * 128;

    const float* A = (ASEL == 0) ? Aext : (ASEL == 1) ? (const float*)g_h2in
                                                      : (const float*)g_Z2;
    const uint4* WH = (WSEL == 0) ? g_W1tH : (WSEL == 1) ? g_W2H : g_WlH;
    const uint4* WL = (WSEL == 0) ? g_W1tL : (WSEL == 1) ? g_W2L : g_WlL;
    const int WR16 = (WSEL == 1) ? 33 : 17;
    float* outp = (OSEL == 0) ? (float*)g_P : (OSEL == 1) ? (float*)g_Z2 : outExt;

    if (tid < 128) {
        ((float*)(smem + Q_ROW))[tid] = bias[nBase + tid];
        ((float*)(smem + Q_SUM))[tid] = 0.f;
        ((float*)(smem + Q_SSQ))[tid] = 0.f;
    }

    const int m0 = (wid & 3) * 32;
    const int n0 = (wid >> 2) * 64;
    float acc[2][8][4];
    #pragma unroll
    for (int mi = 0; mi < 2; ++mi)
        #pragma unroll
        for (int ni = 0; ni < 8; ++ni)
            #pragma unroll
            for (int c = 0; c < 4; ++c) acc[mi][ni][c] = 0.f;

    const uint32_t aRowOff = (uint32_t)(m0 + (lane & 15)) * (uint32_t)A_STRIDE
                           + (uint32_t)(lane >> 4) * 16u;
    const uint32_t bOff = (uint32_t)((lane & 7) + ((lane >> 3) & 1) * 8) * 272u
                        + ((uint32_t)(lane >> 4) * 8u + (uint32_t)n0) * 2u;

    #pragma unroll 1
    for (int c = 0; c < KCH; ++c) {
        if (c) __syncthreads();
        {
            uint4* dh = reinterpret_cast<uint4*>(smem + Q_WHI);
            uint4* dl = reinterpret_cast<uint4*>(smem + Q_WLO);
            const uint4* sh = WH + (size_t)(c * 64) * WR16 + (nBase >> 3);
            const uint4* sl = WL + (size_t)(c * 64) * WR16 + (nBase >> 3);
            for (int i = tid; i < 1088; i += 256) {
                int kk = i / 17, q = i - kk * 17;
                dh[i] = sh[(size_t)kk * WR16 + q];
                dl[i] = sl[(size_t)kk * WR16 + q];
            }
        }
        {
            const int r = tid >> 1, h = tid & 1, rg = mBase + r;
            char* ahi = smem + Q_AHI + r * A_STRIDE;
            char* alo = smem + Q_ALO + r * A_STRIDE;
            const float4* ar = reinterpret_cast<const float4*>(A + (size_t)rg * ldA + c * 64);
            #pragma unroll
            for (int jj = 0; jj < 8; ++jj) {
                int j = h * 8 + jj;
                float4 v = make_float4(0.f, 0.f, 0.f, 0.f);
                if (rg < M) {
                    v = ar[j];
                    if (ASEL == 2) {
                        int kg = c * 64 + j * 4;
                        float4 sc = ld4(g_scale2 + kg), sh4 = ld4(g_shift2 + kg);
                        v.x = fmaxf(fmaf(v.x, sc.x, sh4.x), 0.f);
                        v.y = fmaxf(fmaf(v.y, sc.y, sh4.y), 0.f);
                        v.z = fmaxf(fmaf(v.z, sc.z, sh4.z), 0.f);
                        v.w = fmaxf(fmaf(v.w, sc.w, sh4.w), 0.f);
                    }
                }
                split_store(ahi, alo, j, v);
            }
        }
        __syncthreads();

        #pragma unroll
        for (int kt = 0; kt < 4; ++kt) {
            const uint32_t k0b = (uint32_t)kt * 32u;
            const uint32_t kwb = (uint32_t)kt * 4352u;
            uint32_t ah[2][4], al[2][4];
            ldsm4(ah[0], sb + Q_AHI + aRowOff + k0b);
            ldsm4(ah[1], sb + Q_AHI + aRowOff + 16u * A_STRIDE + k0b);
            ldsm4(al[0], sb + Q_ALO + aRowOff + k0b);
            ldsm4(al[1], sb + Q_ALO + aRowOff + 16u * A_STRIDE + k0b);

            #pragma unroll
            for (int ni2 = 0; ni2 < 4; ++ni2) {
                uint32_t th[4], tl[4];
                ldsm4t(th, sb + Q_WHI + bOff + kwb + (uint32_t)ni2 * 32u);
                ldsm4t(tl, sb + Q_WLO + bOff + kwb + (uint32_t)ni2 * 32u);
                #pragma unroll
                for (int mi = 0; mi < 2; ++mi) {
                    mma_bf16(acc[mi][2 * ni2],     ah[mi], th);
                    mma_bf16(acc[mi][2 * ni2],     al[mi], th);
                    mma_bf16(acc[mi][2 * ni2],     ah[mi], tl);
                    mma_bf16(acc[mi][2 * ni2 + 1], ah[mi], th + 2);
                    mma_bf16(acc[mi][2 * ni2 + 1], al[mi], th + 2);
                    mma_bf16(acc[mi][2 * ni2 + 1], ah[mi], tl + 2);
                }
            }
        }
    }
    __syncthreads();

    const float* bs = (const float*)(smem + Q_ROW);
    float* s_sum = (float*)(smem + Q_SUM);
    float* s_ssq = (float*)(smem + Q_SSQ);
    const int g = lane >> 2, t2 = (lane & 3) * 2;

    float csum[8][2], cssq[8][2];
    if (OSEL == 1) {
        #pragma unroll
        for (int ni = 0; ni < 8; ++ni) {
            csum[ni][0] = 0.f; csum[ni][1] = 0.f;
            cssq[ni][0] = 0.f; cssq[ni][1] = 0.f;
        }
    }

    #pragma unroll
    for (int mi = 0; mi < 2; ++mi) {
        const int row = mBase + m0 + mi * 16 + g;
        const bool v0 = row < M, v1 = (row + 8) < M;
        #pragma unroll
        for (int ni = 0; ni < 8; ++ni) {
            const int col = n0 + ni * 8 + t2;
            float b0 = bs[col], b1 = bs[col + 1];
            float y0 = acc[mi][ni][0] + b0;
            float y1 = acc[mi][ni][1] + b1;
            float y2 = acc[mi][ni][2] + b0;
            float y3 = acc[mi][ni][3] + b1;
            if (OSEL == 2) {
                y0 = fmaxf(y0, 0.f); y1 = fmaxf(y1, 0.f);
                y2 = fmaxf(y2, 0.f); y3 = fmaxf(y3, 0.f);
            }
            if (v0)
                *reinterpret_cast<float2*>(outp + (size_t)row * outLd + nBase + col)
                    = make_float2(y0, y1);
            if (v1)
                *reinterpret_cast<float2*>(outp + (size_t)(row + 8) * outLd + nBase + col)
                    = make_float2(y2, y3);
            if (OSEL == 1) {
                if (v0) {
                    csum[ni][0] += y0; csum[ni][1] += y1;
                    cssq[ni][0] += y0 * y0; cssq[ni][1] += y1 * y1;
                }
                if (v1) {
                    csum[ni][0] += y2; csum[ni][1] += y3;
                    cssq[ni][0] += y2 * y2; cssq[ni][1] += y3 * y3;
                }
            }
        }
    }
    if (OSEL == 1) {
        #pragma unroll
        for (int ni = 0; ni < 8; ++ni)
            #pragma unroll
            for (int par = 0; par < 2; ++par) {
                float s = csum[ni][par], q = cssq[ni][par];
                #pragma unroll
                for (int o = 4; o < 32; o <<= 1) {
                    s += __shfl_xor_sync(0xFFFFFFFFu, s, o);
                    q += __shfl_xor_sync(0xFFFFFFFFu, q, o);
                }
                if (g == 0) {
                    atomicAdd(&s_sum[n0 + ni * 8 + t2 + par], s);
                    atomicAdd(&s_ssq[n0 + ni * 8 + t2 + par], q);
                }
            }
        __syncthreads();
        if (tid < 128) {
            atomicAdd(&g_sum2[nBase + tid], s_sum[tid]);
            atomicAdd(&g_ssq2[nBase + tid], s_ssq[tid]);
        }
    }
}

// ---------------- BN finalize -------------------------------------------------
__global__ void finalize_bn(const float* __restrict__ gamma,
                            const float* __restrict__ beta,
                            int C, float invM, int which)
{
    int i = blockIdx.x * blockDim.x + threadIdx.x;
    if (i < C) {
        const float* sum = (which == 0) ? g_sum1 : g_sum2;
        const float* ssq = (which == 0) ? g_ssq1 : g_ssq2;
        float*     scale = (which == 0) ? g_scale1 : g_scale2;
        float*     shift = (which == 0) ? g_shift1 : g_shift2;
        float mu  = sum[i] * invM;
        float var = ssq[i] * invM - mu * mu;
        float inv = rsqrtf(var + EPS_BN);
        float sc  = gamma[i] * inv;
        scale[i] = sc;
        shift[i] = beta[i] - mu * sc;
    }
}

// ---------------- BN+ReLU then scatter-add (vector atomics) -----------------
__global__ void scatter_kernel(const int* __restrict__ ecol) {
    const int lane   = threadIdx.x & 31;
    const int warp   = (blockIdx.x * blockDim.x + threadIdx.x) >> 5;
    const int nWarps = (gridDim.x * blockDim.x) >> 5;

    float4 sc = *reinterpret_cast<const float4*>(&g_scale1[lane << 2]);
    float4 sh = *reinterpret_cast<const float4*>(&g_shift1[lane << 2]);

    for (int e = warp; e < E_EDGES; e += nWarps) {
        int c = ecol[e];
        float4 y = *reinterpret_cast<const float4*>(&g_Y[(size_t)e * 128 + (lane << 2)]);
        y.x = fmaxf(fmaf(y.x, sc.x, sh.x), 0.f);
        y.y = fmaxf(fmaf(y.y, sc.y, sh.y), 0.f);
        y.z = fmaxf(fmaf(y.z, sc.z, sh.z), 0.f);
        y.w = fmaxf(fmaf(y.w, sc.w, sh.w), 0.f);
        float* dst = &g_s[(size_t)c * 128 + (lane << 2)];
        asm volatile("red.global.add.v4.f32 [%0], {%1,%2,%3,%4};"
                     :: "l"(dst), "f"(y.x), "f"(y.y), "f"(y.z), "f"(y.w)
                     : "memory");
        if (lane == 0) atomicAdd(&g_cnt[c], 1);
    }
}

// ---------------- build h2in = concat(x, s/cnt) ------------------------------
__global__ void build_h2in(const float* __restrict__ x) {
    int idx = blockIdx.x * blockDim.x + threadIdx.x;
    int stride = gridDim.x * blockDim.x;
    const int total = N_NODES * 64;
    for (int i = idx; i < total; i += stride) {
        int n = i >> 6, q = i & 63;
        float4 v;
        if (q < 32) {
            v = ld4(x + (size_t)n * 128 + (q << 2));
        } else {
            int c = q - 32;
            v = ld4(g_s + (size_t)n * 128 + (c << 2));
            int cnt = g_cnt[n];
            float inv = (cnt > 0) ? (1.f / (float)cnt) : 0.f;
            v.x *= inv; v.y *= inv; v.z *= inv; v.w *= inv;
        }
        *reinterpret_cast<float4*>(g_h2in + (size_t)n * 256 + (q << 2)) = v;
    }
}

// ---------------- launch ------------------------------------------------------
extern "C" void kernel_launch(void* const* d_in, const int* in_sizes, int n_in,
                              void* d_out, int out_size)
{
    const float* x     = (const float*)d_in[0];
    const int*   eidx  = (const int*)  d_in[1];
    const float* eattr = (const float*)d_in[2];
    const float* W1  = (const float*)d_in[5];
    const float* b1  = (const float*)d_in[6];
    const float* g1  = (const float*)d_in[7];
    const float* be1 = (const float*)d_in[8];
    const float* W2  = (const float*)d_in[9];
    const float* b2  = (const float*)d_in[10];
    const float* g2  = (const float*)d_in[11];
    const float* be2 = (const float*)d_in[12];
    const float* Wl  = (const float*)d_in[13];
    const float* bl  = (const float*)d_in[14];
    float* out = (float*)d_out;

    const int* erow = eidx;
    const int* ecol = eidx + E_EDGES;

    cudaFuncSetAttribute(gemm1_mma, cudaFuncAttributeMaxDynamicSharedMemorySize, G_TOT);
    cudaFuncSetAttribute(mma_gemm<2, 0, 0, 0>, cudaFuncAttributeMaxDynamicSharedMemorySize, Q_TOT);
    cudaFuncSetAttribute(mma_gemm<4, 1, 1, 1>, cudaFuncAttributeMaxDynamicSharedMemorySize, Q_TOT);
    cudaFuncSetAttribute(mma_gemm<4, 2, 2, 2>, cudaFuncAttributeMaxDynamicSharedMemorySize, Q_TOT);

    const int MB = (N_NODES + 127) / 128;   // 391

    // 0) zero accumulators + prep all weight images
    zero_kernel<<<2048, 256>>>();
    prep_W<<<480, 256>>>(W1, W2, Wl);

    // 1) P = x @ W1_top + b1
    mma_gemm<2, 0, 0, 0><<<dim3(MB, 1), 256, Q_TOT>>>(x, 128, N_NODES, b1, nullptr, 128);

    // 2) persistent: Q = eattr @ W1_bot; Y = Q + P[row]; fused BN1 stats
    gemm1_mma<<<G_GRID, 256, G_TOT>>>(eattr, erow);

    // 3) BN1 scale/shift
    finalize_bn<<<1, 256>>>(g1, be1, 128, 1.f / (float)E_EDGES, 0);

    // 4) BN1 + ReLU + scatter
    scatter_kernel<<<2368, 256>>>(ecol);

    // 5) h2in = concat(x, s/cnt)
    build_h2in<<<2048, 256>>>(x);

    // 6) Z2 = h2in @ W2 + b2, fused BN2 stats
    mma_gemm<4, 1, 1, 1><<<dim3(MB, 2), 256, Q_TOT>>>(nullptr, 256, N_NODES, b2, nullptr, 256);

    // 7) BN2 scale/shift
    finalize_bn<<<1, 256>>>(g2, be2, 256, 1.f / (float)N_NODES, 1);

    // 8) out = relu(relu(bn2(Z2)) @ Wl + bl)
    mma_gemm<4, 2, 2, 2><<<dim3(MB, 1), 256, Q_TOT>>>(nullptr, 256, N_NODES, bl, out, 128);
}

// round 9
// speedup vs baseline: 2.6612x; 1.1197x over previous
#include <cuda_runtime.h>
#include <cuda_bf16.h>
#include <cstdint>

#define E_EDGES 1600000
#define N_NODES 50000
#define EPS_BN 1e-5f

// ---------------- scratch (device globals; no allocations allowed) ----------
__device__ float g_Y[(size_t)E_EDGES * 128];      // pre-BN edge activations
__device__ float g_P[(size_t)N_NODES * 128];      // x @ W1_top + b1
__device__ float g_s[(size_t)N_NODES * 128];      // scatter-sum accumulator
__device__ int   g_cnt[N_NODES];
__device__ float g_h2in[(size_t)N_NODES * 256];
__device__ float g_Z2[(size_t)N_NODES * 256];
__device__ float g_sum1[128], g_ssq1[128], g_scale1[128], g_shift1[128];
__device__ float g_sum2[256], g_ssq2[256], g_scale2[256], g_shift2[256];
// Weight bf16 hi/lo images (padded rows, uint4-clean)
__device__ uint4 g_WimgHi[1088],  g_WimgLo[1088];   // W1_bot [64 k][136 n]
__device__ uint4 g_W1tH[2176],    g_W1tL[2176];     // W1_top [128 k][136 n]
__device__ uint4 g_W2H[8448],     g_W2L[8448];      // W2    [256 k][264 n]
__device__ uint4 g_WlH[4352],     g_WlL[4352];      // Wl    [256 k][136 n]

__device__ __forceinline__ float4 ld4(const float* p) {
    return *reinterpret_cast<const float4*>(p);
}
__device__ __forceinline__ uint32_t smem_u32(const void* p) {
    uint32_t a;
    asm("{ .reg .u64 t; cvta.to.shared.u64 t, %1; cvt.u32.u64 %0, t; }" : "=r"(a) : "l"(p));
    return a;
}

// ---------------- warp MMA primitives (sm_80 baseline) ----------------------
__device__ __forceinline__ void mma_bf16(float* c, const uint32_t* a, const uint32_t* b) {
    asm volatile(
        "mma.sync.aligned.m16n8k16.row.col.f32.bf16.bf16.f32 "
        "{%0,%1,%2,%3}, {%4,%5,%6,%7}, {%8,%9}, {%0,%1,%2,%3};"
        : "+f"(c[0]), "+f"(c[1]), "+f"(c[2]), "+f"(c[3])
        : "r"(a[0]), "r"(a[1]), "r"(a[2]), "r"(a[3]), "r"(b[0]), "r"(b[1]));
}
__device__ __forceinline__ void ldsm4(uint32_t* r, uint32_t addr) {
    asm volatile("ldmatrix.sync.aligned.m8n8.x4.shared.b16 {%0,%1,%2,%3}, [%4];"
        : "=r"(r[0]), "=r"(r[1]), "=r"(r[2]), "=r"(r[3]) : "r"(addr));
}
__device__ __forceinline__ void ldsm4t(uint32_t* r, uint32_t addr) {
    asm volatile("ldmatrix.sync.aligned.m8n8.x4.trans.shared.b16 {%0,%1,%2,%3}, [%4];"
        : "=r"(r[0]), "=r"(r[1]), "=r"(r[2]), "=r"(r[3]) : "r"(addr));
}
__device__ __forceinline__ void split_store(char* hi, char* lo, int j, float4 v) {
    __nv_bfloat16 h0 = __float2bfloat16_rn(v.x), h1 = __float2bfloat16_rn(v.y);
    __nv_bfloat16 h2 = __float2bfloat16_rn(v.z), h3 = __float2bfloat16_rn(v.w);
    __nv_bfloat162 hp0(h0, h1), hp1(h2, h3);
    __nv_bfloat162 lp0(__float2bfloat16_rn(v.x - __bfloat162float(h0)),
                       __float2bfloat16_rn(v.y - __bfloat162float(h1)));
    __nv_bfloat162 lp1(__float2bfloat16_rn(v.z - __bfloat162float(h2)),
                       __float2bfloat16_rn(v.w - __bfloat162float(h3)));
    *reinterpret_cast<uint2*>(hi + j * 8) =
        make_uint2(*reinterpret_cast<uint32_t*>(&hp0), *reinterpret_cast<uint32_t*>(&hp1));
    *reinterpret_cast<uint2*>(lo + j * 8) =
        make_uint2(*reinterpret_cast<uint32_t*>(&lp0), *reinterpret_cast<uint32_t*>(&lp1));
}
__device__ __forceinline__ void cp_async16(uint32_t saddr, const void* gptr) {
    asm volatile("cp.async.cg.shared.global [%0], [%1], 16;"
                 :: "r"(saddr), "l"(gptr) : "memory");
}
__device__ __forceinline__ void prefetchL1(const void* gptr) {
    asm volatile("prefetch.global.L1 [%0];" :: "l"(gptr));
}

// ---------------- zero scratch ----------------------------------------------
__global__ void zero_kernel() {
    int idx = blockIdx.x * blockDim.x + threadIdx.x;
    int stride = gridDim.x * blockDim.x;
    float4 z4 = make_float4(0.f, 0.f, 0.f, 0.f);
    int total4 = N_NODES * 32;
    float4* s4 = reinterpret_cast<float4*>(g_s);
    for (int i = idx; i < total4; i += stride) s4[i] = z4;
    for (int i = idx; i < N_NODES; i += stride) g_cnt[i] = 0;
    if (idx < 128) { g_sum1[idx] = 0.f; g_ssq1[idx] = 0.f; }
    if (idx < 256) { g_sum2[idx] = 0.f; g_ssq2[idx] = 0.f; }
}

// ---------------- prep: all weight hi/lo bf16 images --------------------------
__global__ void prep_W(const float* __restrict__ W1, const float* __restrict__ W2,
                       const float* __restrict__ Wl) {
    int idx = blockIdx.x * blockDim.x + threadIdx.x;
    float f;
    uint16_t *dh, *dl;
    int off;
    if (idx < 8192) {                       // W1_bot: [64 k][128 n] -> 136 stride
        int k = idx >> 7, n = idx & 127;
        f = W1[(size_t)(128 + k) * 128 + n];
        dh = reinterpret_cast<uint16_t*>(g_WimgHi);
        dl = reinterpret_cast<uint16_t*>(g_WimgLo);
        off = k * 136 + n;
    } else if (idx < 24576) {               // W1_top: [128 k][128 n] -> 136
        int l = idx - 8192, k = l >> 7, n = l & 127;
        f = W1[(size_t)k * 128 + n];
        dh = reinterpret_cast<uint16_t*>(g_W1tH);
        dl = reinterpret_cast<uint16_t*>(g_W1tL);
        off = k * 136 + n;
    } else if (idx < 90112) {               // W2: [256 k][256 n] -> 264
        int l = idx - 24576, k = l >> 8, n = l & 255;
        f = W2[(size_t)k * 256 + n];
        dh = reinterpret_cast<uint16_t*>(g_W2H);
        dl = reinterpret_cast<uint16_t*>(g_W2L);
        off = k * 264 + n;
    } else if (idx < 122880) {              // Wl: [256 k][128 n] -> 136
        int l = idx - 90112, k = l >> 7, n = l & 127;
        f = Wl[(size_t)k * 128 + n];
        dh = reinterpret_cast<uint16_t*>(g_WlH);
        dl = reinterpret_cast<uint16_t*>(g_WlL);
        off = k * 136 + n;
    } else return;
    __nv_bfloat16 h = __float2bfloat16_rn(f);
    __nv_bfloat16 l = __float2bfloat16_rn(f - __bfloat162float(h));
    dh[off] = *reinterpret_cast<uint16_t*>(&h);
    dl[off] = *reinterpret_cast<uint16_t*>(&l);
}

// ---------------- shared SMEM layout ------------------------------------------
#define Q_AHI 0
#define Q_ALO 18432
#define Q_WHI 36864
#define Q_WLO 54272
#define Q_ROW 71680          // (mma_gemm: bias slot)
#define Q_SUM 72192
#define Q_SSQ 72704
#define Q_TOT 73216          // mma_gemm footprint
#define A_STRIDE 144
// gemm1 persistent additions:
#define G_STAGE 71680        // raw eattr tile [128][272B] = 34816
#define G_SROWSTG 106496     // staged erow (512)
#define G_SROW 107008        // active erow (512)
#define G_SUM 107520
#define G_SSQ 108032
#define G_TOT 108544
#define G_GRID 296
#define G_NT (E_EDGES / 128)

// ---------------- gemm1 (persistent): Q = eattr @ W1_bot; Y = Q + P[row] -----
__global__ void __launch_bounds__(256, 2)
gemm1_mma(const float* __restrict__ eattr, const int* __restrict__ erow) {
    extern __shared__ char smem[];
    const uint32_t sb = smem_u32(smem);
    const int tid = threadIdx.x, wid = tid >> 5, lane = tid & 31;

    // one-time: W images, stat init
    {
        uint4* dh = reinterpret_cast<uint4*>(smem + Q_WHI);
        uint4* dl = reinterpret_cast<uint4*>(smem + Q_WLO);
        for (int i = tid; i < 1088; i += 256) { dh[i] = g_WimgHi[i]; dl[i] = g_WimgLo[i]; }
    }
    if (tid < 128) {
        ((float*)(smem + G_SUM))[tid] = 0.f;
        ((float*)(smem + G_SSQ))[tid] = 0.f;
    }

    // prologue: stage first tile
    {
        int t0 = blockIdx.x;
        const char* src = (const char*)(eattr + (size_t)t0 * 128 * 64);
        #pragma unroll
        for (int i = tid; i < 2048; i += 256) {
            int r = i >> 4, q = i & 15;
            cp_async16(sb + G_STAGE + r * 272 + q * 16, src + (size_t)r * 256 + q * 16);
        }
        if (tid < 32)
            cp_async16(sb + G_SROWSTG + tid * 16,
                       (const char*)(erow + (size_t)t0 * 128) + tid * 16);
        asm volatile("cp.async.commit_group;" ::: "memory");
    }

    const int m0 = (wid & 3) * 32;
    const int n0 = (wid >> 2) * 64;
    const uint32_t aRowOff = (uint32_t)(m0 + (lane & 15)) * (uint32_t)A_STRIDE
                           + (uint32_t)(lane >> 4) * 16u;
    const uint32_t bOff = (uint32_t)((lane & 7) + ((lane >> 3) & 1) * 8) * 272u
                        + ((uint32_t)(lane >> 4) * 8u + (uint32_t)n0) * 2u;
    const int g = lane >> 2, t2 = (lane & 3) * 2;
    const int* s_row = (const int*)(smem + G_SROW);
    float* s_sum = (float*)(smem + G_SUM);
    float* s_ssq = (float*)(smem + G_SSQ);

    // BN1 stats: per-thread accumulators, tile-invariant column ownership
    float csum[8][2], cssq[8][2];
    #pragma unroll
    for (int ni = 0; ni < 8; ++ni) {
        csum[ni][0] = 0.f; csum[ni][1] = 0.f;
        cssq[ni][0] = 0.f; cssq[ni][1] = 0.f;
    }

    for (int t = blockIdx.x; t < G_NT; t += G_GRID) {
        asm volatile("cp.async.wait_group 0;" ::: "memory");
        __syncthreads();   // stage ready; prior epilogue done

        // convert stage -> A hi/lo images; publish erow
        {
            const int r = tid >> 1, h = tid & 1;
            const char* srow = smem + G_STAGE + r * 272;
            char* ahi = smem + Q_AHI + r * A_STRIDE;
            char* alo = smem + Q_ALO + r * A_STRIDE;
            #pragma unroll
            for (int jj = 0; jj < 8; ++jj) {
                int j = h * 8 + jj;
                float4 v = *reinterpret_cast<const float4*>(srow + j * 16);
                split_store(ahi, alo, j, v);
            }
            if (tid < 128)
                ((int*)(smem + G_SROW))[tid] = ((const int*)(smem + G_SROWSTG))[tid];
        }
        __syncthreads();   // images + s_row visible; stage consumed

        // read gather rows + prefetch their P lines into L1 (hidden by MMA)
        int G00 = s_row[m0 + g],      G01 = s_row[m0 + g + 8];
        int G10 = s_row[m0 + 16 + g], G11 = s_row[m0 + 16 + g + 8];
        {
            const float* pb = g_P;
            prefetchL1(pb + (size_t)G00 * 128 + n0 + t2);
            prefetchL1(pb + (size_t)G00 * 128 + n0 + t2 + 32);
            prefetchL1(pb + (size_t)G01 * 128 + n0 + t2);
            prefetchL1(pb + (size_t)G01 * 128 + n0 + t2 + 32);
            prefetchL1(pb + (size_t)G10 * 128 + n0 + t2);
            prefetchL1(pb + (size_t)G10 * 128 + n0 + t2 + 32);
            prefetchL1(pb + (size_t)G11 * 128 + n0 + t2);
            prefetchL1(pb + (size_t)G11 * 128 + n0 + t2 + 32);
        }

        // stage next tile (overlaps MMA + epilogue)
        if (t + G_GRID < G_NT) {
            int tn = t + G_GRID;
            const char* src = (const char*)(eattr + (size_t)tn * 128 * 64);
            #pragma unroll
            for (int i = tid; i < 2048; i += 256) {
                int r = i >> 4, q = i & 15;
                cp_async16(sb + G_STAGE + r * 272 + q * 16, src + (size_t)r * 256 + q * 16);
            }
            if (tid < 32)
                cp_async16(sb + G_SROWSTG + tid * 16,
                           (const char*)(erow + (size_t)tn * 128) + tid * 16);
            asm volatile("cp.async.commit_group;" ::: "memory");
        }

        // ---- MMA ----
        float acc[2][8][4];
        #pragma unroll
        for (int mi = 0; mi < 2; ++mi)
            #pragma unroll
            for (int ni = 0; ni < 8; ++ni)
                #pragma unroll
                for (int c = 0; c < 4; ++c) acc[mi][ni][c] = 0.f;

        #pragma unroll
        for (int kt = 0; kt < 4; ++kt) {
            const uint32_t k0b = (uint32_t)kt * 32u;
            const uint32_t kwb = (uint32_t)kt * 4352u;
            uint32_t ah[2][4], al[2][4];
            ldsm4(ah[0], sb + Q_AHI + aRowOff + k0b);
            ldsm4(ah[1], sb + Q_AHI + aRowOff + 16u * A_STRIDE + k0b);
            ldsm4(al[0], sb + Q_ALO + aRowOff + k0b);
            ldsm4(al[1], sb + Q_ALO + aRowOff + 16u * A_STRIDE + k0b);

            #pragma unroll
            for (int ni2 = 0; ni2 < 4; ++ni2) {
                uint32_t th[4], tl[4];
                ldsm4t(th, sb + Q_WHI + bOff + kwb + (uint32_t)ni2 * 32u);
                ldsm4t(tl, sb + Q_WLO + bOff + kwb + (uint32_t)ni2 * 32u);
                #pragma unroll
                for (int mi = 0; mi < 2; ++mi) {
                    mma_bf16(acc[mi][2 * ni2],     ah[mi], th);
                    mma_bf16(acc[mi][2 * ni2],     al[mi], th);
                    mma_bf16(acc[mi][2 * ni2],     ah[mi], tl);
                    mma_bf16(acc[mi][2 * ni2 + 1], ah[mi], th + 2);
                    mma_bf16(acc[mi][2 * ni2 + 1], al[mi], th + 2);
                    mma_bf16(acc[mi][2 * ni2 + 1], ah[mi], tl + 2);
                }
            }
        }

        // ---- epilogue: Y = Q + P[row] (L1-hot), streaming store, reg stats --
        const int mBase = t * 128;
        #pragma unroll
        for (int mi = 0; mi < 2; ++mi) {
            const int r0 = m0 + mi * 16 + g;
            const int G0 = (mi == 0) ? G00 : G10;
            const int G1 = (mi == 0) ? G01 : G11;
            const int row = mBase + r0;
            #pragma unroll
            for (int ni = 0; ni < 8; ++ni) {
                const int col = n0 + ni * 8 + t2;
                float2 p0 = *reinterpret_cast<const float2*>(g_P + (size_t)G0 * 128 + col);
                float2 p1 = *reinterpret_cast<const float2*>(g_P + (size_t)G1 * 128 + col);
                float y0 = acc[mi][ni][0] + p0.x;
                float y1 = acc[mi][ni][1] + p0.y;
                float y2 = acc[mi][ni][2] + p1.x;
                float y3 = acc[mi][ni][3] + p1.y;
                __stcs(reinterpret_cast<float2*>(g_Y + (size_t)row * 128 + col),
                       make_float2(y0, y1));
                __stcs(reinterpret_cast<float2*>(g_Y + (size_t)(row + 8) * 128 + col),
                       make_float2(y2, y3));
                csum[ni][0] += y0 + y2;
                csum[ni][1] += y1 + y3;
                cssq[ni][0] += y0 * y0 + y2 * y2;
                cssq[ni][1] += y1 * y1 + y3 * y3;
            }
        }
    }

    // ---- one-time BN1 stats reduction + global flush ----
    #pragma unroll
    for (int ni = 0; ni < 8; ++ni)
        #pragma unroll
        for (int par = 0; par < 2; ++par) {
            float s = csum[ni][par], q = cssq[ni][par];
            #pragma unroll
            for (int o = 4; o < 32; o <<= 1) {
                s += __shfl_xor_sync(0xFFFFFFFFu, s, o);
                q += __shfl_xor_sync(0xFFFFFFFFu, q, o);
            }
            if (g == 0) {
                atomicAdd(&s_sum[n0 + ni * 8 + t2 + par], s);
                atomicAdd(&s_ssq[n0 + ni * 8 + t2 + par], q);
            }
        }
    __syncthreads();
    if (tid < 128) {
        atomicAdd(&g_sum1[tid], s_sum[tid]);
        atomicAdd(&g_ssq1[tid], s_ssq[tid]);
    }
}

// ---------------- unified k-chunked bf16-split MMA GEMM ----------------------
// ASEL: 0=ext arg (x), 1=g_h2in, 2=g_Z2 (+bn2+relu transform)
// WSEL: 0=W1_top(17), 1=W2(33), 2=Wl(17)
// OSEL: 0=g_P, 1=g_Z2(+BN2 stats), 2=ext out arg(+relu)
template<int KCH, int ASEL, int WSEL, int OSEL>
__global__ void __launch_bounds__(256, 2)
mma_gemm(const float* __restrict__ Aext, int ldA, int M,
         const float* __restrict__ bias, float* __restrict__ outExt, int outLd)
{
    extern __shared__ char smem[];
    const uint32_t sb = smem_u32(smem);
    const int tid = threadIdx.x, wid = tid >> 5, lane = tid & 31;
    const int mBase = blockIdx.x * 128;
    const int nBase = blockIdx.y * 128;

    const float* A = (ASEL == 0) ? Aext : (ASEL == 1) ? (const float*)g_h2in
                                                      : (const float*)g_Z2;
    const uint4* WH = (WSEL == 0) ? g_W1tH : (WSEL == 1) ? g_W2H : g_WlH;
    const uint4* WL = (WSEL == 0) ? g_W1tL : (WSEL == 1) ? g_W2L : g_WlL;
    const int WR16 = (WSEL == 1) ? 33 : 17;
    float* outp = (OSEL == 0) ? (float*)g_P : (OSEL == 1) ? (float*)g_Z2 : outExt;

    if (tid < 128) {
        ((float*)(smem + Q_ROW))[tid] = bias[nBase + tid];
        ((float*)(smem + Q_SUM))[tid] = 0.f;
        ((float*)(smem + Q_SSQ))[tid] = 0.f;
    }

    const int m0 = (wid & 3) * 32;
    const int n0 = (wid >> 2) * 64;
    float acc[2][8][4];
    #pragma unroll
    for (int mi = 0; mi < 2; ++mi)
        #pragma unroll
        for (int ni = 0; ni < 8; ++ni)
            #pragma unroll
            for (int c = 0; c < 4; ++c) acc[mi][ni][c] = 0.f;

    const uint32_t aRowOff = (uint32_t)(m0 + (lane & 15)) * (uint32_t)A_STRIDE
                           + (uint32_t)(lane >> 4) * 16u;
    const uint32_t bOff = (uint32_t)((lane & 7) + ((lane >> 3) & 1) * 8) * 272u
                        + ((uint32_t)(lane >> 4) * 8u + (uint32_t)n0) * 2u;

    #pragma unroll 1
    for (int c = 0; c < KCH; ++c) {
        if (c) __syncthreads();
        {
            uint4* dh = reinterpret_cast<uint4*>(smem + Q_WHI);
            uint4* dl = reinterpret_cast<uint4*>(smem + Q_WLO);
            const uint4* sh = WH + (size_t)(c * 64) * WR16 + (nBase >> 3);
            const uint4* sl = WL + (size_t)(c * 64) * WR16 + (nBase >> 3);
            for (int i = tid; i < 1088; i += 256) {
                int kk = i / 17, q = i - kk * 17;
                dh[i] = sh[(size_t)kk * WR16 + q];
                dl[i] = sl[(size_t)kk * WR16 + q];
            }
        }
        {
            const int r = tid >> 1, h = tid & 1, rg = mBase + r;
            char* ahi = smem + Q_AHI + r * A_STRIDE;
            char* alo = smem + Q_ALO + r * A_STRIDE;
            const float4* ar = reinterpret_cast<const float4*>(A + (size_t)rg * ldA + c * 64);
            #pragma unroll
            for (int jj = 0; jj < 8; ++jj) {
                int j = h * 8 + jj;
                float4 v = make_float4(0.f, 0.f, 0.f, 0.f);
                if (rg < M) {
                    v = ar[j];
                    if (ASEL == 2) {
                        int kg = c * 64 + j * 4;
                        float4 sc = ld4(g_scale2 + kg), sh4 = ld4(g_shift2 + kg);
                        v.x = fmaxf(fmaf(v.x, sc.x, sh4.x), 0.f);
                        v.y = fmaxf(fmaf(v.y, sc.y, sh4.y), 0.f);
                        v.z = fmaxf(fmaf(v.z, sc.z, sh4.z), 0.f);
                        v.w = fmaxf(fmaf(v.w, sc.w, sh4.w), 0.f);
                    }
                }
                split_store(ahi, alo, j, v);
            }
        }
        __syncthreads();

        #pragma unroll
        for (int kt = 0; kt < 4; ++kt) {
            const uint32_t k0b = (uint32_t)kt * 32u;
            const uint32_t kwb = (uint32_t)kt * 4352u;
            uint32_t ah[2][4], al[2][4];
            ldsm4(ah[0], sb + Q_AHI + aRowOff + k0b);
            ldsm4(ah[1], sb + Q_AHI + aRowOff + 16u * A_STRIDE + k0b);
            ldsm4(al[0], sb + Q_ALO + aRowOff + k0b);
            ldsm4(al[1], sb + Q_ALO + aRowOff + 16u * A_STRIDE + k0b);

            #pragma unroll
            for (int ni2 = 0; ni2 < 4; ++ni2) {
                uint32_t th[4], tl[4];
                ldsm4t(th, sb + Q_WHI + bOff + kwb + (uint32_t)ni2 * 32u);
                ldsm4t(tl, sb + Q_WLO + bOff + kwb + (uint32_t)ni2 * 32u);
                #pragma unroll
                for (int mi = 0; mi < 2; ++mi) {
                    mma_bf16(acc[mi][2 * ni2],     ah[mi], th);
                    mma_bf16(acc[mi][2 * ni2],     al[mi], th);
                    mma_bf16(acc[mi][2 * ni2],     ah[mi], tl);
                    mma_bf16(acc[mi][2 * ni2 + 1], ah[mi], th + 2);
                    mma_bf16(acc[mi][2 * ni2 + 1], al[mi], th + 2);
                    mma_bf16(acc[mi][2 * ni2 + 1], ah[mi], tl + 2);
                }
            }
        }
    }
    __syncthreads();

    const float* bs = (const float*)(smem + Q_ROW);
    float* s_sum = (float*)(smem + Q_SUM);
    float* s_ssq = (float*)(smem + Q_SSQ);
    const int g = lane >> 2, t2 = (lane & 3) * 2;

    float csum[8][2], cssq[8][2];
    if (OSEL == 1) {
        #pragma unroll
        for (int ni = 0; ni < 8; ++ni) {
            csum[ni][0] = 0.f; csum[ni][1] = 0.f;
            cssq[ni][0] = 0.f; cssq[ni][1] = 0.f;
        }
    }

    #pragma unroll
    for (int mi = 0; mi < 2; ++mi) {
        const int row = mBase + m0 + mi * 16 + g;
        const bool v0 = row < M, v1 = (row + 8) < M;
        #pragma unroll
        for (int ni = 0; ni < 8; ++ni) {
            const int col = n0 + ni * 8 + t2;
            float b0 = bs[col], b1 = bs[col + 1];
            float y0 = acc[mi][ni][0] + b0;
            float y1 = acc[mi][ni][1] + b1;
            float y2 = acc[mi][ni][2] + b0;
            float y3 = acc[mi][ni][3] + b1;
            if (OSEL == 2) {
                y0 = fmaxf(y0, 0.f); y1 = fmaxf(y1, 0.f);
                y2 = fmaxf(y2, 0.f); y3 = fmaxf(y3, 0.f);
            }
            if (v0)
                *reinterpret_cast<float2*>(outp + (size_t)row * outLd + nBase + col)
                    = make_float2(y0, y1);
            if (v1)
                *reinterpret_cast<float2*>(outp + (size_t)(row + 8) * outLd + nBase + col)
                    = make_float2(y2, y3);
            if (OSEL == 1) {
                if (v0) {
                    csum[ni][0] += y0; csum[ni][1] += y1;
                    cssq[ni][0] += y0 * y0; cssq[ni][1] += y1 * y1;
                }
                if (v1) {
                    csum[ni][0] += y2; csum[ni][1] += y3;
                    cssq[ni][0] += y2 * y2; cssq[ni][1] += y3 * y3;
                }
            }
        }
    }
    if (OSEL == 1) {
        #pragma unroll
        for (int ni = 0; ni < 8; ++ni)
            #pragma unroll
            for (int par = 0; par < 2; ++par) {
                float s = csum[ni][par], q = cssq[ni][par];
                #pragma unroll
                for (int o = 4; o < 32; o <<= 1) {
                    s += __shfl_xor_sync(0xFFFFFFFFu, s, o);
                    q += __shfl_xor_sync(0xFFFFFFFFu, q, o);
                }
                if (g == 0) {
                    atomicAdd(&s_sum[n0 + ni * 8 + t2 + par], s);
                    atomicAdd(&s_ssq[n0 + ni * 8 + t2 + par], q);
                }
            }
        __syncthreads();
        if (tid < 128) {
            atomicAdd(&g_sum2[nBase + tid], s_sum[tid]);
            atomicAdd(&g_ssq2[nBase + tid], s_ssq[tid]);
        }
    }
}

// ---------------- BN finalize -------------------------------------------------
__global__ void finalize_bn(const float* __restrict__ gamma,
                            const float* __restrict__ beta,
                            int C, float invM, int which)
{
    int i = blockIdx.x * blockDim.x + threadIdx.x;
    if (i < C) {
        const float* sum = (which == 0) ? g_sum1 : g_sum2;
        const float* ssq = (which == 0) ? g_ssq1 : g_ssq2;
        float*     scale = (which == 0) ? g_scale1 : g_scale2;
        float*     shift = (which == 0) ? g_shift1 : g_shift2;
        float mu  = sum[i] * invM;
        float var = ssq[i] * invM - mu * mu;
        float inv = rsqrtf(var + EPS_BN);
        float sc  = gamma[i] * inv;
        scale[i] = sc;
        shift[i] = beta[i] - mu * sc;
    }
}

// ---------------- BN+ReLU then scatter-add (vector atomics) -----------------
__global__ void scatter_kernel(const int* __restrict__ ecol) {
    const int lane   = threadIdx.x & 31;
    const int warp   = (blockIdx.x * blockDim.x + threadIdx.x) >> 5;
    const int nWarps = (gridDim.x * blockDim.x) >> 5;

    float4 sc = *reinterpret_cast<const float4*>(&g_scale1[lane << 2]);
    float4 sh = *reinterpret_cast<const float4*>(&g_shift1[lane << 2]);

    for (int e = warp; e < E_EDGES; e += nWarps) {
        int c = ecol[e];
        float4 y = __ldcs(reinterpret_cast<const float4*>(&g_Y[(size_t)e * 128 + (lane << 2)]));
        y.x = fmaxf(fmaf(y.x, sc.x, sh.x), 0.f);
        y.y = fmaxf(fmaf(y.y, sc.y, sh.y), 0.f);
        y.z = fmaxf(fmaf(y.z, sc.z, sh.z), 0.f);
        y.w = fmaxf(fmaf(y.w, sc.w, sh.w), 0.f);
        float* dst = &g_s[(size_t)c * 128 + (lane << 2)];
        asm volatile("red.global.add.v4.f32 [%0], {%1,%2,%3,%4};"
                     :: "l"(dst), "f"(y.x), "f"(y.y), "f"(y.z), "f"(y.w)
                     : "memory");
        if (lane == 0) atomicAdd(&g_cnt[c], 1);
    }
}

// ---------------- build h2in = concat(x, s/cnt) ------------------------------
__global__ void build_h2in(const float* __restrict__ x) {
    int idx = blockIdx.x * blockDim.x + threadIdx.x;
    int stride = gridDim.x * blockDim.x;
    const int total = N_NODES * 64;
    for (int i = idx; i < total; i += stride) {
        int n = i >> 6, q = i & 63;
        float4 v;
        if (q < 32) {
            v = ld4(x + (size_t)n * 128 + (q << 2));
        } else {
            int c = q - 32;
            v = ld4(g_s + (size_t)n * 128 + (c << 2));
            int cnt = g_cnt[n];
            float inv = (cnt > 0) ? (1.f / (float)cnt) : 0.f;
            v.x *= inv; v.y *= inv; v.z *= inv; v.w *= inv;
        }
        *reinterpret_cast<float4*>(g_h2in + (size_t)n * 256 + (q << 2)) = v;
    }
}

// ---------------- launch ------------------------------------------------------
extern "C" void kernel_launch(void* const* d_in, const int* in_sizes, int n_in,
                              void* d_out, int out_size)
{
    const float* x     = (const float*)d_in[0];
    const int*   eidx  = (const int*)  d_in[1];
    const float* eattr = (const float*)d_in[2];
    const float* W1  = (const float*)d_in[5];
    const float* b1  = (const float*)d_in[6];
    const float* g1  = (const float*)d_in[7];
    const float* be1 = (const float*)d_in[8];
    const float* W2  = (const float*)d_in[9];
    const float* b2  = (const float*)d_in[10];
    const float* g2  = (const float*)d_in[11];
    const float* be2 = (const float*)d_in[12];
    const float* Wl  = (const float*)d_in[13];
    const float* bl  = (const float*)d_in[14];
    float* out = (float*)d_out;

    const int* erow = eidx;
    const int* ecol = eidx + E_EDGES;

    cudaFuncSetAttribute(gemm1_mma, cudaFuncAttributeMaxDynamicSharedMemorySize, G_TOT);
    cudaFuncSetAttribute(mma_gemm<2, 0, 0, 0>, cudaFuncAttributeMaxDynamicSharedMemorySize, Q_TOT);
    cudaFuncSetAttribute(mma_gemm<4, 1, 1, 1>, cudaFuncAttributeMaxDynamicSharedMemorySize, Q_TOT);
    cudaFuncSetAttribute(mma_gemm<4, 2, 2, 2>, cudaFuncAttributeMaxDynamicSharedMemorySize, Q_TOT);

    const int MB = (N_NODES + 127) / 128;   // 391

    // 0) zero accumulators + prep all weight images
    zero_kernel<<<2048, 256>>>();
    prep_W<<<480, 256>>>(W1, W2, Wl);

    // 1) P = x @ W1_top + b1
    mma_gemm<2, 0, 0, 0><<<dim3(MB, 1), 256, Q_TOT>>>(x, 128, N_NODES, b1, nullptr, 128);

    // 2) persistent: Q = eattr @ W1_bot; Y = Q + P[row]; fused BN1 stats
    gemm1_mma<<<G_GRID, 256, G_TOT>>>(eattr, erow);

    // 3) BN1 scale/shift
    finalize_bn<<<1, 256>>>(g1, be1, 128, 1.f / (float)E_EDGES, 0);

    // 4) BN1 + ReLU + scatter
    scatter_kernel<<<2368, 256>>>(ecol);

    // 5) h2in = concat(x, s/cnt)
    build_h2in<<<2048, 256>>>(x);

    // 6) Z2 = h2in @ W2 + b2, fused BN2 stats
    mma_gemm<4, 1, 1, 1><<<dim3(MB, 2), 256, Q_TOT>>>(nullptr, 256, N_NODES, b2, nullptr, 256);

    // 7) BN2 scale/shift
    finalize_bn<<<1, 256>>>(g2, be2, 256, 1.f / (float)N_NODES, 1);

    // 8) out = relu(relu(bn2(Z2)) @ Wl + bl)
    mma_gemm<4, 2, 2, 2><<<dim3(MB, 1), 256, Q_TOT>>>(nullptr, 256, N_NODES, bl, out, 128);
}

// round 10
// speedup vs baseline: 2.8846x; 1.0839x over previous
#include <cuda_runtime.h>
#include <cuda_bf16.h>
#include <cuda_fp16.h>
#include <cstdint>

#define E_EDGES 1600000
#define N_NODES 50000
#define EPS_BN 1e-5f

// ---------------- scratch (device globals; no allocations allowed) ----------
__device__ __half g_Y[(size_t)E_EDGES * 128];     // pre-BN edge activations (fp16)
__device__ float g_P[(size_t)N_NODES * 128];      // x @ W1_top + b1
__device__ float g_s[(size_t)N_NODES * 128];      // scatter-sum accumulator
__device__ int   g_cnt[N_NODES];
__device__ float g_h2in[(size_t)N_NODES * 256];
__device__ float g_Z2[(size_t)N_NODES * 256];
__device__ float g_sum1[128], g_ssq1[128], g_scale1[128], g_shift1[128];
__device__ float g_sum2[256], g_ssq2[256], g_scale2[256], g_shift2[256];
// Weight bf16 hi/lo images (padded rows, uint4-clean)
__device__ uint4 g_WimgHi[1088],  g_WimgLo[1088];   // W1_bot [64 k][136 n]
__device__ uint4 g_W1tH[2176],    g_W1tL[2176];     // W1_top [128 k][136 n]
__device__ uint4 g_W2H[8448],     g_W2L[8448];      // W2    [256 k][264 n]
__device__ uint4 g_WlH[4352],     g_WlL[4352];      // Wl    [256 k][136 n]

__device__ __forceinline__ float4 ld4(const float* p) {
    return *reinterpret_cast<const float4*>(p);
}
__device__ __forceinline__ uint32_t smem_u32(const void* p) {
    uint32_t a;
    asm("{ .reg .u64 t; cvta.to.shared.u64 t, %1; cvt.u32.u64 %0, t; }" : "=r"(a) : "l"(p));
    return a;
}

// ---------------- warp MMA primitives (sm_80 baseline) ----------------------
__device__ __forceinline__ void mma_bf16(float* c, const uint32_t* a, const uint32_t* b) {
    asm volatile(
        "mma.sync.aligned.m16n8k16.row.col.f32.bf16.bf16.f32 "
        "{%0,%1,%2,%3}, {%4,%5,%6,%7}, {%8,%9}, {%0,%1,%2,%3};"
        : "+f"(c[0]), "+f"(c[1]), "+f"(c[2]), "+f"(c[3])
        : "r"(a[0]), "r"(a[1]), "r"(a[2]), "r"(a[3]), "r"(b[0]), "r"(b[1]));
}
__device__ __forceinline__ void ldsm4(uint32_t* r, uint32_t addr) {
    asm volatile("ldmatrix.sync.aligned.m8n8.x4.shared.b16 {%0,%1,%2,%3}, [%4];"
        : "=r"(r[0]), "=r"(r[1]), "=r"(r[2]), "=r"(r[3]) : "r"(addr));
}
__device__ __forceinline__ void ldsm4t(uint32_t* r, uint32_t addr) {
    asm volatile("ldmatrix.sync.aligned.m8n8.x4.trans.shared.b16 {%0,%1,%2,%3}, [%4];"
        : "=r"(r[0]), "=r"(r[1]), "=r"(r[2]), "=r"(r[3]) : "r"(addr));
}
__device__ __forceinline__ void split_store(char* hi, char* lo, int j, float4 v) {
    __nv_bfloat16 h0 = __float2bfloat16_rn(v.x), h1 = __float2bfloat16_rn(v.y);
    __nv_bfloat16 h2 = __float2bfloat16_rn(v.z), h3 = __float2bfloat16_rn(v.w);
    __nv_bfloat162 hp0(h0, h1), hp1(h2, h3);
    __nv_bfloat162 lp0(__float2bfloat16_rn(v.x - __bfloat162float(h0)),
                       __float2bfloat16_rn(v.y - __bfloat162float(h1)));
    __nv_bfloat162 lp1(__float2bfloat16_rn(v.z - __bfloat162float(h2)),
                       __float2bfloat16_rn(v.w - __bfloat162float(h3)));
    *reinterpret_cast<uint2*>(hi + j * 8) =
        make_uint2(*reinterpret_cast<uint32_t*>(&hp0), *reinterpret_cast<uint32_t*>(&hp1));
    *reinterpret_cast<uint2*>(lo + j * 8) =
        make_uint2(*reinterpret_cast<uint32_t*>(&lp0), *reinterpret_cast<uint32_t*>(&lp1));
}
__device__ __forceinline__ void cp_async16(uint32_t saddr, const void* gptr) {
    asm volatile("cp.async.cg.shared.global [%0], [%1], 16;"
                 :: "r"(saddr), "l"(gptr) : "memory");
}
__device__ __forceinline__ void prefetchL1(const void* gptr) {
    asm volatile("prefetch.global.L1 [%0];" :: "l"(gptr));
}

// ---------------- zero scratch ----------------------------------------------
__global__ void zero_kernel() {
    int idx = blockIdx.x * blockDim.x + threadIdx.x;
    int stride = gridDim.x * blockDim.x;
    float4 z4 = make_float4(0.f, 0.f, 0.f, 0.f);
    int total4 = N_NODES * 32;
    float4* s4 = reinterpret_cast<float4*>(g_s);
    for (int i = idx; i < total4; i += stride) s4[i] = z4;
    for (int i = idx; i < N_NODES; i += stride) g_cnt[i] = 0;
    if (idx < 128) { g_sum1[idx] = 0.f; g_ssq1[idx] = 0.f; }
    if (idx < 256) { g_sum2[idx] = 0.f; g_ssq2[idx] = 0.f; }
}

// ---------------- prep: all weight hi/lo bf16 images --------------------------
__global__ void prep_W(const float* __restrict__ W1, const float* __restrict__ W2,
                       const float* __restrict__ Wl) {
    int idx = blockIdx.x * blockDim.x + threadIdx.x;
    float f;
    uint16_t *dh, *dl;
    int off;
    if (idx < 8192) {                       // W1_bot: [64 k][128 n] -> 136 stride
        int k = idx >> 7, n = idx & 127;
        f = W1[(size_t)(128 + k) * 128 + n];
        dh = reinterpret_cast<uint16_t*>(g_WimgHi);
        dl = reinterpret_cast<uint16_t*>(g_WimgLo);
        off = k * 136 + n;
    } else if (idx < 24576) {               // W1_top: [128 k][128 n] -> 136
        int l = idx - 8192, k = l >> 7, n = l & 127;
        f = W1[(size_t)k * 128 + n];
        dh = reinterpret_cast<uint16_t*>(g_W1tH);
        dl = reinterpret_cast<uint16_t*>(g_W1tL);
        off = k * 136 + n;
    } else if (idx < 90112) {               // W2: [256 k][256 n] -> 264
        int l = idx - 24576, k = l >> 8, n = l & 255;
        f = W2[(size_t)k * 256 + n];
        dh = reinterpret_cast<uint16_t*>(g_W2H);
        dl = reinterpret_cast<uint16_t*>(g_W2L);
        off = k * 264 + n;
    } else if (idx < 122880) {              // Wl: [256 k][128 n] -> 136
        int l = idx - 90112, k = l >> 7, n = l & 127;
        f = Wl[(size_t)k * 128 + n];
        dh = reinterpret_cast<uint16_t*>(g_WlH);
        dl = reinterpret_cast<uint16_t*>(g_WlL);
        off = k * 136 + n;
    } else return;
    __nv_bfloat16 h = __float2bfloat16_rn(f);
    __nv_bfloat16 l = __float2bfloat16_rn(f - __bfloat162float(h));
    dh[off] = *reinterpret_cast<uint16_t*>(&h);
    dl[off] = *reinterpret_cast<uint16_t*>(&l);
}

// ---------------- shared SMEM layout ------------------------------------------
#define Q_AHI 0
#define Q_ALO 18432
#define Q_WHI 36864
#define Q_WLO 54272
#define Q_ROW 71680          // (mma_gemm: bias slot)
#define Q_SUM 72192
#define Q_SSQ 72704
#define Q_TOT 73216          // mma_gemm footprint
#define A_STRIDE 144
// gemm1 persistent additions:
#define G_STAGE 71680        // raw eattr tile [128][272B] = 34816
#define G_SROWSTG 106496     // staged erow (512)
#define G_SROW 107008        // active erow (512)
#define G_SUM 107520
#define G_SSQ 108032
#define G_TOT 108544
#define G_GRID 296
#define G_NT (E_EDGES / 128)

// ---------------- gemm1 (persistent): Q = eattr @ W1_bot; Y = Q + P[row] -----
__global__ void __launch_bounds__(256, 2)
gemm1_mma(const float* __restrict__ eattr, const int* __restrict__ erow) {
    extern __shared__ char smem[];
    const uint32_t sb = smem_u32(smem);
    const int tid = threadIdx.x, wid = tid >> 5, lane = tid & 31;

    // one-time: W images, stat init
    {
        uint4* dh = reinterpret_cast<uint4*>(smem + Q_WHI);
        uint4* dl = reinterpret_cast<uint4*>(smem + Q_WLO);
        for (int i = tid; i < 1088; i += 256) { dh[i] = g_WimgHi[i]; dl[i] = g_WimgLo[i]; }
    }
    if (tid < 128) {
        ((float*)(smem + G_SUM))[tid] = 0.f;
        ((float*)(smem + G_SSQ))[tid] = 0.f;
    }

    // prologue: stage first tile
    {
        int t0 = blockIdx.x;
        const char* src = (const char*)(eattr + (size_t)t0 * 128 * 64);
        #pragma unroll
        for (int i = tid; i < 2048; i += 256) {
            int r = i >> 4, q = i & 15;
            cp_async16(sb + G_STAGE + r * 272 + q * 16, src + (size_t)r * 256 + q * 16);
        }
        if (tid < 32)
            cp_async16(sb + G_SROWSTG + tid * 16,
                       (const char*)(erow + (size_t)t0 * 128) + tid * 16);
        asm volatile("cp.async.commit_group;" ::: "memory");
    }

    const int m0 = (wid & 3) * 32;
    const int n0 = (wid >> 2) * 64;
    const uint32_t aRowOff = (uint32_t)(m0 + (lane & 15)) * (uint32_t)A_STRIDE
                           + (uint32_t)(lane >> 4) * 16u;
    const uint32_t bOff = (uint32_t)((lane & 7) + ((lane >> 3) & 1) * 8) * 272u
                        + ((uint32_t)(lane >> 4) * 8u + (uint32_t)n0) * 2u;
    const int g = lane >> 2, t2 = (lane & 3) * 2;
    const int* s_row = (const int*)(smem + G_SROW);
    float* s_sum = (float*)(smem + G_SUM);
    float* s_ssq = (float*)(smem + G_SSQ);

    // BN1 stats: per-thread accumulators, tile-invariant column ownership
    float csum[8][2], cssq[8][2];
    #pragma unroll
    for (int ni = 0; ni < 8; ++ni) {
        csum[ni][0] = 0.f; csum[ni][1] = 0.f;
        cssq[ni][0] = 0.f; cssq[ni][1] = 0.f;
    }

    for (int t = blockIdx.x; t < G_NT; t += G_GRID) {
        asm volatile("cp.async.wait_group 0;" ::: "memory");
        __syncthreads();   // stage ready; prior epilogue done

        // convert stage -> A hi/lo images; publish erow
        {
            const int r = tid >> 1, h = tid & 1;
            const char* srow = smem + G_STAGE + r * 272;
            char* ahi = smem + Q_AHI + r * A_STRIDE;
            char* alo = smem + Q_ALO + r * A_STRIDE;
            #pragma unroll
            for (int jj = 0; jj < 8; ++jj) {
                int j = h * 8 + jj;
                float4 v = *reinterpret_cast<const float4*>(srow + j * 16);
                split_store(ahi, alo, j, v);
            }
            if (tid < 128)
                ((int*)(smem + G_SROW))[tid] = ((const int*)(smem + G_SROWSTG))[tid];
        }
        __syncthreads();   // images + s_row visible; stage consumed

        // read gather rows + prefetch their P lines into L1 (hidden by MMA)
        int G00 = s_row[m0 + g],      G01 = s_row[m0 + g + 8];
        int G10 = s_row[m0 + 16 + g], G11 = s_row[m0 + 16 + g + 8];
        {
            const float* pb = g_P;
            prefetchL1(pb + (size_t)G00 * 128 + n0 + t2);
            prefetchL1(pb + (size_t)G00 * 128 + n0 + t2 + 32);
            prefetchL1(pb + (size_t)G01 * 128 + n0 + t2);
            prefetchL1(pb + (size_t)G01 * 128 + n0 + t2 + 32);
            prefetchL1(pb + (size_t)G10 * 128 + n0 + t2);
            prefetchL1(pb + (size_t)G10 * 128 + n0 + t2 + 32);
            prefetchL1(pb + (size_t)G11 * 128 + n0 + t2);
            prefetchL1(pb + (size_t)G11 * 128 + n0 + t2 + 32);
        }

        // stage next tile (overlaps MMA + epilogue)
        if (t + G_GRID < G_NT) {
            int tn = t + G_GRID;
            const char* src = (const char*)(eattr + (size_t)tn * 128 * 64);
            #pragma unroll
            for (int i = tid; i < 2048; i += 256) {
                int r = i >> 4, q = i & 15;
                cp_async16(sb + G_STAGE + r * 272 + q * 16, src + (size_t)r * 256 + q * 16);
            }
            if (tid < 32)
                cp_async16(sb + G_SROWSTG + tid * 16,
                           (const char*)(erow + (size_t)tn * 128) + tid * 16);
            asm volatile("cp.async.commit_group;" ::: "memory");
        }

        // ---- MMA ----
        float acc[2][8][4];
        #pragma unroll
        for (int mi = 0; mi < 2; ++mi)
            #pragma unroll
            for (int ni = 0; ni < 8; ++ni)
                #pragma unroll
                for (int c = 0; c < 4; ++c) acc[mi][ni][c] = 0.f;

        #pragma unroll
        for (int kt = 0; kt < 4; ++kt) {
            const uint32_t k0b = (uint32_t)kt * 32u;
            const uint32_t kwb = (uint32_t)kt * 4352u;
            uint32_t ah[2][4], al[2][4];
            ldsm4(ah[0], sb + Q_AHI + aRowOff + k0b);
            ldsm4(ah[1], sb + Q_AHI + aRowOff + 16u * A_STRIDE + k0b);
            ldsm4(al[0], sb + Q_ALO + aRowOff + k0b);
            ldsm4(al[1], sb + Q_ALO + aRowOff + 16u * A_STRIDE + k0b);

            #pragma unroll
            for (int ni2 = 0; ni2 < 4; ++ni2) {
                uint32_t th[4], tl[4];
                ldsm4t(th, sb + Q_WHI + bOff + kwb + (uint32_t)ni2 * 32u);
                ldsm4t(tl, sb + Q_WLO + bOff + kwb + (uint32_t)ni2 * 32u);
                #pragma unroll
                for (int mi = 0; mi < 2; ++mi) {
                    mma_bf16(acc[mi][2 * ni2],     ah[mi], th);
                    mma_bf16(acc[mi][2 * ni2],     al[mi], th);
                    mma_bf16(acc[mi][2 * ni2],     ah[mi], tl);
                    mma_bf16(acc[mi][2 * ni2 + 1], ah[mi], th + 2);
                    mma_bf16(acc[mi][2 * ni2 + 1], al[mi], th + 2);
                    mma_bf16(acc[mi][2 * ni2 + 1], ah[mi], tl + 2);
                }
            }
        }

        // ---- epilogue: Y = Q + P[row] (L1-hot), fp16 streaming store --------
        const int mBase = t * 128;
        #pragma unroll
        for (int mi = 0; mi < 2; ++mi) {
            const int r0 = m0 + mi * 16 + g;
            const int G0 = (mi == 0) ? G00 : G10;
            const int G1 = (mi == 0) ? G01 : G11;
            const int row = mBase + r0;
            #pragma unroll
            for (int ni = 0; ni < 8; ++ni) {
                const int col = n0 + ni * 8 + t2;
                float2 p0 = *reinterpret_cast<const float2*>(g_P + (size_t)G0 * 128 + col);
                float2 p1 = *reinterpret_cast<const float2*>(g_P + (size_t)G1 * 128 + col);
                float y0 = acc[mi][ni][0] + p0.x;
                float y1 = acc[mi][ni][1] + p0.y;
                float y2 = acc[mi][ni][2] + p1.x;
                float y3 = acc[mi][ni][3] + p1.y;
                __half2 h01 = __floats2half2_rn(y0, y1);
                __half2 h23 = __floats2half2_rn(y2, y3);
                __stcs(reinterpret_cast<__half2*>(g_Y + (size_t)row * 128 + col), h01);
                __stcs(reinterpret_cast<__half2*>(g_Y + (size_t)(row + 8) * 128 + col), h23);
                csum[ni][0] += y0 + y2;
                csum[ni][1] += y1 + y3;
                cssq[ni][0] += y0 * y0 + y2 * y2;
                cssq[ni][1] += y1 * y1 + y3 * y3;
            }
        }
    }

    // ---- one-time BN1 stats reduction + global flush ----
    #pragma unroll
    for (int ni = 0; ni < 8; ++ni)
        #pragma unroll
        for (int par = 0; par < 2; ++par) {
            float s = csum[ni][par], q = cssq[ni][par];
            #pragma unroll
            for (int o = 4; o < 32; o <<= 1) {
                s += __shfl_xor_sync(0xFFFFFFFFu, s, o);
                q += __shfl_xor_sync(0xFFFFFFFFu, q, o);
            }
            if (g == 0) {
                atomicAdd(&s_sum[n0 + ni * 8 + t2 + par], s);
                atomicAdd(&s_ssq[n0 + ni * 8 + t2 + par], q);
            }
        }
    __syncthreads();
    if (tid < 128) {
        atomicAdd(&g_sum1[tid], s_sum[tid]);
        atomicAdd(&g_ssq1[tid], s_ssq[tid]);
    }
}

// ---------------- unified k-chunked bf16-split MMA GEMM ----------------------
// ASEL: 0=ext arg (x), 1=g_h2in, 2=g_Z2 (+bn2+relu transform)
// WSEL: 0=W1_top(17), 1=W2(33), 2=Wl(17)
// OSEL: 0=g_P, 1=g_Z2(+BN2 stats), 2=ext out arg(+relu)
template<int KCH, int ASEL, int WSEL, int OSEL>
__global__ void __launch_bounds__(256, 2)
mma_gemm(const float* __restrict__ Aext, int ldA, int M,
         const float* __restrict__ bias, float* __restrict__ outExt, int outLd)
{
    extern __shared__ char smem[];
    const uint32_t sb = smem_u32(smem);
    const int tid = threadIdx.x, wid = tid >> 5, lane = tid & 31;
    const int mBase = blockIdx.x * 128;
    const int nBase = blockIdx.y * 128;

    const float* A = (ASEL == 0) ? Aext : (ASEL == 1) ? (const float*)g_h2in
                                                      : (const float*)g_Z2;
    const uint4* WH = (WSEL == 0) ? g_W1tH : (WSEL == 1) ? g_W2H : g_WlH;
    const uint4* WL = (WSEL == 0) ? g_W1tL : (WSEL == 1) ? g_W2L : g_WlL;
    const int WR16 = (WSEL == 1) ? 33 : 17;
    float* outp = (OSEL == 0) ? (float*)g_P : (OSEL == 1) ? (float*)g_Z2 : outExt;

    if (tid < 128) {
        ((float*)(smem + Q_ROW))[tid] = bias[nBase + tid];
        ((float*)(smem + Q_SUM))[tid] = 0.f;
        ((float*)(smem + Q_SSQ))[tid] = 0.f;
    }

    const int m0 = (wid & 3) * 32;
    const int n0 = (wid >> 2) * 64;
    float acc[2][8][4];
    #pragma unroll
    for (int mi = 0; mi < 2; ++mi)
        #pragma unroll
        for (int ni = 0; ni < 8; ++ni)
            #pragma unroll
            for (int c = 0; c < 4; ++c) acc[mi][ni][c] = 0.f;

    const uint32_t aRowOff = (uint32_t)(m0 + (lane & 15)) * (uint32_t)A_STRIDE
                           + (uint32_t)(lane >> 4) * 16u;
    const uint32_t bOff = (uint32_t)((lane & 7) + ((lane >> 3) & 1) * 8) * 272u
                        + ((uint32_t)(lane >> 4) * 8u + (uint32_t)n0) * 2u;

    #pragma unroll 1
    for (int c = 0; c < KCH; ++c) {
        if (c) __syncthreads();
        {
            uint4* dh = reinterpret_cast<uint4*>(smem + Q_WHI);
            uint4* dl = reinterpret_cast<uint4*>(smem + Q_WLO);
            const uint4* sh = WH + (size_t)(c * 64) * WR16 + (nBase >> 3);
            const uint4* sl = WL + (size_t)(c * 64) * WR16 + (nBase >> 3);
            for (int i = tid; i < 1088; i += 256) {
                int kk = i / 17, q = i - kk * 17;
                dh[i] = sh[(size_t)kk * WR16 + q];
                dl[i] = sl[(size_t)kk * WR16 + q];
            }
        }
        {
            const int r = tid >> 1, h = tid & 1, rg = mBase + r;
            char* ahi = smem + Q_AHI + r * A_STRIDE;
            char* alo = smem + Q_ALO + r * A_STRIDE;
            const float4* ar = reinterpret_cast<const float4*>(A + (size_t)rg * ldA + c * 64);
            #pragma unroll
            for (int jj = 0; jj < 8; ++jj) {
                int j = h * 8 + jj;
                float4 v = make_float4(0.f, 0.f, 0.f, 0.f);
                if (rg < M) {
                    v = ar[j];
                    if (ASEL == 2) {
                        int kg = c * 64 + j * 4;
                        float4 sc = ld4(g_scale2 + kg), sh4 = ld4(g_shift2 + kg);
                        v.x = fmaxf(fmaf(v.x, sc.x, sh4.x), 0.f);
                        v.y = fmaxf(fmaf(v.y, sc.y, sh4.y), 0.f);
                        v.z = fmaxf(fmaf(v.z, sc.z, sh4.z), 0.f);
                        v.w = fmaxf(fmaf(v.w, sc.w, sh4.w), 0.f);
                    }
                }
                split_store(ahi, alo, j, v);
            }
        }
        __syncthreads();

        #pragma unroll
        for (int kt = 0; kt < 4; ++kt) {
            const uint32_t k0b = (uint32_t)kt * 32u;
            const uint32_t kwb = (uint32_t)kt * 4352u;
            uint32_t ah[2][4], al[2][4];
            ldsm4(ah[0], sb + Q_AHI + aRowOff + k0b);
            ldsm4(ah[1], sb + Q_AHI + aRowOff + 16u * A_STRIDE + k0b);
            ldsm4(al[0], sb + Q_ALO + aRowOff + k0b);
            ldsm4(al[1], sb + Q_ALO + aRowOff + 16u * A_STRIDE + k0b);

            #pragma unroll
            for (int ni2 = 0; ni2 < 4; ++ni2) {
                uint32_t th[4], tl[4];
                ldsm4t(th, sb + Q_WHI + bOff + kwb + (uint32_t)ni2 * 32u);
                ldsm4t(tl, sb + Q_WLO + bOff + kwb + (uint32_t)ni2 * 32u);
                #pragma unroll
                for (int mi = 0; mi < 2; ++mi) {
                    mma_bf16(acc[mi][2 * ni2],     ah[mi], th);
                    mma_bf16(acc[mi][2 * ni2],     al[mi], th);
                    mma_bf16(acc[mi][2 * ni2],     ah[mi], tl);
                    mma_bf16(acc[mi][2 * ni2 + 1], ah[mi], th + 2);
                    mma_bf16(acc[mi][2 * ni2 + 1], al[mi], th + 2);
                    mma_bf16(acc[mi][2 * ni2 + 1], ah[mi], tl + 2);
                }
            }
        }
    }
    __syncthreads();

    const float* bs = (const float*)(smem + Q_ROW);
    float* s_sum = (float*)(smem + Q_SUM);
    float* s_ssq = (float*)(smem + Q_SSQ);
    const int g = lane >> 2, t2 = (lane & 3) * 2;

    float csum[8][2], cssq[8][2];
    if (OSEL == 1) {
        #pragma unroll
        for (int ni = 0; ni < 8; ++ni) {
            csum[ni][0] = 0.f; csum[ni][1] = 0.f;
            cssq[ni][0] = 0.f; cssq[ni][1] = 0.f;
        }
    }

    #pragma unroll
    for (int mi = 0; mi < 2; ++mi) {
        const int row = mBase + m0 + mi * 16 + g;
        const bool v0 = row < M, v1 = (row + 8) < M;
        #pragma unroll
        for (int ni = 0; ni < 8; ++ni) {
            const int col = n0 + ni * 8 + t2;
            float b0 = bs[col], b1 = bs[col + 1];
            float y0 = acc[mi][ni][0] + b0;
            float y1 = acc[mi][ni][1] + b1;
            float y2 = acc[mi][ni][2] + b0;
            float y3 = acc[mi][ni][3] + b1;
            if (OSEL == 2) {
                y0 = fmaxf(y0, 0.f); y1 = fmaxf(y1, 0.f);
                y2 = fmaxf(y2, 0.f); y3 = fmaxf(y3, 0.f);
            }
            if (v0)
                *reinterpret_cast<float2*>(outp + (size_t)row * outLd + nBase + col)
                    = make_float2(y0, y1);
            if (v1)
                *reinterpret_cast<float2*>(outp + (size_t)(row + 8) * outLd + nBase + col)
                    = make_float2(y2, y3);
            if (OSEL == 1) {
                if (v0) {
                    csum[ni][0] += y0; csum[ni][1] += y1;
                    cssq[ni][0] += y0 * y0; cssq[ni][1] += y1 * y1;
                }
                if (v1) {
                    csum[ni][0] += y2; csum[ni][1] += y3;
                    cssq[ni][0] += y2 * y2; cssq[ni][1] += y3 * y3;
                }
            }
        }
    }
    if (OSEL == 1) {
        #pragma unroll
        for (int ni = 0; ni < 8; ++ni)
            #pragma unroll
            for (int par = 0; par < 2; ++par) {
                float s = csum[ni][par], q = cssq[ni][par];
                #pragma unroll
                for (int o = 4; o < 32; o <<= 1) {
                    s += __shfl_xor_sync(0xFFFFFFFFu, s, o);
                    q += __shfl_xor_sync(0xFFFFFFFFu, q, o);
                }
                if (g == 0) {
                    atomicAdd(&s_sum[n0 + ni * 8 + t2 + par], s);
                    atomicAdd(&s_ssq[n0 + ni * 8 + t2 + par], q);
                }
            }
        __syncthreads();
        if (tid < 128) {
            atomicAdd(&g_sum2[nBase + tid], s_sum[tid]);
            atomicAdd(&g_ssq2[nBase + tid], s_ssq[tid]);
        }
    }
}

// ---------------- BN finalize -------------------------------------------------
__global__ void finalize_bn(const float* __restrict__ gamma,
                            const float* __restrict__ beta,
                            int C, float invM, int which)
{
    int i = blockIdx.x * blockDim.x + threadIdx.x;
    if (i < C) {
        const float* sum = (which == 0) ? g_sum1 : g_sum2;
        const float* ssq = (which == 0) ? g_ssq1 : g_ssq2;
        float*     scale = (which == 0) ? g_scale1 : g_scale2;
        float*     shift = (which == 0) ? g_shift1 : g_shift2;
        float mu  = sum[i] * invM;
        float var = ssq[i] * invM - mu * mu;
        float inv = rsqrtf(var + EPS_BN);
        float sc  = gamma[i] * inv;
        scale[i] = sc;
        shift[i] = beta[i] - mu * sc;
    }
}

// ---------------- BN+ReLU then scatter-add (fp16 Y, vector atomics) ----------
__global__ void scatter_kernel(const int* __restrict__ ecol) {
    const int lane   = threadIdx.x & 31;
    const int warp   = (blockIdx.x * blockDim.x + threadIdx.x) >> 5;
    const int nWarps = (gridDim.x * blockDim.x) >> 5;

    float4 sc = *reinterpret_cast<const float4*>(&g_scale1[lane << 2]);
    float4 sh = *reinterpret_cast<const float4*>(&g_shift1[lane << 2]);

    for (int e = warp; e < E_EDGES; e += nWarps) {
        int c = ecol[e];
        uint2 raw = __ldcs(reinterpret_cast<const uint2*>(&g_Y[(size_t)e * 128 + (lane << 2)]));
        __half2 ha = *reinterpret_cast<__half2*>(&raw.x);
        __half2 hb = *reinterpret_cast<__half2*>(&raw.y);
        float2 f01 = __half22float2(ha);
        float2 f23 = __half22float2(hb);
        float y0 = fmaxf(fmaf(f01.x, sc.x, sh.x), 0.f);
        float y1 = fmaxf(fmaf(f01.y, sc.y, sh.y), 0.f);
        float y2 = fmaxf(fmaf(f23.x, sc.z, sh.z), 0.f);
        float y3 = fmaxf(fmaf(f23.y, sc.w, sh.w), 0.f);
        float* dst = &g_s[(size_t)c * 128 + (lane << 2)];
        asm volatile("red.global.add.v4.f32 [%0], {%1,%2,%3,%4};"
                     :: "l"(dst), "f"(y0), "f"(y1), "f"(y2), "f"(y3)
                     : "memory");
        if (lane == 0) atomicAdd(&g_cnt[c], 1);
    }
}

// ---------------- build h2in = concat(x, s/cnt) ------------------------------
__global__ void build_h2in(const float* __restrict__ x) {
    int idx = blockIdx.x * blockDim.x + threadIdx.x;
    int stride = gridDim.x * blockDim.x;
    const int total = N_NODES * 64;
    for (int i = idx; i < total; i += stride) {
        int n = i >> 6, q = i & 63;
        float4 v;
        if (q < 32) {
            v = ld4(x + (size_t)n * 128 + (q << 2));
        } else {
            int c = q - 32;
            v = ld4(g_s + (size_t)n * 128 + (c << 2));
            int cnt = g_cnt[n];
            float inv = (cnt > 0) ? (1.f / (float)cnt) : 0.f;
            v.x *= inv; v.y *= inv; v.z *= inv; v.w *= inv;
        }
        *reinterpret_cast<float4*>(g_h2in + (size_t)n * 256 + (q << 2)) = v;
    }
}

// ---------------- launch ------------------------------------------------------
extern "C" void kernel_launch(void* const* d_in, const int* in_sizes, int n_in,
                              void* d_out, int out_size)
{
    const float* x     = (const float*)d_in[0];
    const int*   eidx  = (const int*)  d_in[1];
    const float* eattr = (const float*)d_in[2];
    const float* W1  = (const float*)d_in[5];
    const float* b1  = (const float*)d_in[6];
    const float* g1  = (const float*)d_in[7];
    const float* be1 = (const float*)d_in[8];
    const float* W2  = (const float*)d_in[9];
    const float* b2  = (const float*)d_in[10];
    const float* g2  = (const float*)d_in[11];
    const float* be2 = (const float*)d_in[12];
    const float* Wl  = (const float*)d_in[13];
    const float* bl  = (const float*)d_in[14];
    float* out = (float*)d_out;

    const int* erow = eidx;
    const int* ecol = eidx + E_EDGES;

    cudaFuncSetAttribute(gemm1_mma, cudaFuncAttributeMaxDynamicSharedMemorySize, G_TOT);
    cudaFuncSetAttribute(mma_gemm<2, 0, 0, 0>, cudaFuncAttributeMaxDynamicSharedMemorySize, Q_TOT);
    cudaFuncSetAttribute(mma_gemm<4, 1, 1, 1>, cudaFuncAttributeMaxDynamicSharedMemorySize, Q_TOT);
    cudaFuncSetAttribute(mma_gemm<4, 2, 2, 2>, cudaFuncAttributeMaxDynamicSharedMemorySize, Q_TOT);

    const int MB = (N_NODES + 127) / 128;   // 391

    // 0) zero accumulators + prep all weight images
    zero_kernel<<<2048, 256>>>();
    prep_W<<<480, 256>>>(W1, W2, Wl);

    // 1) P = x @ W1_top + b1
    mma_gemm<2, 0, 0, 0><<<dim3(MB, 1), 256, Q_TOT>>>(x, 128, N_NODES, b1, nullptr, 128);

    // 2) persistent: Q = eattr @ W1_bot; Y = Q + P[row]; fused BN1 stats
    gemm1_mma<<<G_GRID, 256, G_TOT>>>(eattr, erow);

    // 3) BN1 scale/shift
    finalize_bn<<<1, 256>>>(g1, be1, 128, 1.f / (float)E_EDGES, 0);

    // 4) BN1 + ReLU + scatter (fp16 Y)
    scatter_kernel<<<2368, 256>>>(ecol);

    // 5) h2in = concat(x, s/cnt)
    build_h2in<<<2048, 256>>>(x);

    // 6) Z2 = h2in @ W2 + b2, fused BN2 stats
    mma_gemm<4, 1, 1, 1><<<dim3(MB, 2), 256, Q_TOT>>>(nullptr, 256, N_NODES, b2, nullptr, 256);

    // 7) BN2 scale/shift
    finalize_bn<<<1, 256>>>(g2, be2, 256, 1.f / (float)N_NODES, 1);

    // 8) out = relu(relu(bn2(Z2)) @ Wl + bl)
    mma_gemm<4, 2, 2, 2><<<dim3(MB, 1), 256, Q_TOT>>>(nullptr, 256, N_NODES, bl, out, 128);
}

// round 11
// speedup vs baseline: 3.0987x; 1.0742x over previous
#include <cuda_runtime.h>
#include <cuda_bf16.h>
#include <cuda_fp16.h>
#include <cstdint>

#define E_EDGES 1600000
#define N_NODES 50000
#define EPS_BN 1e-5f

// ---------------- scratch (device globals; no allocations allowed) ----------
__device__ __half g_Y[(size_t)E_EDGES * 128];     // pre-BN edge activations (fp16)
__device__ float g_P[(size_t)N_NODES * 128];      // x @ W1_top + b1
__device__ float g_s[(size_t)N_NODES * 128];      // scatter-sum accumulator
__device__ int   g_cnt[N_NODES];
__device__ float g_h2in[(size_t)N_NODES * 256];
__device__ float g_Z2[(size_t)N_NODES * 256];
__device__ float g_sum1[128], g_ssq1[128], g_scale1[128], g_shift1[128];
__device__ float g_sum2[256], g_ssq2[256], g_scale2[256], g_shift2[256];
// Weight images (padded rows, uint4-clean)
__device__ uint4 g_W1bH16[1088],  g_W1bL16[1088];  // W1_bot fp16 hi/lo [64 k][136 n]
__device__ uint4 g_W1tH[2176],    g_W1tL[2176];    // W1_top bf16 [128 k][136 n]
__device__ uint4 g_W2H[8448],     g_W2L[8448];     // W2    bf16 [256 k][264 n]
__device__ uint4 g_WlH[4352],     g_WlL[4352];     // Wl    bf16 [256 k][136 n]

__device__ __forceinline__ float4 ld4(const float* p) {
    return *reinterpret_cast<const float4*>(p);
}
__device__ __forceinline__ uint32_t smem_u32(const void* p) {
    uint32_t a;
    asm("{ .reg .u64 t; cvta.to.shared.u64 t, %1; cvt.u32.u64 %0, t; }" : "=r"(a) : "l"(p));
    return a;
}

// ---------------- warp MMA primitives (sm_80 baseline) ----------------------
__device__ __forceinline__ void mma_bf16(float* c, const uint32_t* a, const uint32_t* b) {
    asm volatile(
        "mma.sync.aligned.m16n8k16.row.col.f32.bf16.bf16.f32 "
        "{%0,%1,%2,%3}, {%4,%5,%6,%7}, {%8,%9}, {%0,%1,%2,%3};"
        : "+f"(c[0]), "+f"(c[1]), "+f"(c[2]), "+f"(c[3])
        : "r"(a[0]), "r"(a[1]), "r"(a[2]), "r"(a[3]), "r"(b[0]), "r"(b[1]));
}
__device__ __forceinline__ void mma_f16(float* c, const uint32_t* a, const uint32_t* b) {
    asm volatile(
        "mma.sync.aligned.m16n8k16.row.col.f32.f16.f16.f32 "
        "{%0,%1,%2,%3}, {%4,%5,%6,%7}, {%8,%9}, {%0,%1,%2,%3};"
        : "+f"(c[0]), "+f"(c[1]), "+f"(c[2]), "+f"(c[3])
        : "r"(a[0]), "r"(a[1]), "r"(a[2]), "r"(a[3]), "r"(b[0]), "r"(b[1]));
}
__device__ __forceinline__ void ldsm4(uint32_t* r, uint32_t addr) {
    asm volatile("ldmatrix.sync.aligned.m8n8.x4.shared.b16 {%0,%1,%2,%3}, [%4];"
        : "=r"(r[0]), "=r"(r[1]), "=r"(r[2]), "=r"(r[3]) : "r"(addr));
}
__device__ __forceinline__ void ldsm4t(uint32_t* r, uint32_t addr) {
    asm volatile("ldmatrix.sync.aligned.m8n8.x4.trans.shared.b16 {%0,%1,%2,%3}, [%4];"
        : "=r"(r[0]), "=r"(r[1]), "=r"(r[2]), "=r"(r[3]) : "r"(addr));
}
__device__ __forceinline__ void split_store(char* hi, char* lo, int j, float4 v) {
    __nv_bfloat16 h0 = __float2bfloat16_rn(v.x), h1 = __float2bfloat16_rn(v.y);
    __nv_bfloat16 h2 = __float2bfloat16_rn(v.z), h3 = __float2bfloat16_rn(v.w);
    __nv_bfloat162 hp0(h0, h1), hp1(h2, h3);
    __nv_bfloat162 lp0(__float2bfloat16_rn(v.x - __bfloat162float(h0)),
                       __float2bfloat16_rn(v.y - __bfloat162float(h1)));
    __nv_bfloat162 lp1(__float2bfloat16_rn(v.z - __bfloat162float(h2)),
                       __float2bfloat16_rn(v.w - __bfloat162float(h3)));
    *reinterpret_cast<uint2*>(hi + j * 8) =
        make_uint2(*reinterpret_cast<uint32_t*>(&hp0), *reinterpret_cast<uint32_t*>(&hp1));
    *reinterpret_cast<uint2*>(lo + j * 8) =
        make_uint2(*reinterpret_cast<uint32_t*>(&lp0), *reinterpret_cast<uint32_t*>(&lp1));
}
__device__ __forceinline__ void cp_async16(uint32_t saddr, const void* gptr) {
    asm volatile("cp.async.cg.shared.global [%0], [%1], 16;"
                 :: "r"(saddr), "l"(gptr) : "memory");
}
__device__ __forceinline__ void prefetchL1(const void* gptr) {
    asm volatile("prefetch.global.L1 [%0];" :: "l"(gptr));
}

// ---------------- zero scratch ----------------------------------------------
__global__ void zero_kernel() {
    int idx = blockIdx.x * blockDim.x + threadIdx.x;
    int stride = gridDim.x * blockDim.x;
    float4 z4 = make_float4(0.f, 0.f, 0.f, 0.f);
    int total4 = N_NODES * 32;
    float4* s4 = reinterpret_cast<float4*>(g_s);
    for (int i = idx; i < total4; i += stride) s4[i] = z4;
    for (int i = idx; i < N_NODES; i += stride) g_cnt[i] = 0;
    if (idx < 128) { g_sum1[idx] = 0.f; g_ssq1[idx] = 0.f; }
    if (idx < 256) { g_sum2[idx] = 0.f; g_ssq2[idx] = 0.f; }
}

// ---------------- prep: all weight images ------------------------------------
__global__ void prep_W(const float* __restrict__ W1, const float* __restrict__ W2,
                       const float* __restrict__ Wl) {
    int idx = blockIdx.x * blockDim.x + threadIdx.x;
    if (idx < 8192) {                       // W1_bot fp16 hi/lo: [64 k][128 n] -> 136
        int k = idx >> 7, n = idx & 127;
        float f = W1[(size_t)(128 + k) * 128 + n];
        __half h = __float2half_rn(f);
        __half l = __float2half_rn(f - __half2float(h));
        reinterpret_cast<uint16_t*>(g_W1bH16)[k * 136 + n] = *reinterpret_cast<uint16_t*>(&h);
        reinterpret_cast<uint16_t*>(g_W1bL16)[k * 136 + n] = *reinterpret_cast<uint16_t*>(&l);
        return;
    }
    float f;
    uint16_t *dh, *dl;
    int off;
    if (idx < 24576) {                      // W1_top bf16: [128 k][128 n] -> 136
        int l = idx - 8192, k = l >> 7, n = l & 127;
        f = W1[(size_t)k * 128 + n];
        dh = reinterpret_cast<uint16_t*>(g_W1tH);
        dl = reinterpret_cast<uint16_t*>(g_W1tL);
        off = k * 136 + n;
    } else if (idx < 90112) {               // W2 bf16: [256 k][256 n] -> 264
        int l = idx - 24576, k = l >> 8, n = l & 255;
        f = W2[(size_t)k * 256 + n];
        dh = reinterpret_cast<uint16_t*>(g_W2H);
        dl = reinterpret_cast<uint16_t*>(g_W2L);
        off = k * 264 + n;
    } else if (idx < 122880) {              // Wl bf16: [256 k][128 n] -> 136
        int l = idx - 90112, k = l >> 7, n = l & 127;
        f = Wl[(size_t)k * 128 + n];
        dh = reinterpret_cast<uint16_t*>(g_WlH);
        dl = reinterpret_cast<uint16_t*>(g_WlL);
        off = k * 136 + n;
    } else return;
    __nv_bfloat16 h = __float2bfloat16_rn(f);
    __nv_bfloat16 l = __float2bfloat16_rn(f - __bfloat162float(h));
    dh[off] = *reinterpret_cast<uint16_t*>(&h);
    dl[off] = *reinterpret_cast<uint16_t*>(&l);
}

// ---------------- SMEM layouts ------------------------------------------------
// mma_gemm (bf16 3-pass, unchanged):
#define Q_AHI 0
#define Q_ALO 18432
#define Q_WHI 36864
#define Q_WLO 54272
#define Q_ROW 71680
#define Q_SUM 72192
#define Q_SSQ 72704
#define Q_TOT 73216
#define A_STRIDE 144
// gemm1 (fp16 2-pass, persistent):
#define G2_A 0
#define G2_WHI 18432
#define G2_WLO 35840
#define G2_STAGE 53248       // raw eattr tile [128][272B] = 34816
#define G2_SROWSTG 88064
#define G2_SROW 88576
#define G2_SUM 89088
#define G2_SSQ 89600
#define G2_TOT 90112
#define G_GRID 296
#define G_NT (E_EDGES / 128)

// ---------------- gemm1 (persistent, fp16 2-pass): Y = eattr@W1_bot + P[row] --
__global__ void __launch_bounds__(256, 2)
gemm1_mma(const float* __restrict__ eattr, const int* __restrict__ erow) {
    extern __shared__ char smem[];
    const uint32_t sb = smem_u32(smem);
    const int tid = threadIdx.x, wid = tid >> 5, lane = tid & 31;

    // one-time: W fp16 hi/lo images, stat init
    {
        uint4* dh = reinterpret_cast<uint4*>(smem + G2_WHI);
        uint4* dl = reinterpret_cast<uint4*>(smem + G2_WLO);
        for (int i = tid; i < 1088; i += 256) { dh[i] = g_W1bH16[i]; dl[i] = g_W1bL16[i]; }
    }
    if (tid < 128) {
        ((float*)(smem + G2_SUM))[tid] = 0.f;
        ((float*)(smem + G2_SSQ))[tid] = 0.f;
    }

    // prologue: stage first tile
    {
        int t0 = blockIdx.x;
        const char* src = (const char*)(eattr + (size_t)t0 * 128 * 64);
        #pragma unroll
        for (int i = tid; i < 2048; i += 256) {
            int r = i >> 4, q = i & 15;
            cp_async16(sb + G2_STAGE + r * 272 + q * 16, src + (size_t)r * 256 + q * 16);
        }
        if (tid < 32)
            cp_async16(sb + G2_SROWSTG + tid * 16,
                       (const char*)(erow + (size_t)t0 * 128) + tid * 16);
        asm volatile("cp.async.commit_group;" ::: "memory");
    }

    const int m0 = (wid & 3) * 32;
    const int n0 = (wid >> 2) * 64;
    const uint32_t aRowOff = (uint32_t)(m0 + (lane & 15)) * (uint32_t)A_STRIDE
                           + (uint32_t)(lane >> 4) * 16u;
    const uint32_t bOff = (uint32_t)((lane & 7) + ((lane >> 3) & 1) * 8) * 272u
                        + ((uint32_t)(lane >> 4) * 8u + (uint32_t)n0) * 2u;
    const int g = lane >> 2, t2 = (lane & 3) * 2;
    const int* s_row = (const int*)(smem + G2_SROW);
    float* s_sum = (float*)(smem + G2_SUM);
    float* s_ssq = (float*)(smem + G2_SSQ);

    float csum[8][2], cssq[8][2];
    #pragma unroll
    for (int ni = 0; ni < 8; ++ni) {
        csum[ni][0] = 0.f; csum[ni][1] = 0.f;
        cssq[ni][0] = 0.f; cssq[ni][1] = 0.f;
    }

    for (int t = blockIdx.x; t < G_NT; t += G_GRID) {
        asm volatile("cp.async.wait_group 0;" ::: "memory");
        __syncthreads();   // stage ready; prior MMA/epilogue done

        // convert stage -> single fp16 A image; publish erow
        {
            const int r = tid >> 1, h = tid & 1;
            const char* srow = smem + G2_STAGE + r * 272;
            char* ai = smem + G2_A + r * A_STRIDE;
            #pragma unroll
            for (int p = 0; p < 4; ++p) {
                int j = h * 8 + p * 2;
                float4 v0 = *reinterpret_cast<const float4*>(srow + j * 16);
                float4 v1 = *reinterpret_cast<const float4*>(srow + j * 16 + 16);
                __half2 a = __floats2half2_rn(v0.x, v0.y);
                __half2 b = __floats2half2_rn(v0.z, v0.w);
                __half2 c = __floats2half2_rn(v1.x, v1.y);
                __half2 d = __floats2half2_rn(v1.z, v1.w);
                uint4 pk = make_uint4(*reinterpret_cast<uint32_t*>(&a),
                                      *reinterpret_cast<uint32_t*>(&b),
                                      *reinterpret_cast<uint32_t*>(&c),
                                      *reinterpret_cast<uint32_t*>(&d));
                *reinterpret_cast<uint4*>(ai + j * 8) = pk;
            }
            if (tid < 128)
                ((int*)(smem + G2_SROW))[tid] = ((const int*)(smem + G2_SROWSTG))[tid];
        }
        __syncthreads();   // image + s_row visible; stage consumed

        // gather rows + P prefetch (hidden by MMA)
        int G00 = s_row[m0 + g],      G01 = s_row[m0 + g + 8];
        int G10 = s_row[m0 + 16 + g], G11 = s_row[m0 + 16 + g + 8];
        {
            const float* pb = g_P;
            prefetchL1(pb + (size_t)G00 * 128 + n0 + t2);
            prefetchL1(pb + (size_t)G00 * 128 + n0 + t2 + 32);
            prefetchL1(pb + (size_t)G01 * 128 + n0 + t2);
            prefetchL1(pb + (size_t)G01 * 128 + n0 + t2 + 32);
            prefetchL1(pb + (size_t)G10 * 128 + n0 + t2);
            prefetchL1(pb + (size_t)G10 * 128 + n0 + t2 + 32);
            prefetchL1(pb + (size_t)G11 * 128 + n0 + t2);
            prefetchL1(pb + (size_t)G11 * 128 + n0 + t2 + 32);
        }

        // stage next tile
        if (t + G_GRID < G_NT) {
            int tn = t + G_GRID;
            const char* src = (const char*)(eattr + (size_t)tn * 128 * 64);
            #pragma unroll
            for (int i = tid; i < 2048; i += 256) {
                int r = i >> 4, q = i & 15;
                cp_async16(sb + G2_STAGE + r * 272 + q * 16, src + (size_t)r * 256 + q * 16);
            }
            if (tid < 32)
                cp_async16(sb + G2_SROWSTG + tid * 16,
                           (const char*)(erow + (size_t)tn * 128) + tid * 16);
            asm volatile("cp.async.commit_group;" ::: "memory");
        }

        // ---- MMA: 2 passes (A fp16, W hi + W lo) ----
        float acc[2][8][4];
        #pragma unroll
        for (int mi = 0; mi < 2; ++mi)
            #pragma unroll
            for (int ni = 0; ni < 8; ++ni)
                #pragma unroll
                for (int c = 0; c < 4; ++c) acc[mi][ni][c] = 0.f;

        #pragma unroll
        for (int kt = 0; kt < 4; ++kt) {
            const uint32_t k0b = (uint32_t)kt * 32u;
            const uint32_t kwb = (uint32_t)kt * 4352u;
            uint32_t a0[4], a1[4];
            ldsm4(a0, sb + G2_A + aRowOff + k0b);
            ldsm4(a1, sb + G2_A + aRowOff + 16u * A_STRIDE + k0b);

            #pragma unroll
            for (int ni2 = 0; ni2 < 4; ++ni2) {
                uint32_t th[4], tl[4];
                ldsm4t(th, sb + G2_WHI + bOff + kwb + (uint32_t)ni2 * 32u);
                ldsm4t(tl, sb + G2_WLO + bOff + kwb + (uint32_t)ni2 * 32u);
                mma_f16(acc[0][2 * ni2],     a0, th);
                mma_f16(acc[0][2 * ni2],     a0, tl);
                mma_f16(acc[0][2 * ni2 + 1], a0, th + 2);
                mma_f16(acc[0][2 * ni2 + 1], a0, tl + 2);
                mma_f16(acc[1][2 * ni2],     a1, th);
                mma_f16(acc[1][2 * ni2],     a1, tl);
                mma_f16(acc[1][2 * ni2 + 1], a1, th + 2);
                mma_f16(acc[1][2 * ni2 + 1], a1, tl + 2);
            }
        }

        // ---- epilogue: Y = Q + P[row] (L1-hot), fp16 streaming store --------
        const int mBase = t * 128;
        #pragma unroll
        for (int mi = 0; mi < 2; ++mi) {
            const int r0 = m0 + mi * 16 + g;
            const int G0 = (mi == 0) ? G00 : G10;
            const int G1 = (mi == 0) ? G01 : G11;
            const int row = mBase + r0;
            #pragma unroll
            for (int ni = 0; ni < 8; ++ni) {
                const int col = n0 + ni * 8 + t2;
                float2 p0 = *reinterpret_cast<const float2*>(g_P + (size_t)G0 * 128 + col);
                float2 p1 = *reinterpret_cast<const float2*>(g_P + (size_t)G1 * 128 + col);
                float y0 = acc[mi][ni][0] + p0.x;
                float y1 = acc[mi][ni][1] + p0.y;
                float y2 = acc[mi][ni][2] + p1.x;
                float y3 = acc[mi][ni][3] + p1.y;
                __half2 h01 = __floats2half2_rn(y0, y1);
                __half2 h23 = __floats2half2_rn(y2, y3);
                __stcs(reinterpret_cast<__half2*>(g_Y + (size_t)row * 128 + col), h01);
                __stcs(reinterpret_cast<__half2*>(g_Y + (size_t)(row + 8) * 128 + col), h23);
                csum[ni][0] += y0 + y2;
                csum[ni][1] += y1 + y3;
                cssq[ni][0] += y0 * y0 + y2 * y2;
                cssq[ni][1] += y1 * y1 + y3 * y3;
            }
        }
    }

    // ---- one-time BN1 stats reduction + global flush ----
    #pragma unroll
    for (int ni = 0; ni < 8; ++ni)
        #pragma unroll
        for (int par = 0; par < 2; ++par) {
            float s = csum[ni][par], q = cssq[ni][par];
            #pragma unroll
            for (int o = 4; o < 32; o <<= 1) {
                s += __shfl_xor_sync(0xFFFFFFFFu, s, o);
                q += __shfl_xor_sync(0xFFFFFFFFu, q, o);
            }
            if (g == 0) {
                atomicAdd(&s_sum[n0 + ni * 8 + t2 + par], s);
                atomicAdd(&s_ssq[n0 + ni * 8 + t2 + par], q);
            }
        }
    __syncthreads();
    if (tid < 128) {
        atomicAdd(&g_sum1[tid], s_sum[tid]);
        atomicAdd(&g_ssq1[tid], s_ssq[tid]);
    }
}

// ---------------- unified k-chunked bf16-split MMA GEMM (unchanged) ----------
// ASEL: 0=ext arg (x), 1=g_h2in, 2=g_Z2 (+bn2+relu transform)
// WSEL: 0=W1_top(17), 1=W2(33), 2=Wl(17)
// OSEL: 0=g_P, 1=g_Z2(+BN2 stats), 2=ext out arg(+relu)
template<int KCH, int ASEL, int WSEL, int OSEL>
__global__ void __launch_bounds__(256, 2)
mma_gemm(const float* __restrict__ Aext, int ldA, int M,
         const float* __restrict__ bias, float* __restrict__ outExt, int outLd)
{
    extern __shared__ char smem[];
    const uint32_t sb = smem_u32(smem);
    const int tid = threadIdx.x, wid = tid >> 5, lane = tid & 31;
    const int mBase = blockIdx.x * 128;
    const int nBase = blockIdx.y * 128;

    const float* A = (ASEL == 0) ? Aext : (ASEL == 1) ? (const float*)g_h2in
                                                      : (const float*)g_Z2;
    const uint4* WH = (WSEL == 0) ? g_W1tH : (WSEL == 1) ? g_W2H : g_WlH;
    const uint4* WL = (WSEL == 0) ? g_W1tL : (WSEL == 1) ? g_W2L : g_WlL;
    const int WR16 = (WSEL == 1) ? 33 : 17;
    float* outp = (OSEL == 0) ? (float*)g_P : (OSEL == 1) ? (float*)g_Z2 : outExt;

    if (tid < 128) {
        ((float*)(smem + Q_ROW))[tid] = bias[nBase + tid];
        ((float*)(smem + Q_SUM))[tid] = 0.f;
        ((float*)(smem + Q_SSQ))[tid] = 0.f;
    }

    const int m0 = (wid & 3) * 32;
    const int n0 = (wid >> 2) * 64;
    float acc[2][8][4];
    #pragma unroll
    for (int mi = 0; mi < 2; ++mi)
        #pragma unroll
        for (int ni = 0; ni < 8; ++ni)
            #pragma unroll
            for (int c = 0; c < 4; ++c) acc[mi][ni][c] = 0.f;

    const uint32_t aRowOff = (uint32_t)(m0 + (lane & 15)) * (uint32_t)A_STRIDE
                           + (uint32_t)(lane >> 4) * 16u;
    const uint32_t bOff = (uint32_t)((lane & 7) + ((lane >> 3) & 1) * 8) * 272u
                        + ((uint32_t)(lane >> 4) * 8u + (uint32_t)n0) * 2u;

    #pragma unroll 1
    for (int c = 0; c < KCH; ++c) {
        if (c) __syncthreads();
        {
            uint4* dh = reinterpret_cast<uint4*>(smem + Q_WHI);
            uint4* dl = reinterpret_cast<uint4*>(smem + Q_WLO);
            const uint4* sh = WH + (size_t)(c * 64) * WR16 + (nBase >> 3);
            const uint4* sl = WL + (size_t)(c * 64) * WR16 + (nBase >> 3);
            for (int i = tid; i < 1088; i += 256) {
                int kk = i / 17, q = i - kk * 17;
                dh[i] = sh[(size_t)kk * WR16 + q];
                dl[i] = sl[(size_t)kk * WR16 + q];
            }
        }
        {
            const int r = tid >> 1, h = tid & 1, rg = mBase + r;
            char* ahi = smem + Q_AHI + r * A_STRIDE;
            char* alo = smem + Q_ALO + r * A_STRIDE;
            const float4* ar = reinterpret_cast<const float4*>(A + (size_t)rg * ldA + c * 64);
            #pragma unroll
            for (int jj = 0; jj < 8; ++jj) {
                int j = h * 8 + jj;
                float4 v = make_float4(0.f, 0.f, 0.f, 0.f);
                if (rg < M) {
                    v = ar[j];
                    if (ASEL == 2) {
                        int kg = c * 64 + j * 4;
                        float4 sc = ld4(g_scale2 + kg), sh4 = ld4(g_shift2 + kg);
                        v.x = fmaxf(fmaf(v.x, sc.x, sh4.x), 0.f);
                        v.y = fmaxf(fmaf(v.y, sc.y, sh4.y), 0.f);
                        v.z = fmaxf(fmaf(v.z, sc.z, sh4.z), 0.f);
                        v.w = fmaxf(fmaf(v.w, sc.w, sh4.w), 0.f);
                    }
                }
                split_store(ahi, alo, j, v);
            }
        }
        __syncthreads();

        #pragma unroll
        for (int kt = 0; kt < 4; ++kt) {
            const uint32_t k0b = (uint32_t)kt * 32u;
            const uint32_t kwb = (uint32_t)kt * 4352u;
            uint32_t ah[2][4], al[2][4];
            ldsm4(ah[0], sb + Q_AHI + aRowOff + k0b);
            ldsm4(ah[1], sb + Q_AHI + aRowOff + 16u * A_STRIDE + k0b);
            ldsm4(al[0], sb + Q_ALO + aRowOff + k0b);
            ldsm4(al[1], sb + Q_ALO + aRowOff + 16u * A_STRIDE + k0b);

            #pragma unroll
            for (int ni2 = 0; ni2 < 4; ++ni2) {
                uint32_t th[4], tl[4];
                ldsm4t(th, sb + Q_WHI + bOff + kwb + (uint32_t)ni2 * 32u);
                ldsm4t(tl, sb + Q_WLO + bOff + kwb + (uint32_t)ni2 * 32u);
                #pragma unroll
                for (int mi = 0; mi < 2; ++mi) {
                    mma_bf16(acc[mi][2 * ni2],     ah[mi], th);
                    mma_bf16(acc[mi][2 * ni2],     al[mi], th);
                    mma_bf16(acc[mi][2 * ni2],     ah[mi], tl);
                    mma_bf16(acc[mi][2 * ni2 + 1], ah[mi], th + 2);
                    mma_bf16(acc[mi][2 * ni2 + 1], al[mi], th + 2);
                    mma_bf16(acc[mi][2 * ni2 + 1], ah[mi], tl + 2);
                }
            }
        }
    }
    __syncthreads();

    const float* bs = (const float*)(smem + Q_ROW);
    float* s_sum = (float*)(smem + Q_SUM);
    float* s_ssq = (float*)(smem + Q_SSQ);
    const int g = lane >> 2, t2 = (lane & 3) * 2;

    float csum[8][2], cssq[8][2];
    if (OSEL == 1) {
        #pragma unroll
        for (int ni = 0; ni < 8; ++ni) {
            csum[ni][0] = 0.f; csum[ni][1] = 0.f;
            cssq[ni][0] = 0.f; cssq[ni][1] = 0.f;
        }
    }

    #pragma unroll
    for (int mi = 0; mi < 2; ++mi) {
        const int row = mBase + m0 + mi * 16 + g;
        const bool v0 = row < M, v1 = (row + 8) < M;
        #pragma unroll
        for (int ni = 0; ni < 8; ++ni) {
            const int col = n0 + ni * 8 + t2;
            float b0 = bs[col], b1 = bs[col + 1];
            float y0 = acc[mi][ni][0] + b0;
            float y1 = acc[mi][ni][1] + b1;
            float y2 = acc[mi][ni][2] + b0;
            float y3 = acc[mi][ni][3] + b1;
            if (OSEL == 2) {
                y0 = fmaxf(y0, 0.f); y1 = fmaxf(y1, 0.f);
                y2 = fmaxf(y2, 0.f); y3 = fmaxf(y3, 0.f);
            }
            if (v0)
                *reinterpret_cast<float2*>(outp + (size_t)row * outLd + nBase + col)
                    = make_float2(y0, y1);
            if (v1)
                *reinterpret_cast<float2*>(outp + (size_t)(row + 8) * outLd + nBase + col)
                    = make_float2(y2, y3);
            if (OSEL == 1) {
                if (v0) {
                    csum[ni][0] += y0; csum[ni][1] += y1;
                    cssq[ni][0] += y0 * y0; cssq[ni][1] += y1 * y1;
                }
                if (v1) {
                    csum[ni][0] += y2; csum[ni][1] += y3;
                    cssq[ni][0] += y2 * y2; cssq[ni][1] += y3 * y3;
                }
            }
        }
    }
    if (OSEL == 1) {
        #pragma unroll
        for (int ni = 0; ni < 8; ++ni)
            #pragma unroll
            for (int par = 0; par < 2; ++par) {
                float s = csum[ni][par], q = cssq[ni][par];
                #pragma unroll
                for (int o = 4; o < 32; o <<= 1) {
                    s += __shfl_xor_sync(0xFFFFFFFFu, s, o);
                    q += __shfl_xor_sync(0xFFFFFFFFu, q, o);
                }
                if (g == 0) {
                    atomicAdd(&s_sum[n0 + ni * 8 + t2 + par], s);
                    atomicAdd(&s_ssq[n0 + ni * 8 + t2 + par], q);
                }
            }
        __syncthreads();
        if (tid < 128) {
            atomicAdd(&g_sum2[nBase + tid], s_sum[tid]);
            atomicAdd(&g_ssq2[nBase + tid], s_ssq[tid]);
        }
    }
}

// ---------------- BN finalize -------------------------------------------------
__global__ void finalize_bn(const float* __restrict__ gamma,
                            const float* __restrict__ beta,
                            int C, float invM, int which)
{
    int i = blockIdx.x * blockDim.x + threadIdx.x;
    if (i < C) {
        const float* sum = (which == 0) ? g_sum1 : g_sum2;
        const float* ssq = (which == 0) ? g_ssq1 : g_ssq2;
        float*     scale = (which == 0) ? g_scale1 : g_scale2;
        float*     shift = (which == 0) ? g_shift1 : g_shift2;
        float mu  = sum[i] * invM;
        float var = ssq[i] * invM - mu * mu;
        float inv = rsqrtf(var + EPS_BN);
        float sc  = gamma[i] * inv;
        scale[i] = sc;
        shift[i] = beta[i] - mu * sc;
    }
}

// ---------------- BN+ReLU then scatter-add (fp16 Y, vector atomics) ----------
__global__ void scatter_kernel(const int* __restrict__ ecol) {
    const int lane   = threadIdx.x & 31;
    const int warp   = (blockIdx.x * blockDim.x + threadIdx.x) >> 5;
    const int nWarps = (gridDim.x * blockDim.x) >> 5;

    float4 sc = *reinterpret_cast<const float4*>(&g_scale1[lane << 2]);
    float4 sh = *reinterpret_cast<const float4*>(&g_shift1[lane << 2]);

    for (int e = warp; e < E_EDGES; e += nWarps) {
        int c = ecol[e];
        uint2 raw = __ldcs(reinterpret_cast<const uint2*>(&g_Y[(size_t)e * 128 + (lane << 2)]));
        __half2 ha = *reinterpret_cast<__half2*>(&raw.x);
        __half2 hb = *reinterpret_cast<__half2*>(&raw.y);
        float2 f01 = __half22float2(ha);
        float2 f23 = __half22float2(hb);
        float y0 = fmaxf(fmaf(f01.x, sc.x, sh.x), 0.f);
        float y1 = fmaxf(fmaf(f01.y, sc.y, sh.y), 0.f);
        float y2 = fmaxf(fmaf(f23.x, sc.z, sh.z), 0.f);
        float y3 = fmaxf(fmaf(f23.y, sc.w, sh.w), 0.f);
        float* dst = &g_s[(size_t)c * 128 + (lane << 2)];
        asm volatile("red.global.add.v4.f32 [%0], {%1,%2,%3,%4};"
                     :: "l"(dst), "f"(y0), "f"(y1), "f"(y2), "f"(y3)
                     : "memory");
        if (lane == 0) atomicAdd(&g_cnt[c], 1);
    }
}

// ---------------- build h2in = concat(x, s/cnt) ------------------------------
__global__ void build_h2in(const float* __restrict__ x) {
    int idx = blockIdx.x * blockDim.x + threadIdx.x;
    int stride = gridDim.x * blockDim.x;
    const int total = N_NODES * 64;
    for (int i = idx; i < total; i += stride) {
        int n = i >> 6, q = i & 63;
        float4 v;
        if (q < 32) {
            v = ld4(x + (size_t)n * 128 + (q << 2));
        } else {
            int c = q - 32;
            v = ld4(g_s + (size_t)n * 128 + (c << 2));
            int cnt = g_cnt[n];
            float inv = (cnt > 0) ? (1.f / (float)cnt) : 0.f;
            v.x *= inv; v.y *= inv; v.z *= inv; v.w *= inv;
        }
        *reinterpret_cast<float4*>(g_h2in + (size_t)n * 256 + (q << 2)) = v;
    }
}

// ---------------- launch ------------------------------------------------------
extern "C" void kernel_launch(void* const* d_in, const int* in_sizes, int n_in,
                              void* d_out, int out_size)
{
    const float* x     = (const float*)d_in[0];
    const int*   eidx  = (const int*)  d_in[1];
    const float* eattr = (const float*)d_in[2];
    const float* W1  = (const float*)d_in[5];
    const float* b1  = (const float*)d_in[6];
    const float* g1  = (const float*)d_in[7];
    const float* be1 = (const float*)d_in[8];
    const float* W2  = (const float*)d_in[9];
    const float* b2  = (const float*)d_in[10];
    const float* g2  = (const float*)d_in[11];
    const float* be2 = (const float*)d_in[12];
    const float* Wl  = (const float*)d_in[13];
    const float* bl  = (const float*)d_in[14];
    float* out = (float*)d_out;

    const int* erow = eidx;
    const int* ecol = eidx + E_EDGES;

    cudaFuncSetAttribute(gemm1_mma, cudaFuncAttributeMaxDynamicSharedMemorySize, G2_TOT);
    cudaFuncSetAttribute(mma_gemm<2, 0, 0, 0>, cudaFuncAttributeMaxDynamicSharedMemorySize, Q_TOT);
    cudaFuncSetAttribute(mma_gemm<4, 1, 1, 1>, cudaFuncAttributeMaxDynamicSharedMemorySize, Q_TOT);
    cudaFuncSetAttribute(mma_gemm<4, 2, 2, 2>, cudaFuncAttributeMaxDynamicSharedMemorySize, Q_TOT);

    const int MB = (N_NODES + 127) / 128;   // 391

    // 0) zero accumulators + prep all weight images
    zero_kernel<<<2048, 256>>>();
    prep_W<<<480, 256>>>(W1, W2, Wl);

    // 1) P = x @ W1_top + b1
    mma_gemm<2, 0, 0, 0><<<dim3(MB, 1), 256, Q_TOT>>>(x, 128, N_NODES, b1, nullptr, 128);

    // 2) persistent fp16 2-pass: Y = eattr @ W1_bot + P[row]; fused BN1 stats
    gemm1_mma<<<G_GRID, 256, G2_TOT>>>(eattr, erow);

    // 3) BN1 scale/shift
    finalize_bn<<<1, 256>>>(g1, be1, 128, 1.f / (float)E_EDGES, 0);

    // 4) BN1 + ReLU + scatter (fp16 Y)
    scatter_kernel<<<2368, 256>>>(ecol);

    // 5) h2in = concat(x, s/cnt)
    build_h2in<<<2048, 256>>>(x);

    // 6) Z2 = h2in @ W2 + b2, fused BN2 stats
    mma_gemm<4, 1, 1, 1><<<dim3(MB, 2), 256, Q_TOT>>>(nullptr, 256, N_NODES, b2, nullptr, 256);

    // 7) BN2 scale/shift
    finalize_bn<<<1, 256>>>(g2, be2, 256, 1.f / (float)N_NODES, 1);

    // 8) out = relu(relu(bn2(Z2)) @ Wl + bl)
    mma_gemm<4, 2, 2, 2><<<dim3(MB, 1), 256, Q_TOT>>>(nullptr, 256, N_NODES, bl, out, 128);
}